// round 1
// baseline (speedup 1.0000x reference)
#include <cuda_runtime.h>

#define BB 2
#define TT 2048
#define EE 768
#define SS 96
#define HH 150
#define WW 8
#define E3 2304
#define NSPAN (BB*SS)   // 192

// -------- device scratch (no allocations allowed) --------
__device__ int   d_starts[NSPAN];
__device__ float d_g[NSPAN * E3];              // [span][ start(768) | end(768) | attnsum(768) ]
__device__ float d_part[3 * 8 * NSPAN * HH];   // k-split partials: [mat][ks][span][h]
__device__ float d_A[NSPAN * HH];              // g_i @ Wa
__device__ float d_Bt[NSPAN * HH];             // g_j @ Wb
__device__ float d_m1[NSPAN * HH];             // mention layer-1 pre-bias
__device__ float d_ms[NSPAN];                  // mention scores

// ---------------------------------------------------------------------------
// k_init: convert span_starts to int32 (handles int64-or-int32 ambiguity)
// ---------------------------------------------------------------------------
__global__ void k_init(const void* sp) {
    __shared__ int is64;
    if (threadIdx.x == 0) {
        const int* w32 = (const int*)sp;
        int z = 1;
        // if data is int64 (values < 2048), every odd 32-bit word of the first
        // 64 words is 0; if int32, these are sorted random starts (nonzero).
        for (int i = 1; i < 64; i += 2) if (w32[i] != 0) { z = 0; break; }
        is64 = z;
    }
    __syncthreads();
    int i = threadIdx.x;
    if (i < NSPAN) {
        if (is64) d_starts[i] = (int)((const long long*)sp)[i];
        else      d_starts[i] = ((const int*)sp)[i];
    }
}

// ---------------------------------------------------------------------------
// k_span: per-span attn MLP (8 tokens) + build g_i  (one block per span)
// ---------------------------------------------------------------------------
__global__ void __launch_bounds__(160) k_span(
    const float* __restrict__ X,
    const float* __restrict__ aw1, const float* __restrict__ ab1,
    const float* __restrict__ aw2, const float* __restrict__ ab2,
    const float* __restrict__ aw3, const float* __restrict__ ab3)
{
    int bi = blockIdx.x;
    int b = bi / SS;
    int st = d_starts[bi];
    int tid = threadIdx.x;

    __shared__ float xs[WW * EE];        // 8 contiguous tokens: 24576 B
    __shared__ float s1[WW][HH + 2];
    __shared__ float s2[WW][HH + 2];
    __shared__ float at[WW];

    const float* Xb = X + ((size_t)b * TT + st) * EE;   // tokens st..st+7 contiguous
    for (int idx = tid; idx < WW * EE; idx += 160) xs[idx] = Xb[idx];
    __syncthreads();

    if (tid < HH) {
        float acc[WW];
        #pragma unroll
        for (int w = 0; w < WW; w++) acc[w] = ab1[tid];
        #pragma unroll 4
        for (int k = 0; k < EE; k++) {
            float wg = aw1[k * HH + tid];
            #pragma unroll
            for (int w = 0; w < WW; w++) acc[w] += xs[w * EE + k] * wg;
        }
        #pragma unroll
        for (int w = 0; w < WW; w++) s1[w][tid] = fmaxf(acc[w], 0.f);
    }
    __syncthreads();
    if (tid < HH) {
        float acc[WW];
        #pragma unroll
        for (int w = 0; w < WW; w++) acc[w] = ab2[tid];
        #pragma unroll 2
        for (int k = 0; k < HH; k++) {
            float wg = aw2[k * HH + tid];
            #pragma unroll
            for (int w = 0; w < WW; w++) acc[w] += s1[w][k] * wg;
        }
        #pragma unroll
        for (int w = 0; w < WW; w++) s2[w][tid] = fmaxf(acc[w], 0.f);
    }
    __syncthreads();
    if (tid < WW) {
        float a = ab3[0];
        for (int h = 0; h < HH; h++) a += s2[tid][h] * aw3[h];
        at[tid] = a;
    }
    __syncthreads();

    float* gp = d_g + (size_t)bi * E3;
    for (int e = tid; e < EE; e += 160) {
        gp[e]          = xs[e];            // start token
        gp[EE + e]     = xs[7 * EE + e];   // end token
        float s = 0.f;
        #pragma unroll
        for (int w = 0; w < WW; w++) s += xs[w * EE + e] * at[w];
        gp[2 * EE + e] = s;                // attention-weighted sum
    }
}

// ---------------------------------------------------------------------------
// k_terms: [192 spans, 2304] @ {Wa | Wb | mw1} with k-split partials.
// grid = 144:  sc (6 span-chunks of 32) x mat (3) x ks (8 k-splits of 288)
// ---------------------------------------------------------------------------
__global__ void __launch_bounds__(160) k_terms(
    const float* __restrict__ pw1, const float* __restrict__ mw1)
{
    int x = blockIdx.x;
    int sc  = x % 6;
    int mat = (x / 6) % 3;
    int ks  = x / 18;
    const float* Wm = (mat == 0) ? pw1 : (mat == 1 ? pw1 + (size_t)E3 * HH : mw1);
    int s0 = sc * 32;
    int kbase = ks * 288;
    int tid = threadIdx.x;

    __shared__ float gs[32][16];

    float acc[32];
    #pragma unroll
    for (int t = 0; t < 32; t++) acc[t] = 0.f;

    for (int kc = 0; kc < 288; kc += 16) {
        int k0 = kbase + kc;
        for (int idx = tid; idx < 512; idx += 160) {
            int t = idx >> 4, kk = idx & 15;
            gs[t][kk] = d_g[(size_t)(s0 + t) * E3 + k0 + kk];
        }
        __syncthreads();
        if (tid < HH) {
            #pragma unroll
            for (int kk = 0; kk < 16; kk++) {
                float wg = Wm[(size_t)(k0 + kk) * HH + tid];
                #pragma unroll
                for (int t = 0; t < 32; t++) acc[t] += gs[t][kk] * wg;
            }
        }
        __syncthreads();
    }
    if (tid < HH) {
        float* op = d_part + (((size_t)mat * 8 + ks) * NSPAN + s0) * HH + tid;
        #pragma unroll
        for (int t = 0; t < 32; t++) op[t * HH] = acc[t];
    }
}

// ---------------------------------------------------------------------------
// k_reduce: sum the 8 k-split partials into d_A / d_Bt / d_m1 (deterministic)
// ---------------------------------------------------------------------------
__global__ void k_reduce() {
    int i = blockIdx.x * blockDim.x + threadIdx.x;     // over NSPAN*HH
    if (i >= NSPAN * HH) return;
    #pragma unroll
    for (int mat = 0; mat < 3; mat++) {
        float s = 0.f;
        #pragma unroll
        for (int ks = 0; ks < 8; ks++)
            s += d_part[((size_t)mat * 8 + ks) * (NSPAN * HH) + i];
        if (mat == 0)      d_A[i]  = s;
        else if (mat == 1) d_Bt[i] = s;
        else               d_m1[i] = s;
    }
}

// ---------------------------------------------------------------------------
// k_ment: mention MLP tail: relu(m1+b) -> 150x150 -> dot -> d_ms
// ---------------------------------------------------------------------------
__global__ void __launch_bounds__(160) k_ment(
    const float* __restrict__ mb1, const float* __restrict__ mw2,
    const float* __restrict__ mb2, const float* __restrict__ mw3,
    const float* __restrict__ mb3)
{
    int s = blockIdx.x;
    int tid = threadIdx.x;
    __shared__ float s1[HH];
    __shared__ float warpsum[8];

    if (tid < HH) s1[tid] = fmaxf(d_m1[s * HH + tid] + mb1[tid], 0.f);
    __syncthreads();
    float p = 0.f;
    if (tid < HH) {
        float v = mb2[tid];
        for (int k = 0; k < HH; k++) v += s1[k] * mw2[k * HH + tid];
        p = fmaxf(v, 0.f) * mw3[tid];
    }
    #pragma unroll
    for (int o = 16; o > 0; o >>= 1) p += __shfl_down_sync(0xffffffffu, p, o);
    if ((tid & 31) == 0) warpsum[tid >> 5] = p;
    __syncthreads();
    if (tid == 0) {
        float t = mb3[0];
        for (int w = 0; w < 5; w++) t += warpsum[w];
        d_ms[s] = t;
    }
}

// ---------------------------------------------------------------------------
// k_pair: dominant kernel. Block = (b, i, j-chunk of 32).
//   C_ij[h] = sum_k g_i[k]*g_j[k]*Wc[k,h] via smem-staged diag(g_i)*Wc tiles.
//   Fused: + A[i] + B[j] + pb1, relu, 150x150 layer-2, relu, final dot,
//   mention combine, /3, clip.
// ---------------------------------------------------------------------------
__global__ void __launch_bounds__(160) k_pair(
    const float* __restrict__ pw1, const float* __restrict__ pb1,
    const float* __restrict__ pw2, const float* __restrict__ pb2,
    const float* __restrict__ pw3, const float* __restrict__ pb3,
    float* __restrict__ out)
{
    int blk = blockIdx.x;
    int bi = blk / 3;              // global span index of i  (0..191)
    int jc = blk % 3;
    int b = bi / SS;
    int j0 = jc * 32;
    int tid = threadIdx.x;

    const float* Wc = pw1 + (size_t)2 * E3 * HH;
    const float* gi = d_g + (size_t)bi * E3;
    const float* Gb = d_g + (size_t)b * SS * E3;

    __shared__ float ws[16][HH + 2];   // diag(g_i)-scaled Wc tile
    __shared__ float gs[32][16];       // G tile (32 j-rows)
    __shared__ float s1[32][HH + 2];   // h1 / h2 staging

    float acc[32];
    #pragma unroll
    for (int t = 0; t < 32; t++) acc[t] = 0.f;

    for (int k0 = 0; k0 < E3; k0 += 16) {
        for (int idx = tid; idx < 16 * HH; idx += 160) {
            int kk = idx / HH, h = idx - kk * HH;
            ws[kk][h] = gi[k0 + kk] * Wc[(size_t)(k0 + kk) * HH + h];
        }
        for (int idx = tid; idx < 512; idx += 160) {
            int t = idx >> 4, kk = idx & 15;
            gs[t][kk] = Gb[(size_t)(j0 + t) * E3 + k0 + kk];
        }
        __syncthreads();
        if (tid < HH) {
            #pragma unroll
            for (int kk = 0; kk < 16; kk++) {
                float w = ws[kk][tid];
                #pragma unroll
                for (int t = 0; t < 32; t++) acc[t] += gs[t][kk] * w;
            }
        }
        __syncthreads();
    }

    // layer-1 epilogue: + A[i] + B[j] + pb1, relu
    if (tid < HH) {
        float a = d_A[bi * HH + tid] + pb1[tid];
        #pragma unroll
        for (int t = 0; t < 32; t++) {
            float v = acc[t] + a + d_Bt[(b * SS + j0 + t) * HH + tid];
            s1[t][tid] = fmaxf(v, 0.f);
        }
    }
    __syncthreads();

    // layer-2: 150 x 150
    if (tid < HH) {
        #pragma unroll
        for (int t = 0; t < 32; t++) acc[t] = pb2[tid];
        #pragma unroll 2
        for (int k = 0; k < HH; k++) {
            float w = pw2[k * HH + tid];
            #pragma unroll
            for (int t = 0; t < 32; t++) acc[t] += s1[t][k] * w;
        }
    }
    __syncthreads();
    if (tid < HH) {
        #pragma unroll
        for (int t = 0; t < 32; t++) s1[t][tid] = fmaxf(acc[t], 0.f);
    }
    __syncthreads();

    // layer-3 + mention combine + clip
    if (tid < 32) {
        int t = tid;
        float sc = pb3[0];
        for (int h = 0; h < HH; h++) sc += s1[t][h] * pw3[h];
        float v = (d_ms[bi] + d_ms[b * SS + j0 + t] + sc) * (1.f / 3.f);
        v = fminf(fmaxf(v, 0.f), 1.f);
        out[(size_t)bi * SS + j0 + t] = v;
    }
}

// ---------------------------------------------------------------------------
extern "C" void kernel_launch(void* const* d_in, const int* in_sizes, int n_in,
                              void* d_out, int out_size)
{
    const float* X   = (const float*)d_in[0];
    const void*  sp  = d_in[1];
    const float* aw1 = (const float*)d_in[2];
    const float* ab1 = (const float*)d_in[3];
    const float* aw2 = (const float*)d_in[4];
    const float* ab2 = (const float*)d_in[5];
    const float* aw3 = (const float*)d_in[6];
    const float* ab3 = (const float*)d_in[7];
    const float* mw1 = (const float*)d_in[8];
    const float* mb1 = (const float*)d_in[9];
    const float* mw2 = (const float*)d_in[10];
    const float* mb2 = (const float*)d_in[11];
    const float* mw3 = (const float*)d_in[12];
    const float* mb3 = (const float*)d_in[13];
    const float* pw1 = (const float*)d_in[14];
    const float* pb1 = (const float*)d_in[15];
    const float* pw2 = (const float*)d_in[16];
    const float* pb2 = (const float*)d_in[17];
    const float* pw3 = (const float*)d_in[18];
    const float* pb3 = (const float*)d_in[19];
    float* out = (float*)d_out;

    k_init<<<1, 192>>>(sp);
    k_span<<<NSPAN, 160>>>(X, aw1, ab1, aw2, ab2, aw3, ab3);
    k_terms<<<144, 160>>>(pw1, mw1);
    k_reduce<<<(NSPAN * HH + 255) / 256, 256>>>();
    k_ment<<<NSPAN, 160>>>(mb1, mw2, mb2, mw3, mb3);
    k_pair<<<NSPAN * 3, 160>>>(pw1, pb1, pw2, pb2, pw3, pb3, out);
}

// round 2
// speedup vs baseline: 1.5904x; 1.5904x over previous
#include <cuda_runtime.h>

#define BB 2
#define TT 2048
#define EE 768
#define SS 96
#define HH 150
#define HP 152
#define WW 8
#define E3 2304
#define NSPAN (BB*SS)   // 192

// -------- device scratch (no allocations allowed) --------
__device__ int   d_starts[NSPAN];
__device__ float d_g[NSPAN * E3];              // [span][ start | end | attnsum ]
__device__ float d_part[3 * 8 * NSPAN * HH];   // k-split partials: [mat][ks][span][h]
__device__ float d_A[NSPAN * HH];              // g_i @ Wa
__device__ float d_Bt[NSPAN * HH];             // g_j @ Wb
__device__ float d_m1[NSPAN * HH];             // mention layer-1 pre-bias
__device__ float d_ms[NSPAN];                  // mention scores

// ---------------------------------------------------------------------------
// k_init: convert span_starts to int32 (handles int64-or-int32 ambiguity)
// ---------------------------------------------------------------------------
__global__ void k_init(const void* sp) {
    __shared__ int is64;
    if (threadIdx.x == 0) {
        const int* w32 = (const int*)sp;
        int z = 1;
        for (int i = 1; i < 64; i += 2) if (w32[i] != 0) { z = 0; break; }
        is64 = z;
    }
    __syncthreads();
    int i = threadIdx.x;
    if (i < NSPAN) {
        if (is64) d_starts[i] = (int)((const long long*)sp)[i];
        else      d_starts[i] = ((const int*)sp)[i];
    }
}

// ---------------------------------------------------------------------------
// k_span: per-span attn MLP (8 tokens) + build g_i  (one block per span)
// ---------------------------------------------------------------------------
__global__ void __launch_bounds__(160) k_span(
    const float* __restrict__ X,
    const float* __restrict__ aw1, const float* __restrict__ ab1,
    const float* __restrict__ aw2, const float* __restrict__ ab2,
    const float* __restrict__ aw3, const float* __restrict__ ab3)
{
    int bi = blockIdx.x;
    int b = bi / SS;
    int st = d_starts[bi];
    int tid = threadIdx.x;

    __shared__ __align__(16) float xs[WW * EE];   // 8 contiguous tokens
    __shared__ float s1[WW][HH + 2];
    __shared__ float s2[WW][HH + 2];
    __shared__ float at[WW];

    const float* Xb = X + ((size_t)b * TT + st) * EE;
    for (int idx = tid; idx < WW * EE; idx += 160) xs[idx] = Xb[idx];
    __syncthreads();

    if (tid < HH) {
        float acc[WW];
        #pragma unroll
        for (int w = 0; w < WW; w++) acc[w] = ab1[tid];
        for (int k = 0; k < EE; k += 4) {
            float w0 = aw1[(k + 0) * HH + tid];
            float w1 = aw1[(k + 1) * HH + tid];
            float w2 = aw1[(k + 2) * HH + tid];
            float w3 = aw1[(k + 3) * HH + tid];
            #pragma unroll
            for (int w = 0; w < WW; w++) {
                float4 xv = *(const float4*)&xs[w * EE + k];
                acc[w] += xv.x * w0 + xv.y * w1 + xv.z * w2 + xv.w * w3;
            }
        }
        #pragma unroll
        for (int w = 0; w < WW; w++) s1[w][tid] = fmaxf(acc[w], 0.f);
    }
    __syncthreads();
    if (tid < HH) {
        float acc[WW];
        #pragma unroll
        for (int w = 0; w < WW; w++) acc[w] = ab2[tid];
        #pragma unroll 2
        for (int k = 0; k < HH; k++) {
            float wg = aw2[k * HH + tid];
            #pragma unroll
            for (int w = 0; w < WW; w++) acc[w] += s1[w][k] * wg;
        }
        #pragma unroll
        for (int w = 0; w < WW; w++) s2[w][tid] = fmaxf(acc[w], 0.f);
    }
    __syncthreads();
    if (tid < WW) {
        float a = ab3[0];
        for (int h = 0; h < HH; h++) a += s2[tid][h] * aw3[h];
        at[tid] = a;
    }
    __syncthreads();

    float* gp = d_g + (size_t)bi * E3;
    for (int e = tid; e < EE; e += 160) {
        gp[e]          = xs[e];
        gp[EE + e]     = xs[7 * EE + e];
        float s = 0.f;
        #pragma unroll
        for (int w = 0; w < WW; w++) s += xs[w * EE + e] * at[w];
        gp[2 * EE + e] = s;
    }
}

// ---------------------------------------------------------------------------
// k_terms: [192 spans, 2304] @ {Wa | Wb | mw1} with k-split partials.
// grid = 144: sc(6 span-chunks of 32) x mat(3) x ks(8 k-splits of 288)
// ---------------------------------------------------------------------------
__global__ void __launch_bounds__(160) k_terms(
    const float* __restrict__ pw1, const float* __restrict__ mw1)
{
    int x = blockIdx.x;
    int sc  = x % 6;
    int mat = (x / 6) % 3;
    int ks  = x / 18;
    const float* Wm = (mat == 0) ? pw1 : (mat == 1 ? pw1 + (size_t)E3 * HH : mw1);
    int s0 = sc * 32;
    int kbase = ks * 288;
    int tid = threadIdx.x;

    __shared__ __align__(16) float4 gs4[32][4];
    float* gsf = (float*)gs4;

    float acc[32];
    #pragma unroll
    for (int t = 0; t < 32; t++) acc[t] = 0.f;

    for (int kc = 0; kc < 288; kc += 16) {
        int k0 = kbase + kc;
        for (int idx = tid; idx < 512; idx += 160) {
            int t = idx >> 4, kk = idx & 15;
            gsf[idx] = d_g[(size_t)(s0 + t) * E3 + k0 + kk];
        }
        __syncthreads();
        if (tid < HH) {
            float wreg[16];
            #pragma unroll
            for (int kk = 0; kk < 16; kk++) wreg[kk] = Wm[(size_t)(k0 + kk) * HH + tid];
            #pragma unroll
            for (int t = 0; t < 32; t++) {
                float4 a0 = gs4[t][0], a1 = gs4[t][1], a2 = gs4[t][2], a3 = gs4[t][3];
                float s = acc[t];
                s += a0.x*wreg[0]  + a0.y*wreg[1]  + a0.z*wreg[2]  + a0.w*wreg[3];
                s += a1.x*wreg[4]  + a1.y*wreg[5]  + a1.z*wreg[6]  + a1.w*wreg[7];
                s += a2.x*wreg[8]  + a2.y*wreg[9]  + a2.z*wreg[10] + a2.w*wreg[11];
                s += a3.x*wreg[12] + a3.y*wreg[13] + a3.z*wreg[14] + a3.w*wreg[15];
                acc[t] = s;
            }
        }
        __syncthreads();
    }
    if (tid < HH) {
        float* op = d_part + (((size_t)mat * 8 + ks) * NSPAN + s0) * HH + tid;
        #pragma unroll
        for (int t = 0; t < 32; t++) op[t * HH] = acc[t];
    }
}

// ---------------------------------------------------------------------------
// k_reduce: sum k-split partials into d_A / d_Bt / d_m1 (deterministic)
// ---------------------------------------------------------------------------
__global__ void k_reduce() {
    int i = blockIdx.x * blockDim.x + threadIdx.x;
    if (i >= NSPAN * HH) return;
    #pragma unroll
    for (int mat = 0; mat < 3; mat++) {
        float s = 0.f;
        #pragma unroll
        for (int ks = 0; ks < 8; ks++)
            s += d_part[((size_t)mat * 8 + ks) * (NSPAN * HH) + i];
        if (mat == 0)      d_A[i]  = s;
        else if (mat == 1) d_Bt[i] = s;
        else               d_m1[i] = s;
    }
}

// ---------------------------------------------------------------------------
// k_ment: mention MLP tail
// ---------------------------------------------------------------------------
__global__ void __launch_bounds__(160) k_ment(
    const float* __restrict__ mb1, const float* __restrict__ mw2,
    const float* __restrict__ mb2, const float* __restrict__ mw3,
    const float* __restrict__ mb3)
{
    int s = blockIdx.x;
    int tid = threadIdx.x;
    __shared__ float s1[HH];
    __shared__ float warpsum[8];

    if (tid < HH) s1[tid] = fmaxf(d_m1[s * HH + tid] + mb1[tid], 0.f);
    __syncthreads();
    float p = 0.f;
    if (tid < HH) {
        float v = mb2[tid];
        for (int k = 0; k < HH; k++) v += s1[k] * mw2[k * HH + tid];
        p = fmaxf(v, 0.f) * mw3[tid];
    }
    #pragma unroll
    for (int o = 16; o > 0; o >>= 1) p += __shfl_down_sync(0xffffffffu, p, o);
    if ((tid & 31) == 0) warpsum[tid >> 5] = p;
    __syncthreads();
    if (tid == 0) {
        float t = mb3[0];
        for (int w = 0; w < 5; w++) t += warpsum[w];
        d_ms[s] = t;
    }
}

// ---------------------------------------------------------------------------
// k_pair: dominant kernel. Block = (i, 32-j chunk).
//   C[j,h] = sum_k (g_j[k]*g_i[k]) * Wc[k,h] : gi-scaling folded into gs tile,
//   Wc read straight from L2 into 16 registers/chunk. float4 smem broadcasts.
//   Fused: layer-1 epilogue, layer-2 (float4), layer-3, mention combine, clip.
// ---------------------------------------------------------------------------
__global__ void __launch_bounds__(160) k_pair(
    const float* __restrict__ pw1, const float* __restrict__ pb1,
    const float* __restrict__ pw2, const float* __restrict__ pb2,
    const float* __restrict__ pw3, const float* __restrict__ pb3,
    float* __restrict__ out)
{
    int blk = blockIdx.x;
    int bi = blk / 3;              // global span index of i (0..191)
    int jc = blk % 3;
    int b = bi / SS;
    int j0 = jc * 32;
    int tid = threadIdx.x;

    const float* Wc = pw1 + (size_t)2 * E3 * HH;
    const float* gi = d_g + (size_t)bi * E3;
    const float* Gb = d_g + (size_t)b * SS * E3;

    __shared__ __align__(16) float4 gs4[32][4];    // gi-scaled g_j tile
    __shared__ __align__(16) float s1[32][HP];     // h1/h2 staging (padded)
    float* gsf = (float*)gs4;

    float acc[32];
    #pragma unroll
    for (int t = 0; t < 32; t++) acc[t] = 0.f;

    for (int k0 = 0; k0 < E3; k0 += 16) {
        for (int idx = tid; idx < 512; idx += 160) {
            int t = idx >> 4, kk = idx & 15;
            gsf[idx] = Gb[(size_t)(j0 + t) * E3 + k0 + kk] * gi[k0 + kk];
        }
        __syncthreads();
        if (tid < HH) {
            float wreg[16];
            #pragma unroll
            for (int kk = 0; kk < 16; kk++) wreg[kk] = Wc[(size_t)(k0 + kk) * HH + tid];
            #pragma unroll
            for (int t = 0; t < 32; t++) {
                float4 a0 = gs4[t][0], a1 = gs4[t][1], a2 = gs4[t][2], a3 = gs4[t][3];
                float s = acc[t];
                s += a0.x*wreg[0]  + a0.y*wreg[1]  + a0.z*wreg[2]  + a0.w*wreg[3];
                s += a1.x*wreg[4]  + a1.y*wreg[5]  + a1.z*wreg[6]  + a1.w*wreg[7];
                s += a2.x*wreg[8]  + a2.y*wreg[9]  + a2.z*wreg[10] + a2.w*wreg[11];
                s += a3.x*wreg[12] + a3.y*wreg[13] + a3.z*wreg[14] + a3.w*wreg[15];
                acc[t] = s;
            }
        }
        __syncthreads();
    }

    // layer-1 epilogue: + A[i] + B[j] + pb1, relu  (pad cols 150,151 with 0)
    if (tid < HH) {
        float a = d_A[bi * HH + tid] + pb1[tid];
        #pragma unroll
        for (int t = 0; t < 32; t++) {
            float v = acc[t] + a + d_Bt[(b * SS + j0 + t) * HH + tid];
            s1[t][tid] = fmaxf(v, 0.f);
        }
    } else if (tid < HP) {
        #pragma unroll
        for (int t = 0; t < 32; t++) s1[t][tid] = 0.f;
    }
    __syncthreads();

    // layer-2: 150 x 150, float4 over s1 rows
    if (tid < HH) {
        #pragma unroll
        for (int t = 0; t < 32; t++) acc[t] = pb2[tid];
        for (int kq = 0; kq < 37; kq++) {
            int k = kq * 4;
            float w0 = pw2[(k + 0) * HH + tid];
            float w1 = pw2[(k + 1) * HH + tid];
            float w2 = pw2[(k + 2) * HH + tid];
            float w3 = pw2[(k + 3) * HH + tid];
            #pragma unroll
            for (int t = 0; t < 32; t++) {
                float4 sv = *(const float4*)&s1[t][k];
                acc[t] += sv.x * w0 + sv.y * w1 + sv.z * w2 + sv.w * w3;
            }
        }
        // remainder k = 148, 149
        {
            float w0 = pw2[148 * HH + tid];
            float w1 = pw2[149 * HH + tid];
            #pragma unroll
            for (int t = 0; t < 32; t++)
                acc[t] += s1[t][148] * w0 + s1[t][149] * w1;
        }
    }
    __syncthreads();
    if (tid < HH) {
        #pragma unroll
        for (int t = 0; t < 32; t++) s1[t][tid] = fmaxf(acc[t], 0.f);
    }
    __syncthreads();

    // layer-3 + mention combine + clip
    if (tid < 32) {
        int t = tid;
        float sc = pb3[0];
        for (int h = 0; h < HH; h++) sc += s1[t][h] * pw3[h];
        float v = (d_ms[bi] + d_ms[b * SS + j0 + t] + sc) * (1.f / 3.f);
        v = fminf(fmaxf(v, 0.f), 1.f);
        out[(size_t)bi * SS + j0 + t] = v;
    }
}

// ---------------------------------------------------------------------------
extern "C" void kernel_launch(void* const* d_in, const int* in_sizes, int n_in,
                              void* d_out, int out_size)
{
    const float* X   = (const float*)d_in[0];
    const void*  sp  = d_in[1];
    const float* aw1 = (const float*)d_in[2];
    const float* ab1 = (const float*)d_in[3];
    const float* aw2 = (const float*)d_in[4];
    const float* ab2 = (const float*)d_in[5];
    const float* aw3 = (const float*)d_in[6];
    const float* ab3 = (const float*)d_in[7];
    const float* mw1 = (const float*)d_in[8];
    const float* mb1 = (const float*)d_in[9];
    const float* mw2 = (const float*)d_in[10];
    const float* mb2 = (const float*)d_in[11];
    const float* mw3 = (const float*)d_in[12];
    const float* mb3 = (const float*)d_in[13];
    const float* pw1 = (const float*)d_in[14];
    const float* pb1 = (const float*)d_in[15];
    const float* pw2 = (const float*)d_in[16];
    const float* pb2 = (const float*)d_in[17];
    const float* pw3 = (const float*)d_in[18];
    const float* pb3 = (const float*)d_in[19];
    float* out = (float*)d_out;

    k_init<<<1, 192>>>(sp);
    k_span<<<NSPAN, 160>>>(X, aw1, ab1, aw2, ab2, aw3, ab3);
    k_terms<<<144, 160>>>(pw1, mw1);
    k_reduce<<<(NSPAN * HH + 255) / 256, 256>>>();
    k_ment<<<NSPAN, 160>>>(mb1, mw2, mb2, mw3, mb3);
    k_pair<<<NSPAN * 3, 160>>>(pw1, pb1, pw2, pb2, pw3, pb3, out);
}

// round 3
// speedup vs baseline: 2.3382x; 1.4702x over previous
#include <cuda_runtime.h>

#define BB 2
#define TT 2048
#define EE 768
#define SS 96
#define HH 150
#define HPAD 160
#define WW 8
#define E3 2304
#define NSPAN (BB*SS)   // 192

// -------- device scratch --------
__device__ int   d_starts[NSPAN];
__device__ float d_g[NSPAN * E3];
__device__ float d_part[3 * 8 * NSPAN * HH];
__device__ float d_A[NSPAN * HH];
__device__ float d_Bt[NSPAN * HH];
__device__ float d_m1[NSPAN * HH];
__device__ float d_ms[NSPAN];

// ---------------------------------------------------------------------------
__global__ void k_init(const void* sp) {
    __shared__ int is64;
    if (threadIdx.x == 0) {
        const int* w32 = (const int*)sp;
        int z = 1;
        for (int i = 1; i < 64; i += 2) if (w32[i] != 0) { z = 0; break; }
        is64 = z;
    }
    __syncthreads();
    int i = threadIdx.x;
    if (i < NSPAN) {
        if (is64) d_starts[i] = (int)((const long long*)sp)[i];
        else      d_starts[i] = ((const int*)sp)[i];
    }
}

// ---------------------------------------------------------------------------
__global__ void __launch_bounds__(160) k_span(
    const float* __restrict__ X,
    const float* __restrict__ aw1, const float* __restrict__ ab1,
    const float* __restrict__ aw2, const float* __restrict__ ab2,
    const float* __restrict__ aw3, const float* __restrict__ ab3)
{
    int bi = blockIdx.x;
    int b = bi / SS;
    int st = d_starts[bi];
    int tid = threadIdx.x;

    __shared__ __align__(16) float xs[WW * EE];
    __shared__ float s1[WW][HH + 2];
    __shared__ float s2[WW][HH + 2];
    __shared__ float at[WW];

    const float* Xb = X + ((size_t)b * TT + st) * EE;
    for (int idx = tid; idx < WW * EE; idx += 160) xs[idx] = Xb[idx];
    __syncthreads();

    if (tid < HH) {
        float acc[WW];
        #pragma unroll
        for (int w = 0; w < WW; w++) acc[w] = ab1[tid];
        for (int k = 0; k < EE; k += 4) {
            float w0 = aw1[(k + 0) * HH + tid];
            float w1 = aw1[(k + 1) * HH + tid];
            float w2 = aw1[(k + 2) * HH + tid];
            float w3 = aw1[(k + 3) * HH + tid];
            #pragma unroll
            for (int w = 0; w < WW; w++) {
                float4 xv = *(const float4*)&xs[w * EE + k];
                acc[w] += xv.x * w0 + xv.y * w1 + xv.z * w2 + xv.w * w3;
            }
        }
        #pragma unroll
        for (int w = 0; w < WW; w++) s1[w][tid] = fmaxf(acc[w], 0.f);
    }
    __syncthreads();
    if (tid < HH) {
        float acc[WW];
        #pragma unroll
        for (int w = 0; w < WW; w++) acc[w] = ab2[tid];
        #pragma unroll 2
        for (int k = 0; k < HH; k++) {
            float wg = aw2[k * HH + tid];
            #pragma unroll
            for (int w = 0; w < WW; w++) acc[w] += s1[w][k] * wg;
        }
        #pragma unroll
        for (int w = 0; w < WW; w++) s2[w][tid] = fmaxf(acc[w], 0.f);
    }
    __syncthreads();
    if (tid < WW) {
        float a = ab3[0];
        for (int h = 0; h < HH; h++) a += s2[tid][h] * aw3[h];
        at[tid] = a;
    }
    __syncthreads();

    float* gp = d_g + (size_t)bi * E3;
    for (int e = tid; e < EE; e += 160) {
        gp[e]          = xs[e];
        gp[EE + e]     = xs[7 * EE + e];
        float s = 0.f;
        #pragma unroll
        for (int w = 0; w < WW; w++) s += xs[w * EE + e] * at[w];
        gp[2 * EE + e] = s;
    }
}

// ---------------------------------------------------------------------------
__global__ void __launch_bounds__(160) k_terms(
    const float* __restrict__ pw1, const float* __restrict__ mw1)
{
    int x = blockIdx.x;
    int sc  = x % 6;
    int mat = (x / 6) % 3;
    int ks  = x / 18;
    const float* Wm = (mat == 0) ? pw1 : (mat == 1 ? pw1 + (size_t)E3 * HH : mw1);
    int s0 = sc * 32;
    int kbase = ks * 288;
    int tid = threadIdx.x;

    __shared__ __align__(16) float4 gs4[32][4];
    float* gsf = (float*)gs4;

    float acc[32];
    #pragma unroll
    for (int t = 0; t < 32; t++) acc[t] = 0.f;

    for (int kc = 0; kc < 288; kc += 16) {
        int k0 = kbase + kc;
        for (int idx = tid; idx < 512; idx += 160) {
            int t = idx >> 4, kk = idx & 15;
            gsf[idx] = d_g[(size_t)(s0 + t) * E3 + k0 + kk];
        }
        __syncthreads();
        if (tid < HH) {
            float wreg[16];
            #pragma unroll
            for (int kk = 0; kk < 16; kk++) wreg[kk] = Wm[(size_t)(k0 + kk) * HH + tid];
            #pragma unroll
            for (int t = 0; t < 32; t++) {
                float4 a0 = gs4[t][0], a1 = gs4[t][1], a2 = gs4[t][2], a3 = gs4[t][3];
                float s = acc[t];
                s += a0.x*wreg[0]  + a0.y*wreg[1]  + a0.z*wreg[2]  + a0.w*wreg[3];
                s += a1.x*wreg[4]  + a1.y*wreg[5]  + a1.z*wreg[6]  + a1.w*wreg[7];
                s += a2.x*wreg[8]  + a2.y*wreg[9]  + a2.z*wreg[10] + a2.w*wreg[11];
                s += a3.x*wreg[12] + a3.y*wreg[13] + a3.z*wreg[14] + a3.w*wreg[15];
                acc[t] = s;
            }
        }
        __syncthreads();
    }
    if (tid < HH) {
        float* op = d_part + (((size_t)mat * 8 + ks) * NSPAN + s0) * HH + tid;
        #pragma unroll
        for (int t = 0; t < 32; t++) op[t * HH] = acc[t];
    }
}

// ---------------------------------------------------------------------------
__global__ void k_reduce() {
    int i = blockIdx.x * blockDim.x + threadIdx.x;
    if (i >= NSPAN * HH) return;
    #pragma unroll
    for (int mat = 0; mat < 3; mat++) {
        float s = 0.f;
        #pragma unroll
        for (int ks = 0; ks < 8; ks++)
            s += d_part[((size_t)mat * 8 + ks) * (NSPAN * HH) + i];
        if (mat == 0)      d_A[i]  = s;
        else if (mat == 1) d_Bt[i] = s;
        else               d_m1[i] = s;
    }
}

// ---------------------------------------------------------------------------
__global__ void __launch_bounds__(160) k_ment(
    const float* __restrict__ mb1, const float* __restrict__ mw2,
    const float* __restrict__ mb2, const float* __restrict__ mw3,
    const float* __restrict__ mb3)
{
    int s = blockIdx.x;
    int tid = threadIdx.x;
    __shared__ float s1[HH];
    __shared__ float warpsum[8];

    if (tid < HH) s1[tid] = fmaxf(d_m1[s * HH + tid] + mb1[tid], 0.f);
    __syncthreads();
    float p = 0.f;
    if (tid < HH) {
        float v = mb2[tid];
        for (int k = 0; k < HH; k++) v += s1[k] * mw2[k * HH + tid];
        p = fmaxf(v, 0.f) * mw3[tid];
    }
    #pragma unroll
    for (int o = 16; o > 0; o >>= 1) p += __shfl_down_sync(0xffffffffu, p, o);
    if ((tid & 31) == 0) warpsum[tid >> 5] = p;
    __syncthreads();
    if (tid == 0) {
        float t = mb3[0];
        for (int w = 0; w < 5; w++) t += warpsum[w];
        d_ms[s] = t;
    }
}

// ---------------------------------------------------------------------------
// k_pair: triangular (i-chunk<=j-chunk) C-tile + dual epilogues.
// 256 threads: warp jg owns 4 j-rows, lane hg owns 5 h-cols (h padded to 160).
// ---------------------------------------------------------------------------
struct EpiArgs {
    const float* Abase; int Astr;     // A term: base at t=0, stride per t
    const float* Bbase; int Bstr;     // B term
    const float* msF;   int msFstr;   // mention of first pair index
    const float* msS;   int msSstr;   // mention of second pair index
    float* outBase;     int outStr;   // output addr for t, stride per t
};

__device__ __forceinline__ void run_epilogue(
    const float acc[4][5], const EpiArgs& ea,
    const float* __restrict__ pb1, const float* __restrict__ pw2,
    const float* __restrict__ pb2, const float* __restrict__ pw3,
    const float* __restrict__ pb3,
    float (*s1)[HPAD], float (*ps)[36], float (*ws)[HPAD],
    int jg, int hg, int tid,
    const int* kkr, const int* hrr, const bool* okr)
{
    int h0 = 5 * hg;
    __syncthreads();
    // ---- layer-1 epilogue -> s1 (relu), pad zeros ----
    #pragma unroll
    for (int q = 0; q < 5; q++) {
        int h = h0 + q;
        #pragma unroll
        for (int jj = 0; jj < 4; jj++) {
            int t = 4 * jg + jj;
            float v = 0.f;
            if (h < HH) {
                float c = acc[jj][q] + pb1[h];
                c = c + ea.Abase[t * ea.Astr + h];
                c = c + ea.Bbase[t * ea.Bstr + h];
                v = fmaxf(c, 0.f);
            }
            s1[t][h] = v;
        }
    }
    // ---- layer-2: h2[32t,150h] = s1 @ pw2, chunked like C-term ----
    float acc2[4][5];
    #pragma unroll
    for (int jj = 0; jj < 4; jj++)
        #pragma unroll
        for (int q = 0; q < 5; q++) {
            int h = h0 + q;
            acc2[jj][q] = (h < HH) ? pb2[h] : 0.f;
        }
    for (int k0 = 0; k0 < HPAD; k0 += 16) {
        __syncthreads();
        #pragma unroll
        for (int r = 0; r < 10; r++) {
            if (okr[r] && (k0 + kkr[r]) < HH)
                ws[kkr[r]][hrr[r]] = pw2[(k0 + kkr[r]) * HH + hrr[r]];
        }
        #pragma unroll
        for (int r = 0; r < 2; r++) {
            int idx = tid + 256 * r;
            int t = idx >> 4, kk = idx & 15;
            ps[kk][t] = s1[t][k0 + kk];
        }
        __syncthreads();
        #pragma unroll
        for (int kk = 0; kk < 16; kk++) {
            float4 p = *(const float4*)&ps[kk][4 * jg];
            float w0 = ws[kk][h0 + 0], w1 = ws[kk][h0 + 1], w2 = ws[kk][h0 + 2];
            float w3 = ws[kk][h0 + 3], w4 = ws[kk][h0 + 4];
            acc2[0][0] += p.x * w0; acc2[0][1] += p.x * w1; acc2[0][2] += p.x * w2;
            acc2[0][3] += p.x * w3; acc2[0][4] += p.x * w4;
            acc2[1][0] += p.y * w0; acc2[1][1] += p.y * w1; acc2[1][2] += p.y * w2;
            acc2[1][3] += p.y * w3; acc2[1][4] += p.y * w4;
            acc2[2][0] += p.z * w0; acc2[2][1] += p.z * w1; acc2[2][2] += p.z * w2;
            acc2[2][3] += p.z * w3; acc2[2][4] += p.z * w4;
            acc2[3][0] += p.w * w0; acc2[3][1] += p.w * w1; acc2[3][2] += p.w * w2;
            acc2[3][3] += p.w * w3; acc2[3][4] += p.w * w4;
        }
    }
    // ---- layer-3 in-register: relu(acc2) . pw3, warp butterfly over hg ----
    float part[4];
    #pragma unroll
    for (int jj = 0; jj < 4; jj++) {
        float s = 0.f;
        #pragma unroll
        for (int q = 0; q < 5; q++) {
            int h = h0 + q;
            if (h < HH) s += fmaxf(acc2[jj][q], 0.f) * pw3[h];
        }
        part[jj] = s;
    }
    #pragma unroll
    for (int jj = 0; jj < 4; jj++)
        #pragma unroll
        for (int off = 16; off > 0; off >>= 1)
            part[jj] += __shfl_xor_sync(0xffffffffu, part[jj], off);
    if (hg == 0) {
        #pragma unroll
        for (int jj = 0; jj < 4; jj++) {
            int t = 4 * jg + jj;
            float sc = part[jj] + pb3[0];
            float v = ((ea.msF[t * ea.msFstr] + ea.msS[t * ea.msSstr]) + sc) * (1.f / 3.f);
            v = fminf(fmaxf(v, 0.f), 1.f);
            ea.outBase[(size_t)t * ea.outStr] = v;
        }
    }
}

__global__ void __launch_bounds__(256, 2) k_pair(
    const float* __restrict__ pw1, const float* __restrict__ pb1,
    const float* __restrict__ pw2, const float* __restrict__ pb2,
    const float* __restrict__ pw3, const float* __restrict__ pb3,
    float* __restrict__ out)
{
    int x = blockIdx.x;
    int b = x / 192;
    int r = x % 192;
    int il, c;
    if (r < 96)       { il = r & 31;              c = r >> 5; }
    else if (r < 160) { int rr = r - 96;  il = 32 + (rr & 31); c = 1 + (rr >> 5); }
    else              { il = 64 + (r - 160);      c = 2; }
    int bi = b * SS + il;
    int j0 = c * 32;
    int bS = b * SS;
    int tid = threadIdx.x;
    int jg = tid >> 5;         // warp id: owns j rows 4jg..4jg+3
    int hg = tid & 31;         // lane: owns h cols 5hg..5hg+4
    int h0 = 5 * hg;

    const float* Wc = pw1 + (size_t)2 * E3 * HH;
    const float* gi = d_g + (size_t)bi * E3;
    const float* Gb = d_g + (size_t)bS * E3;

    __shared__ __align__(16) float ps[16][36];
    __shared__ __align__(16) float ws[16][HPAD];
    __shared__ __align__(16) float s1[32][HPAD];

    // precompute ws staging coords (16x160 flat over 256 threads, 10 rounds)
    int kkr[10], hrr[10]; bool okr[10];
    #pragma unroll
    for (int rr2 = 0; rr2 < 10; rr2++) {
        int idx = tid + 256 * rr2;
        kkr[rr2] = idx / HPAD;
        hrr[rr2] = idx - kkr[rr2] * HPAD;
        okr[rr2] = (hrr[rr2] < HH);
    }

    float acc[4][5];
    #pragma unroll
    for (int jj = 0; jj < 4; jj++)
        #pragma unroll
        for (int q = 0; q < 5; q++) acc[jj][q] = 0.f;

    for (int k0 = 0; k0 < E3; k0 += 16) {
        __syncthreads();
        #pragma unroll
        for (int rr2 = 0; rr2 < 10; rr2++) {
            if (okr[rr2])
                ws[kkr[rr2]][hrr[rr2]] = Wc[(size_t)(k0 + kkr[rr2]) * HH + hrr[rr2]];
        }
        #pragma unroll
        for (int rr2 = 0; rr2 < 2; rr2++) {
            int idx = tid + 256 * rr2;
            int t = idx >> 4, kk = idx & 15;
            ps[kk][t] = Gb[(size_t)(j0 + t) * E3 + k0 + kk] * gi[k0 + kk];
        }
        __syncthreads();
        #pragma unroll
        for (int kk = 0; kk < 16; kk++) {
            float4 p = *(const float4*)&ps[kk][4 * jg];
            float w0 = ws[kk][h0 + 0], w1 = ws[kk][h0 + 1], w2 = ws[kk][h0 + 2];
            float w3 = ws[kk][h0 + 3], w4 = ws[kk][h0 + 4];
            acc[0][0] += p.x * w0; acc[0][1] += p.x * w1; acc[0][2] += p.x * w2;
            acc[0][3] += p.x * w3; acc[0][4] += p.x * w4;
            acc[1][0] += p.y * w0; acc[1][1] += p.y * w1; acc[1][2] += p.y * w2;
            acc[1][3] += p.y * w3; acc[1][4] += p.y * w4;
            acc[2][0] += p.z * w0; acc[2][1] += p.z * w1; acc[2][2] += p.z * w2;
            acc[2][3] += p.z * w3; acc[2][4] += p.z * w4;
            acc[3][0] += p.w * w0; acc[3][1] += p.w * w1; acc[3][2] += p.w * w2;
            acc[3][3] += p.w * w3; acc[3][4] += p.w * w4;
        }
    }

    // ---- forward epilogue: pairs (i, j0+t) ----
    EpiArgs fa;
    fa.Abase = d_A + bi * HH;            fa.Astr = 0;
    fa.Bbase = d_Bt + (bS + j0) * HH;    fa.Bstr = HH;
    fa.msF   = d_ms + bi;                fa.msFstr = 0;
    fa.msS   = d_ms + bS + j0;           fa.msSstr = 1;
    fa.outBase = out + (size_t)bi * SS + j0;  fa.outStr = 1;
    run_epilogue(acc, fa, pb1, pw2, pb2, pw3, pb3, s1, ps, ws,
                 jg, hg, tid, kkr, hrr, okr);

    // ---- transpose epilogue: pairs (j0+t, i) ----
    EpiArgs ta;
    ta.Abase = d_A + (bS + j0) * HH;     ta.Astr = HH;
    ta.Bbase = d_Bt + bi * HH;           ta.Bstr = 0;
    ta.msF   = d_ms + bS + j0;           ta.msFstr = 1;
    ta.msS   = d_ms + bi;                ta.msSstr = 0;
    ta.outBase = out + (size_t)(bS + j0) * SS + il;  ta.outStr = SS;
    run_epilogue(acc, ta, pb1, pw2, pb2, pw3, pb3, s1, ps, ws,
                 jg, hg, tid, kkr, hrr, okr);
}

// ---------------------------------------------------------------------------
extern "C" void kernel_launch(void* const* d_in, const int* in_sizes, int n_in,
                              void* d_out, int out_size)
{
    const float* X   = (const float*)d_in[0];
    const void*  sp  = d_in[1];
    const float* aw1 = (const float*)d_in[2];
    const float* ab1 = (const float*)d_in[3];
    const float* aw2 = (const float*)d_in[4];
    const float* ab2 = (const float*)d_in[5];
    const float* aw3 = (const float*)d_in[6];
    const float* ab3 = (const float*)d_in[7];
    const float* mw1 = (const float*)d_in[8];
    const float* mb1 = (const float*)d_in[9];
    const float* mw2 = (const float*)d_in[10];
    const float* mb2 = (const float*)d_in[11];
    const float* mw3 = (const float*)d_in[12];
    const float* mb3 = (const float*)d_in[13];
    const float* pw1 = (const float*)d_in[14];
    const float* pb1 = (const float*)d_in[15];
    const float* pw2 = (const float*)d_in[16];
    const float* pb2 = (const float*)d_in[17];
    const float* pw3 = (const float*)d_in[18];
    const float* pb3 = (const float*)d_in[19];
    float* out = (float*)d_out;

    k_init<<<1, 192>>>(sp);
    k_span<<<NSPAN, 160>>>(X, aw1, ab1, aw2, ab2, aw3, ab3);
    k_terms<<<144, 160>>>(pw1, mw1);
    k_reduce<<<(NSPAN * HH + 255) / 256, 256>>>();
    k_ment<<<NSPAN, 160>>>(mb1, mw2, mb2, mw3, mb3);
    k_pair<<<2 * 192, 256>>>(pw1, pb1, pw2, pb2, pw3, pb3, out);
}

// round 4
// speedup vs baseline: 2.7418x; 1.1726x over previous
#include <cuda_runtime.h>

#define BB 2
#define TT 2048
#define EE 768
#define SS 96
#define HH 150
#define HS 168          // padded smem row stride (floats) for weight tiles
#define WW 8
#define E3 2304
#define NSPAN (BB*SS)   // 192
#define KC 32           // k-chunk of pair C-term
#define NCH (E3/KC)     // 72

// -------- device scratch --------
__device__ int   d_starts[NSPAN];
__device__ float d_g[NSPAN * E3];
__device__ float d_part[3 * 16 * NSPAN * HH];
__device__ float d_A[NSPAN * HH];
__device__ float d_Bt[NSPAN * HH];
__device__ float d_m1[NSPAN * HH];
__device__ float d_ms[NSPAN];

// ---------------------------------------------------------------------------
__global__ void k_init(const void* sp) {
    __shared__ int is64;
    if (threadIdx.x == 0) {
        const int* w32 = (const int*)sp;
        int z = 1;
        for (int i = 1; i < 64; i += 2) if (w32[i] != 0) { z = 0; break; }
        is64 = z;
    }
    __syncthreads();
    int i = threadIdx.x;
    if (i < NSPAN) {
        if (is64) d_starts[i] = (int)((const long long*)sp)[i];
        else      d_starts[i] = ((const int*)sp)[i];
    }
}

// ---------------------------------------------------------------------------
// k_span: 320 threads, k-split layer-1 for SMSP balance.
// ---------------------------------------------------------------------------
__global__ void __launch_bounds__(320) k_span(
    const float* __restrict__ X,
    const float* __restrict__ aw1, const float* __restrict__ ab1,
    const float* __restrict__ aw2, const float* __restrict__ ab2,
    const float* __restrict__ aw3, const float* __restrict__ ab3)
{
    int bi = blockIdx.x;
    int b = bi / SS;
    int st = d_starts[bi];
    int tid = threadIdx.x;

    __shared__ __align__(16) float xs[WW * EE];
    __shared__ float part[2][WW][152];
    __shared__ float s1[WW][152];
    __shared__ float s2[WW][152];
    __shared__ float at[WW];

    const float* Xb = X + ((size_t)b * TT + st) * EE;
    for (int i = tid; i < WW * EE; i += 320) xs[i] = Xb[i];
    __syncthreads();

    int half = tid / 160;
    int h = tid - half * 160;
    if (half < 2 && h < HH) {
        float acc[WW];
        #pragma unroll
        for (int w = 0; w < WW; w++) acc[w] = half ? 0.f : ab1[h];
        int kb = half * 384;
        for (int k = kb; k < kb + 384; k += 4) {
            float w0 = aw1[(k + 0) * HH + h];
            float w1 = aw1[(k + 1) * HH + h];
            float w2 = aw1[(k + 2) * HH + h];
            float w3 = aw1[(k + 3) * HH + h];
            #pragma unroll
            for (int w = 0; w < WW; w++) {
                float4 xv = *(const float4*)&xs[w * EE + k];
                acc[w] += xv.x * w0 + xv.y * w1 + xv.z * w2 + xv.w * w3;
            }
        }
        #pragma unroll
        for (int w = 0; w < WW; w++) part[half][w][h] = acc[w];
    }
    __syncthreads();

    if (tid < HH) {
        #pragma unroll
        for (int w = 0; w < WW; w++)
            s1[w][tid] = fmaxf(part[0][w][tid] + part[1][w][tid], 0.f);
    }
    __syncthreads();

    if (tid < HH) {
        float acc[WW];
        #pragma unroll
        for (int w = 0; w < WW; w++) acc[w] = ab2[tid];
        #pragma unroll 2
        for (int k = 0; k < HH; k++) {
            float wg = aw2[k * HH + tid];
            #pragma unroll
            for (int w = 0; w < WW; w++) acc[w] += s1[w][k] * wg;
        }
        #pragma unroll
        for (int w = 0; w < WW; w++) s2[w][tid] = fmaxf(acc[w], 0.f);
    }
    __syncthreads();
    if (tid < WW) {
        float a = ab3[0];
        for (int hh = 0; hh < HH; hh++) a += s2[tid][hh] * aw3[hh];
        at[tid] = a;
    }
    __syncthreads();

    float* gp = d_g + (size_t)bi * E3;
    for (int e = tid; e < EE; e += 320) {
        gp[e]          = xs[e];
        gp[EE + e]     = xs[7 * EE + e];
        float s = 0.f;
        #pragma unroll
        for (int w = 0; w < WW; w++) s += xs[w * EE + e] * at[w];
        gp[2 * EE + e] = s;
    }
}

// ---------------------------------------------------------------------------
// k_terms: 256-thread balanced tiles. grid = sc(6) x mat(3) x ks(16) = 288.
// Each block: 32 spans x 150 h over k-range 144 (9 chunks of 16).
// ---------------------------------------------------------------------------
__global__ void __launch_bounds__(256) k_terms(
    const float* __restrict__ pw1, const float* __restrict__ mw1)
{
    int x = blockIdx.x;
    int sc  = x % 6;
    int mat = (x / 6) % 3;
    int ks  = x / 18;
    const float* Wm = (mat == 0) ? pw1 : (mat == 1 ? pw1 + (size_t)E3 * HH : mw1);
    int s0 = sc * 32;
    int kbase = ks * 144;
    int tid = threadIdx.x;
    int jg = tid >> 5;       // warp: rows 4jg..4jg+3
    int hg = tid & 31;       // lane: cols 5hg..5hg+4
    int h0 = 5 * hg;
    int kk2 = tid >> 4;      // weight-staging row
    int hb2 = tid & 15;

    __shared__ __align__(16) float wst[16 * HS];
    __shared__ __align__(16) float pst[16 * 36];

    float acc[4][5];
    #pragma unroll
    for (int jj = 0; jj < 4; jj++)
        #pragma unroll
        for (int q = 0; q < 5; q++) acc[jj][q] = 0.f;

    for (int kc = 0; kc < 144; kc += 16) {
        int k0 = kbase + kc;
        __syncthreads();
        #pragma unroll
        for (int q = 0; q < 10; q++) {
            int h = hb2 + 16 * q;
            if (h < 160)
                wst[kk2 * HS + h] = (h < HH) ? Wm[(size_t)(k0 + kk2) * HH + h] : 0.f;
        }
        #pragma unroll
        for (int r = 0; r < 2; r++) {
            int idx = tid + 256 * r;
            int t = idx >> 4, kk = idx & 15;
            pst[kk * 36 + t] = d_g[(size_t)(s0 + t) * E3 + k0 + kk];
        }
        __syncthreads();
        #pragma unroll
        for (int kk = 0; kk < 16; kk++) {
            float4 p = *(const float4*)&pst[kk * 36 + 4 * jg];
            const float* wr = &wst[kk * HS + h0];
            float w0 = wr[0], w1 = wr[1], w2 = wr[2], w3 = wr[3], w4 = wr[4];
            acc[0][0] += p.x * w0; acc[0][1] += p.x * w1; acc[0][2] += p.x * w2;
            acc[0][3] += p.x * w3; acc[0][4] += p.x * w4;
            acc[1][0] += p.y * w0; acc[1][1] += p.y * w1; acc[1][2] += p.y * w2;
            acc[1][3] += p.y * w3; acc[1][4] += p.y * w4;
            acc[2][0] += p.z * w0; acc[2][1] += p.z * w1; acc[2][2] += p.z * w2;
            acc[2][3] += p.z * w3; acc[2][4] += p.z * w4;
            acc[3][0] += p.w * w0; acc[3][1] += p.w * w1; acc[3][2] += p.w * w2;
            acc[3][3] += p.w * w3; acc[3][4] += p.w * w4;
        }
    }
    #pragma unroll
    for (int jj = 0; jj < 4; jj++) {
        int t = 4 * jg + jj;
        float* op = d_part + (((size_t)mat * 16 + ks) * NSPAN + s0 + t) * HH;
        #pragma unroll
        for (int q = 0; q < 5; q++) {
            int h = h0 + q;
            if (h < HH) op[h] = acc[jj][q];
        }
    }
}

// ---------------------------------------------------------------------------
__global__ void k_reduce() {
    int i = blockIdx.x * blockDim.x + threadIdx.x;
    if (i >= NSPAN * HH) return;
    #pragma unroll
    for (int mat = 0; mat < 3; mat++) {
        float s = 0.f;
        #pragma unroll
        for (int ks = 0; ks < 16; ks++)
            s += d_part[((size_t)mat * 16 + ks) * (NSPAN * HH) + i];
        if (mat == 0)      d_A[i]  = s;
        else if (mat == 1) d_Bt[i] = s;
        else               d_m1[i] = s;
    }
}

// ---------------------------------------------------------------------------
__global__ void __launch_bounds__(160) k_ment(
    const float* __restrict__ mb1, const float* __restrict__ mw2,
    const float* __restrict__ mb2, const float* __restrict__ mw3,
    const float* __restrict__ mb3)
{
    int s = blockIdx.x;
    int tid = threadIdx.x;
    __shared__ float s1[HH];
    __shared__ float warpsum[8];

    if (tid < HH) s1[tid] = fmaxf(d_m1[s * HH + tid] + mb1[tid], 0.f);
    __syncthreads();
    float p = 0.f;
    if (tid < HH) {
        float v = mb2[tid];
        for (int k = 0; k < HH; k++) v += s1[k] * mw2[k * HH + tid];
        p = fmaxf(v, 0.f) * mw3[tid];
    }
    #pragma unroll
    for (int o = 16; o > 0; o >>= 1) p += __shfl_down_sync(0xffffffffu, p, o);
    if ((tid & 31) == 0) warpsum[tid >> 5] = p;
    __syncthreads();
    if (tid == 0) {
        float t = mb3[0];
        for (int w = 0; w < 5; w++) t += warpsum[w];
        d_ms[s] = t;
    }
}

// ---------------------------------------------------------------------------
// k_pair epilogue (shared by forward/transpose orderings)
// ---------------------------------------------------------------------------
struct EpiArgs {
    const float* Abase; int Astr;
    const float* Bbase; int Bstr;
    const float* msF;   int msFstr;
    const float* msS;   int msSstr;
    float* outBase;     int outStr;
};

__device__ __forceinline__ void run_epilogue(
    const float acc[4][5], const EpiArgs& ea,
    const float* __restrict__ pb1, const float* __restrict__ pw2,
    const float* __restrict__ pb2, const float* __restrict__ pw3,
    const float* __restrict__ pb3,
    float* s1, float* ews, float* eps,
    int jg, int hg, int tid)
{
    int h0 = 5 * hg;
    int kk2 = tid >> 4;
    int hb2 = tid & 15;
    __syncthreads();
    // ---- layer-1 epilogue -> s1 (relu), zero pad cols [150,160) ----
    #pragma unroll
    for (int q = 0; q < 5; q++) {
        int h = h0 + q;
        #pragma unroll
        for (int jj = 0; jj < 4; jj++) {
            int t = 4 * jg + jj;
            float v = 0.f;
            if (h < HH) {
                float c = acc[jj][q] + pb1[h];
                c = c + ea.Abase[t * ea.Astr + h];
                c = c + ea.Bbase[t * ea.Bstr + h];
                v = fmaxf(c, 0.f);
            }
            s1[t * HS + h] = v;
        }
    }
    // ---- layer-2 ----
    float acc2[4][5];
    #pragma unroll
    for (int jj = 0; jj < 4; jj++)
        #pragma unroll
        for (int q = 0; q < 5; q++) {
            int h = h0 + q;
            acc2[jj][q] = (h < HH) ? pb2[h] : 0.f;
        }
    for (int k0 = 0; k0 < 160; k0 += 16) {
        __syncthreads();
        #pragma unroll
        for (int q = 0; q < 10; q++) {
            int h = hb2 + 16 * q;
            if (h < 160) {
                float v = 0.f;
                if ((k0 + kk2) < HH && h < HH) v = pw2[(k0 + kk2) * HH + h];
                ews[kk2 * HS + h] = v;
            }
        }
        #pragma unroll
        for (int r = 0; r < 2; r++) {
            int idx = tid + 256 * r;
            int t = idx >> 4, kk = idx & 15;
            eps[kk * 36 + t] = s1[t * HS + k0 + kk];
        }
        __syncthreads();
        #pragma unroll
        for (int kk = 0; kk < 16; kk++) {
            float4 p = *(const float4*)&eps[kk * 36 + 4 * jg];
            const float* wr = &ews[kk * HS + h0];
            float w0 = wr[0], w1 = wr[1], w2 = wr[2], w3 = wr[3], w4 = wr[4];
            acc2[0][0] += p.x * w0; acc2[0][1] += p.x * w1; acc2[0][2] += p.x * w2;
            acc2[0][3] += p.x * w3; acc2[0][4] += p.x * w4;
            acc2[1][0] += p.y * w0; acc2[1][1] += p.y * w1; acc2[1][2] += p.y * w2;
            acc2[1][3] += p.y * w3; acc2[1][4] += p.y * w4;
            acc2[2][0] += p.z * w0; acc2[2][1] += p.z * w1; acc2[2][2] += p.z * w2;
            acc2[2][3] += p.z * w3; acc2[2][4] += p.z * w4;
            acc2[3][0] += p.w * w0; acc2[3][1] += p.w * w1; acc2[3][2] += p.w * w2;
            acc2[3][3] += p.w * w3; acc2[3][4] += p.w * w4;
        }
    }
    // ---- layer-3: relu(acc2) . pw3, warp butterfly over hg ----
    float part[4];
    #pragma unroll
    for (int jj = 0; jj < 4; jj++) {
        float s = 0.f;
        #pragma unroll
        for (int q = 0; q < 5; q++) {
            int h = h0 + q;
            if (h < HH) s += fmaxf(acc2[jj][q], 0.f) * pw3[h];
        }
        part[jj] = s;
    }
    #pragma unroll
    for (int jj = 0; jj < 4; jj++)
        #pragma unroll
        for (int off = 16; off > 0; off >>= 1)
            part[jj] += __shfl_xor_sync(0xffffffffu, part[jj], off);
    if (hg == 0) {
        #pragma unroll
        for (int jj = 0; jj < 4; jj++) {
            int t = 4 * jg + jj;
            float sc = part[jj] + pb3[0];
            float v = ((ea.msF[t * ea.msFstr] + ea.msS[t * ea.msSstr]) + sc) * (1.f / 3.f);
            v = fminf(fmaxf(v, 0.f), 1.f);
            ea.outBase[(size_t)t * ea.outStr] = v;
        }
    }
}

// ---------------------------------------------------------------------------
// k_pair: triangular C-tiles, double-buffered KC=32 staging, dual epilogues.
// ---------------------------------------------------------------------------
__global__ void __launch_bounds__(256, 2) k_pair(
    const float* __restrict__ pw1, const float* __restrict__ pb1,
    const float* __restrict__ pw2, const float* __restrict__ pb2,
    const float* __restrict__ pw3, const float* __restrict__ pb3,
    float* __restrict__ out)
{
    extern __shared__ __align__(16) float sm[];
    float* ws0 = sm;                   // 32*HS = 5376 floats
    float* ws1 = sm + 32 * HS;         // 5376
    float* ps0 = sm + 64 * HS;         // 32*36 = 1152
    float* ps1 = ps0 + 32 * 36;        // 1152
    float* s1  = ws0;                  // epilogue aliases
    float* ews = ws1;
    float* eps = ps0;

    int x = blockIdx.x;
    int b = x / 192;
    int r = x % 192;
    int il, c;
    if (r < 96)       { il = r & 31;              c = r >> 5; }
    else if (r < 160) { int rr = r - 96;  il = 32 + (rr & 31); c = 1 + (rr >> 5); }
    else              { il = 64 + (r - 160);      c = 2; }
    int bi = b * SS + il;
    int j0 = c * 32;
    int bS = b * SS;
    int tid = threadIdx.x;
    int jg = tid >> 5;         // warp: rows 4jg..4jg+3
    int hg = tid & 31;         // lane: cols 5hg..5hg+4
    int h0 = 5 * hg;
    int kkw = tid >> 3;        // ws staging row (0..31)
    int hbw = tid & 7;         // ws staging col base
    int kkp = tid & 31;        // ps staging row
    int tp  = tid >> 5;        // ps staging t base

    const float* Wc = pw1 + (size_t)2 * E3 * HH;
    const float* gi = d_g + (size_t)bi * E3;
    const float* Gb = d_g + (size_t)bS * E3;

    float acc[4][5];
    #pragma unroll
    for (int jj = 0; jj < 4; jj++)
        #pragma unroll
        for (int q = 0; q < 5; q++) acc[jj][q] = 0.f;

    float wre[20], pre[4];

    // ---- prefetch chunk 0 ----
    {
        const float* wrow = Wc + (size_t)kkw * HH;
        #pragma unroll
        for (int q = 0; q < 20; q++) {
            int h = hbw + 8 * q;
            wre[q] = (h < HH) ? wrow[h] : 0.f;
        }
        float gv = gi[kkp];
        #pragma unroll
        for (int rr = 0; rr < 4; rr++) {
            int t = tp + 8 * rr;
            pre[rr] = Gb[(size_t)(j0 + t) * E3 + kkp] * gv;
        }
        #pragma unroll
        for (int q = 0; q < 20; q++) ws0[kkw * HS + hbw + 8 * q] = wre[q];
        #pragma unroll
        for (int rr = 0; rr < 4; rr++) ps0[kkp * 36 + tp + 8 * rr] = pre[rr];
    }
    __syncthreads();

    for (int ch = 0; ch < NCH; ch++) {
        bool more = (ch + 1 < NCH);
        if (more) {
            int k1 = (ch + 1) * KC;
            const float* wrow = Wc + (size_t)(k1 + kkw) * HH;
            #pragma unroll
            for (int q = 0; q < 20; q++) {
                int h = hbw + 8 * q;
                wre[q] = (h < HH) ? wrow[h] : 0.f;
            }
            float gv = gi[k1 + kkp];
            #pragma unroll
            for (int rr = 0; rr < 4; rr++) {
                int t = tp + 8 * rr;
                pre[rr] = Gb[(size_t)(j0 + t) * E3 + k1 + kkp] * gv;
            }
        }
        const float* wsb = (ch & 1) ? ws1 : ws0;
        const float* psb = (ch & 1) ? ps1 : ps0;
        #pragma unroll
        for (int kk = 0; kk < KC; kk++) {
            float4 p = *(const float4*)&psb[kk * 36 + 4 * jg];
            const float* wr = &wsb[kk * HS + h0];
            float w0 = wr[0], w1 = wr[1], w2 = wr[2], w3 = wr[3], w4 = wr[4];
            acc[0][0] += p.x * w0; acc[0][1] += p.x * w1; acc[0][2] += p.x * w2;
            acc[0][3] += p.x * w3; acc[0][4] += p.x * w4;
            acc[1][0] += p.y * w0; acc[1][1] += p.y * w1; acc[1][2] += p.y * w2;
            acc[1][3] += p.y * w3; acc[1][4] += p.y * w4;
            acc[2][0] += p.z * w0; acc[2][1] += p.z * w1; acc[2][2] += p.z * w2;
            acc[2][3] += p.z * w3; acc[2][4] += p.z * w4;
            acc[3][0] += p.w * w0; acc[3][1] += p.w * w1; acc[3][2] += p.w * w2;
            acc[3][3] += p.w * w3; acc[3][4] += p.w * w4;
        }
        if (more) {
            float* wsn = (ch & 1) ? ws0 : ws1;
            float* psn = (ch & 1) ? ps0 : ps1;
            #pragma unroll
            for (int q = 0; q < 20; q++) wsn[kkw * HS + hbw + 8 * q] = wre[q];
            #pragma unroll
            for (int rr = 0; rr < 4; rr++) psn[kkp * 36 + tp + 8 * rr] = pre[rr];
        }
        __syncthreads();
    }

    // ---- forward epilogue: pairs (bi, j0+t) ----
    EpiArgs fa;
    fa.Abase = d_A + bi * HH;            fa.Astr = 0;
    fa.Bbase = d_Bt + (bS + j0) * HH;    fa.Bstr = HH;
    fa.msF   = d_ms + bi;                fa.msFstr = 0;
    fa.msS   = d_ms + bS + j0;           fa.msSstr = 1;
    fa.outBase = out + (size_t)bi * SS + j0;  fa.outStr = 1;
    run_epilogue(acc, fa, pb1, pw2, pb2, pw3, pb3, s1, ews, eps, jg, hg, tid);

    // ---- transpose epilogue: pairs (j0+t, bi) ----
    EpiArgs ta;
    ta.Abase = d_A + (bS + j0) * HH;     ta.Astr = HH;
    ta.Bbase = d_Bt + bi * HH;           ta.Bstr = 0;
    ta.msF   = d_ms + bS + j0;           ta.msFstr = 1;
    ta.msS   = d_ms + bi;                ta.msSstr = 0;
    ta.outBase = out + (size_t)(bS + j0) * SS + il;  ta.outStr = SS;
    run_epilogue(acc, ta, pb1, pw2, pb2, pw3, pb3, s1, ews, eps, jg, hg, tid);
}

// ---------------------------------------------------------------------------
extern "C" void kernel_launch(void* const* d_in, const int* in_sizes, int n_in,
                              void* d_out, int out_size)
{
    const float* X   = (const float*)d_in[0];
    const void*  sp  = d_in[1];
    const float* aw1 = (const float*)d_in[2];
    const float* ab1 = (const float*)d_in[3];
    const float* aw2 = (const float*)d_in[4];
    const float* ab2 = (const float*)d_in[5];
    const float* aw3 = (const float*)d_in[6];
    const float* ab3 = (const float*)d_in[7];
    const float* mw1 = (const float*)d_in[8];
    const float* mb1 = (const float*)d_in[9];
    const float* mw2 = (const float*)d_in[10];
    const float* mb2 = (const float*)d_in[11];
    const float* mw3 = (const float*)d_in[12];
    const float* mb3 = (const float*)d_in[13];
    const float* pw1 = (const float*)d_in[14];
    const float* pb1 = (const float*)d_in[15];
    const float* pw2 = (const float*)d_in[16];
    const float* pb2 = (const float*)d_in[17];
    const float* pw3 = (const float*)d_in[18];
    const float* pb3 = (const float*)d_in[19];
    float* out = (float*)d_out;

    const int smem_pair = (64 * HS + 2 * 32 * 36) * 4;   // 52224 B
    cudaFuncSetAttribute(k_pair, cudaFuncAttributeMaxDynamicSharedMemorySize,
                         smem_pair);

    k_init<<<1, 192>>>(sp);
    k_span<<<NSPAN, 320>>>(X, aw1, ab1, aw2, ab2, aw3, ab3);
    k_terms<<<288, 256>>>(pw1, mw1);
    k_reduce<<<(NSPAN * HH + 255) / 256, 256>>>();
    k_ment<<<NSPAN, 160>>>(mb1, mw2, mb2, mw3, mb3);
    k_pair<<<2 * 192, 256, smem_pair>>>(pw1, pb1, pw2, pb2, pw3, pb3, out);
}

// round 5
// speedup vs baseline: 2.9351x; 1.0705x over previous
#include <cuda_runtime.h>

#define BB 2
#define TT 2048
#define EE 768
#define SS 96
#define HH 150
#define HS 168          // padded smem row stride (floats) for weight tiles
#define WW 8
#define E3 2304
#define NSPAN (BB*SS)   // 192
#define KC 32           // k-chunk of pair C-term
#define KSPL 3          // K splits of the C-term
#define KLEN (E3/KSPL)  // 768
#define NCH2 (KLEN/KC)  // 24
#define NTILE 384       // triangular (i, j-chunk) tiles over both batches

// -------- device scratch --------
__device__ int   d_starts[NSPAN];
__device__ float d_g[NSPAN * E3];
__device__ float d_part[3 * 16 * NSPAN * HH];
__device__ float d_A[NSPAN * HH];
__device__ float d_Bt[NSPAN * HH];
__device__ float d_m1[NSPAN * HH];
__device__ float d_ms[NSPAN];
__device__ float d_Cp[NTILE * KSPL * 32 * 160];   // C-term partials (23.6 MB)

// ---------------------------------------------------------------------------
__global__ void k_init(const void* sp) {
    __shared__ int is64;
    if (threadIdx.x == 0) {
        const int* w32 = (const int*)sp;
        int z = 1;
        for (int i = 1; i < 64; i += 2) if (w32[i] != 0) { z = 0; break; }
        is64 = z;
    }
    __syncthreads();
    int i = threadIdx.x;
    if (i < NSPAN) {
        if (is64) d_starts[i] = (int)((const long long*)sp)[i];
        else      d_starts[i] = ((const int*)sp)[i];
    }
}

// ---------------------------------------------------------------------------
__global__ void __launch_bounds__(320) k_span(
    const float* __restrict__ X,
    const float* __restrict__ aw1, const float* __restrict__ ab1,
    const float* __restrict__ aw2, const float* __restrict__ ab2,
    const float* __restrict__ aw3, const float* __restrict__ ab3)
{
    int bi = blockIdx.x;
    int b = bi / SS;
    int st = d_starts[bi];
    int tid = threadIdx.x;

    __shared__ __align__(16) float xs[WW * EE];
    __shared__ float part[2][WW][152];
    __shared__ float s1[WW][152];
    __shared__ float s2[WW][152];
    __shared__ float at[WW];

    const float* Xb = X + ((size_t)b * TT + st) * EE;
    for (int i = tid; i < WW * EE; i += 320) xs[i] = Xb[i];
    __syncthreads();

    int half = tid / 160;
    int h = tid - half * 160;
    if (half < 2 && h < HH) {
        float acc[WW];
        #pragma unroll
        for (int w = 0; w < WW; w++) acc[w] = half ? 0.f : ab1[h];
        int kb = half * 384;
        for (int k = kb; k < kb + 384; k += 4) {
            float w0 = aw1[(k + 0) * HH + h];
            float w1 = aw1[(k + 1) * HH + h];
            float w2 = aw1[(k + 2) * HH + h];
            float w3 = aw1[(k + 3) * HH + h];
            #pragma unroll
            for (int w = 0; w < WW; w++) {
                float4 xv = *(const float4*)&xs[w * EE + k];
                acc[w] += xv.x * w0 + xv.y * w1 + xv.z * w2 + xv.w * w3;
            }
        }
        #pragma unroll
        for (int w = 0; w < WW; w++) part[half][w][h] = acc[w];
    }
    __syncthreads();

    if (tid < HH) {
        #pragma unroll
        for (int w = 0; w < WW; w++)
            s1[w][tid] = fmaxf(part[0][w][tid] + part[1][w][tid], 0.f);
    }
    __syncthreads();

    if (tid < HH) {
        float acc[WW];
        #pragma unroll
        for (int w = 0; w < WW; w++) acc[w] = ab2[tid];
        #pragma unroll 2
        for (int k = 0; k < HH; k++) {
            float wg = aw2[k * HH + tid];
            #pragma unroll
            for (int w = 0; w < WW; w++) acc[w] += s1[w][k] * wg;
        }
        #pragma unroll
        for (int w = 0; w < WW; w++) s2[w][tid] = fmaxf(acc[w], 0.f);
    }
    __syncthreads();
    if (tid < WW) {
        float a = ab3[0];
        for (int hh = 0; hh < HH; hh++) a += s2[tid][hh] * aw3[hh];
        at[tid] = a;
    }
    __syncthreads();

    float* gp = d_g + (size_t)bi * E3;
    for (int e = tid; e < EE; e += 320) {
        gp[e]          = xs[e];
        gp[EE + e]     = xs[7 * EE + e];
        float s = 0.f;
        #pragma unroll
        for (int w = 0; w < WW; w++) s += xs[w * EE + e] * at[w];
        gp[2 * EE + e] = s;
    }
}

// ---------------------------------------------------------------------------
__global__ void __launch_bounds__(256) k_terms(
    const float* __restrict__ pw1, const float* __restrict__ mw1)
{
    int x = blockIdx.x;
    int sc  = x % 6;
    int mat = (x / 6) % 3;
    int ks  = x / 18;
    const float* Wm = (mat == 0) ? pw1 : (mat == 1 ? pw1 + (size_t)E3 * HH : mw1);
    int s0 = sc * 32;
    int kbase = ks * 144;
    int tid = threadIdx.x;
    int jg = tid >> 5;
    int hg = tid & 31;
    int h0 = 5 * hg;
    int kk2 = tid >> 4;
    int hb2 = tid & 15;

    __shared__ __align__(16) float wst[16 * HS];
    __shared__ __align__(16) float pst[16 * 36];

    float acc[4][5];
    #pragma unroll
    for (int jj = 0; jj < 4; jj++)
        #pragma unroll
        for (int q = 0; q < 5; q++) acc[jj][q] = 0.f;

    for (int kc = 0; kc < 144; kc += 16) {
        int k0 = kbase + kc;
        __syncthreads();
        #pragma unroll
        for (int q = 0; q < 10; q++) {
            int h = hb2 + 16 * q;
            if (h < 160)
                wst[kk2 * HS + h] = (h < HH) ? Wm[(size_t)(k0 + kk2) * HH + h] : 0.f;
        }
        #pragma unroll
        for (int r = 0; r < 2; r++) {
            int idx = tid + 256 * r;
            int t = idx >> 4, kk = idx & 15;
            pst[kk * 36 + t] = d_g[(size_t)(s0 + t) * E3 + k0 + kk];
        }
        __syncthreads();
        #pragma unroll
        for (int kk = 0; kk < 16; kk++) {
            float4 p = *(const float4*)&pst[kk * 36 + 4 * jg];
            const float* wr = &wst[kk * HS + h0];
            float w0 = wr[0], w1 = wr[1], w2 = wr[2], w3 = wr[3], w4 = wr[4];
            acc[0][0] += p.x * w0; acc[0][1] += p.x * w1; acc[0][2] += p.x * w2;
            acc[0][3] += p.x * w3; acc[0][4] += p.x * w4;
            acc[1][0] += p.y * w0; acc[1][1] += p.y * w1; acc[1][2] += p.y * w2;
            acc[1][3] += p.y * w3; acc[1][4] += p.y * w4;
            acc[2][0] += p.z * w0; acc[2][1] += p.z * w1; acc[2][2] += p.z * w2;
            acc[2][3] += p.z * w3; acc[2][4] += p.z * w4;
            acc[3][0] += p.w * w0; acc[3][1] += p.w * w1; acc[3][2] += p.w * w2;
            acc[3][3] += p.w * w3; acc[3][4] += p.w * w4;
        }
    }
    #pragma unroll
    for (int jj = 0; jj < 4; jj++) {
        int t = 4 * jg + jj;
        float* op = d_part + (((size_t)mat * 16 + ks) * NSPAN + s0 + t) * HH;
        #pragma unroll
        for (int q = 0; q < 5; q++) {
            int h = h0 + q;
            if (h < HH) op[h] = acc[jj][q];
        }
    }
}

// ---------------------------------------------------------------------------
__global__ void k_reduce() {
    int i = blockIdx.x * blockDim.x + threadIdx.x;
    if (i >= NSPAN * HH) return;
    #pragma unroll
    for (int mat = 0; mat < 3; mat++) {
        float s = 0.f;
        #pragma unroll
        for (int ks = 0; ks < 16; ks++)
            s += d_part[((size_t)mat * 16 + ks) * (NSPAN * HH) + i];
        if (mat == 0)      d_A[i]  = s;
        else if (mat == 1) d_Bt[i] = s;
        else               d_m1[i] = s;
    }
}

// ---------------------------------------------------------------------------
__global__ void __launch_bounds__(160) k_ment(
    const float* __restrict__ mb1, const float* __restrict__ mw2,
    const float* __restrict__ mb2, const float* __restrict__ mw3,
    const float* __restrict__ mb3)
{
    int s = blockIdx.x;
    int tid = threadIdx.x;
    __shared__ float s1[HH];
    __shared__ float warpsum[8];

    if (tid < HH) s1[tid] = fmaxf(d_m1[s * HH + tid] + mb1[tid], 0.f);
    __syncthreads();
    float p = 0.f;
    if (tid < HH) {
        float v = mb2[tid];
        for (int k = 0; k < HH; k++) v += s1[k] * mw2[k * HH + tid];
        p = fmaxf(v, 0.f) * mw3[tid];
    }
    #pragma unroll
    for (int o = 16; o > 0; o >>= 1) p += __shfl_down_sync(0xffffffffu, p, o);
    if ((tid & 31) == 0) warpsum[tid >> 5] = p;
    __syncthreads();
    if (tid == 0) {
        float t = mb3[0];
        for (int w = 0; w < 5; w++) t += warpsum[w];
        d_ms[s] = t;
    }
}

// ---------------------------------------------------------------------------
// tile decode shared by k_pairC / k_pairE
// ---------------------------------------------------------------------------
__device__ __forceinline__ void decode_tile(int tile, int& b, int& il, int& c) {
    b = tile / 192;
    int r = tile % 192;
    if (r < 96)       { il = r & 31;              c = r >> 5; }
    else if (r < 160) { int rr = r - 96;  il = 32 + (rr & 31); c = 1 + (rr >> 5); }
    else              { il = 64 + (r - 160);      c = 2; }
}

// ---------------------------------------------------------------------------
// k_pairC: C-term only. grid = NTILE * KSPL = 1152 short blocks, occ 3.
// Each handles one (tile, K-slice of 768) with double-buffered KC=32 staging.
// ---------------------------------------------------------------------------
__global__ void __launch_bounds__(256, 3) k_pairC(const float* __restrict__ pw1)
{
    extern __shared__ __align__(16) float sm[];
    float* ws0 = sm;
    float* ws1 = sm + 32 * HS;
    float* ps0 = sm + 64 * HS;
    float* ps1 = ps0 + 32 * 36;

    int x = blockIdx.x;
    int tile = x / KSPL;
    int split = x - tile * KSPL;
    int b, il, c;
    decode_tile(tile, b, il, c);
    int bi = b * SS + il;
    int j0 = c * 32;
    int bS = b * SS;
    int tid = threadIdx.x;
    int jg = tid >> 5;
    int hg = tid & 31;
    int h0 = 5 * hg;
    int kkw = tid >> 3;
    int hbw = tid & 7;
    int kkp = tid & 31;
    int tp  = tid >> 5;

    int kbase = split * KLEN;
    const float* Wc = pw1 + (size_t)2 * E3 * HH;
    const float* gi = d_g + (size_t)bi * E3;
    const float* Gb = d_g + (size_t)bS * E3;

    float acc[4][5];
    #pragma unroll
    for (int jj = 0; jj < 4; jj++)
        #pragma unroll
        for (int q = 0; q < 5; q++) acc[jj][q] = 0.f;

    float wre[20], pre[4];

    // prefetch chunk 0
    {
        const float* wrow = Wc + (size_t)(kbase + kkw) * HH;
        #pragma unroll
        for (int q = 0; q < 20; q++) {
            int h = hbw + 8 * q;
            wre[q] = (h < HH) ? wrow[h] : 0.f;
        }
        float gv = gi[kbase + kkp];
        #pragma unroll
        for (int rr = 0; rr < 4; rr++) {
            int t = tp + 8 * rr;
            pre[rr] = Gb[(size_t)(j0 + t) * E3 + kbase + kkp] * gv;
        }
        #pragma unroll
        for (int q = 0; q < 20; q++) ws0[kkw * HS + hbw + 8 * q] = wre[q];
        #pragma unroll
        for (int rr = 0; rr < 4; rr++) ps0[kkp * 36 + tp + 8 * rr] = pre[rr];
    }
    __syncthreads();

    for (int ch = 0; ch < NCH2; ch++) {
        bool more = (ch + 1 < NCH2);
        if (more) {
            int k1 = kbase + (ch + 1) * KC;
            const float* wrow = Wc + (size_t)(k1 + kkw) * HH;
            #pragma unroll
            for (int q = 0; q < 20; q++) {
                int h = hbw + 8 * q;
                wre[q] = (h < HH) ? wrow[h] : 0.f;
            }
            float gv = gi[k1 + kkp];
            #pragma unroll
            for (int rr = 0; rr < 4; rr++) {
                int t = tp + 8 * rr;
                pre[rr] = Gb[(size_t)(j0 + t) * E3 + k1 + kkp] * gv;
            }
        }
        const float* wsb = (ch & 1) ? ws1 : ws0;
        const float* psb = (ch & 1) ? ps1 : ps0;
        #pragma unroll
        for (int kk = 0; kk < KC; kk++) {
            float4 p = *(const float4*)&psb[kk * 36 + 4 * jg];
            const float* wr = &wsb[kk * HS + h0];
            float w0 = wr[0], w1 = wr[1], w2 = wr[2], w3 = wr[3], w4 = wr[4];
            acc[0][0] += p.x * w0; acc[0][1] += p.x * w1; acc[0][2] += p.x * w2;
            acc[0][3] += p.x * w3; acc[0][4] += p.x * w4;
            acc[1][0] += p.y * w0; acc[1][1] += p.y * w1; acc[1][2] += p.y * w2;
            acc[1][3] += p.y * w3; acc[1][4] += p.y * w4;
            acc[2][0] += p.z * w0; acc[2][1] += p.z * w1; acc[2][2] += p.z * w2;
            acc[2][3] += p.z * w3; acc[2][4] += p.z * w4;
            acc[3][0] += p.w * w0; acc[3][1] += p.w * w1; acc[3][2] += p.w * w2;
            acc[3][3] += p.w * w3; acc[3][4] += p.w * w4;
        }
        if (more) {
            float* wsn = (ch & 1) ? ws0 : ws1;
            float* psn = (ch & 1) ? ps0 : ps1;
            #pragma unroll
            for (int q = 0; q < 20; q++) wsn[kkw * HS + hbw + 8 * q] = wre[q];
            #pragma unroll
            for (int rr = 0; rr < 4; rr++) psn[kkp * 36 + tp + 8 * rr] = pre[rr];
        }
        __syncthreads();
    }

    float* op = d_Cp + ((size_t)tile * KSPL + split) * 32 * 160;
    #pragma unroll
    for (int jj = 0; jj < 4; jj++) {
        #pragma unroll
        for (int q = 0; q < 5; q++)
            op[(4 * jg + jj) * 160 + h0 + q] = acc[jj][q];
    }
}

// ---------------------------------------------------------------------------
// k_pairE: reduce K-split partials + dual fused epilogues. grid = NTILE.
// ---------------------------------------------------------------------------
struct EpiArgs {
    const float* Abase; int Astr;
    const float* Bbase; int Bstr;
    const float* msF;   int msFstr;
    const float* msS;   int msSstr;
    float* outBase;     int outStr;
};

__device__ __forceinline__ void run_epilogue(
    const float acc[4][5], const EpiArgs& ea,
    const float* __restrict__ pb1, const float* __restrict__ pw2,
    const float* __restrict__ pb2, const float* __restrict__ pw3,
    const float* __restrict__ pb3,
    float* s1, float* ews, float* eps,
    int jg, int hg, int tid)
{
    int h0 = 5 * hg;
    int kk2 = tid >> 4;
    int hb2 = tid & 15;
    __syncthreads();
    #pragma unroll
    for (int q = 0; q < 5; q++) {
        int h = h0 + q;
        #pragma unroll
        for (int jj = 0; jj < 4; jj++) {
            int t = 4 * jg + jj;
            float v = 0.f;
            if (h < HH) {
                float cc = acc[jj][q] + pb1[h];
                cc = cc + ea.Abase[t * ea.Astr + h];
                cc = cc + ea.Bbase[t * ea.Bstr + h];
                v = fmaxf(cc, 0.f);
            }
            s1[t * HS + h] = v;
        }
    }
    float acc2[4][5];
    #pragma unroll
    for (int jj = 0; jj < 4; jj++)
        #pragma unroll
        for (int q = 0; q < 5; q++) {
            int h = h0 + q;
            acc2[jj][q] = (h < HH) ? pb2[h] : 0.f;
        }
    for (int k0 = 0; k0 < 160; k0 += 16) {
        __syncthreads();
        #pragma unroll
        for (int q = 0; q < 10; q++) {
            int h = hb2 + 16 * q;
            if (h < 160) {
                float v = 0.f;
                if ((k0 + kk2) < HH && h < HH) v = pw2[(k0 + kk2) * HH + h];
                ews[kk2 * HS + h] = v;
            }
        }
        #pragma unroll
        for (int r = 0; r < 2; r++) {
            int idx = tid + 256 * r;
            int t = idx >> 4, kk = idx & 15;
            eps[kk * 36 + t] = s1[t * HS + k0 + kk];
        }
        __syncthreads();
        #pragma unroll
        for (int kk = 0; kk < 16; kk++) {
            float4 p = *(const float4*)&eps[kk * 36 + 4 * jg];
            const float* wr = &ews[kk * HS + h0];
            float w0 = wr[0], w1 = wr[1], w2 = wr[2], w3 = wr[3], w4 = wr[4];
            acc2[0][0] += p.x * w0; acc2[0][1] += p.x * w1; acc2[0][2] += p.x * w2;
            acc2[0][3] += p.x * w3; acc2[0][4] += p.x * w4;
            acc2[1][0] += p.y * w0; acc2[1][1] += p.y * w1; acc2[1][2] += p.y * w2;
            acc2[1][3] += p.y * w3; acc2[1][4] += p.y * w4;
            acc2[2][0] += p.z * w0; acc2[2][1] += p.z * w1; acc2[2][2] += p.z * w2;
            acc2[2][3] += p.z * w3; acc2[2][4] += p.z * w4;
            acc2[3][0] += p.w * w0; acc2[3][1] += p.w * w1; acc2[3][2] += p.w * w2;
            acc2[3][3] += p.w * w3; acc2[3][4] += p.w * w4;
        }
    }
    float part[4];
    #pragma unroll
    for (int jj = 0; jj < 4; jj++) {
        float s = 0.f;
        #pragma unroll
        for (int q = 0; q < 5; q++) {
            int h = h0 + q;
            if (h < HH) s += fmaxf(acc2[jj][q], 0.f) * pw3[h];
        }
        part[jj] = s;
    }
    #pragma unroll
    for (int jj = 0; jj < 4; jj++)
        #pragma unroll
        for (int off = 16; off > 0; off >>= 1)
            part[jj] += __shfl_xor_sync(0xffffffffu, part[jj], off);
    if (hg == 0) {
        #pragma unroll
        for (int jj = 0; jj < 4; jj++) {
            int t = 4 * jg + jj;
            float sc = part[jj] + pb3[0];
            float v = ((ea.msF[t * ea.msFstr] + ea.msS[t * ea.msSstr]) + sc) * (1.f / 3.f);
            v = fminf(fmaxf(v, 0.f), 1.f);
            ea.outBase[(size_t)t * ea.outStr] = v;
        }
    }
}

__global__ void __launch_bounds__(256) k_pairE(
    const float* __restrict__ pb1, const float* __restrict__ pw2,
    const float* __restrict__ pb2, const float* __restrict__ pw3,
    const float* __restrict__ pb3, float* __restrict__ out)
{
    __shared__ __align__(16) float s1[32 * HS];
    __shared__ __align__(16) float ews[16 * HS];
    __shared__ __align__(16) float eps[16 * 36];

    int tile = blockIdx.x;
    int b, il, c;
    decode_tile(tile, b, il, c);
    int bi = b * SS + il;
    int j0 = c * 32;
    int bS = b * SS;
    int tid = threadIdx.x;
    int jg = tid >> 5;
    int hg = tid & 31;
    int h0 = 5 * hg;

    // reduce K-split partials (deterministic order)
    float acc[4][5];
    const float* cp = d_Cp + (size_t)tile * KSPL * 32 * 160;
    #pragma unroll
    for (int jj = 0; jj < 4; jj++) {
        int t = 4 * jg + jj;
        #pragma unroll
        for (int q = 0; q < 5; q++) {
            int idx = t * 160 + h0 + q;
            float s = cp[idx];
            s += cp[32 * 160 + idx];
            s += cp[2 * 32 * 160 + idx];
            acc[jj][q] = s;
        }
    }

    EpiArgs fa;
    fa.Abase = d_A + bi * HH;            fa.Astr = 0;
    fa.Bbase = d_Bt + (bS + j0) * HH;    fa.Bstr = HH;
    fa.msF   = d_ms + bi;                fa.msFstr = 0;
    fa.msS   = d_ms + bS + j0;           fa.msSstr = 1;
    fa.outBase = out + (size_t)bi * SS + j0;  fa.outStr = 1;
    run_epilogue(acc, fa, pb1, pw2, pb2, pw3, pb3, s1, ews, eps, jg, hg, tid);

    EpiArgs ta;
    ta.Abase = d_A + (bS + j0) * HH;     ta.Astr = HH;
    ta.Bbase = d_Bt + bi * HH;           ta.Bstr = 0;
    ta.msF   = d_ms + bS + j0;           ta.msFstr = 1;
    ta.msS   = d_ms + bi;                ta.msSstr = 0;
    ta.outBase = out + (size_t)(bS + j0) * SS + il;  ta.outStr = SS;
    run_epilogue(acc, ta, pb1, pw2, pb2, pw3, pb3, s1, ews, eps, jg, hg, tid);
}

// ---------------------------------------------------------------------------
extern "C" void kernel_launch(void* const* d_in, const int* in_sizes, int n_in,
                              void* d_out, int out_size)
{
    const float* X   = (const float*)d_in[0];
    const void*  sp  = d_in[1];
    const float* aw1 = (const float*)d_in[2];
    const float* ab1 = (const float*)d_in[3];
    const float* aw2 = (const float*)d_in[4];
    const float* ab2 = (const float*)d_in[5];
    const float* aw3 = (const float*)d_in[6];
    const float* ab3 = (const float*)d_in[7];
    const float* mw1 = (const float*)d_in[8];
    const float* mb1 = (const float*)d_in[9];
    const float* mw2 = (const float*)d_in[10];
    const float* mb2 = (const float*)d_in[11];
    const float* mw3 = (const float*)d_in[12];
    const float* mb3 = (const float*)d_in[13];
    const float* pw1 = (const float*)d_in[14];
    const float* pb1 = (const float*)d_in[15];
    const float* pw2 = (const float*)d_in[16];
    const float* pb2 = (const float*)d_in[17];
    const float* pw3 = (const float*)d_in[18];
    const float* pb3 = (const float*)d_in[19];
    float* out = (float*)d_out;

    const int smem_pairC = (64 * HS + 2 * 32 * 36) * 4;   // 52224 B
    cudaFuncSetAttribute(k_pairC, cudaFuncAttributeMaxDynamicSharedMemorySize,
                         smem_pairC);

    k_init<<<1, 192>>>(sp);
    k_span<<<NSPAN, 320>>>(X, aw1, ab1, aw2, ab2, aw3, ab3);
    k_terms<<<288, 256>>>(pw1, mw1);
    k_reduce<<<(NSPAN * HH + 255) / 256, 256>>>();
    k_ment<<<NSPAN, 160>>>(mb1, mw2, mb2, mw3, mb3);
    k_pairC<<<NTILE * KSPL, 256, smem_pairC>>>(pw1);
    k_pairE<<<NTILE, 256>>>(pb1, pw2, pb2, pw3, pb3, out);
}

// round 7
// speedup vs baseline: 3.3379x; 1.1372x over previous
#include <cuda_runtime.h>
#include <cuda_bf16.h>
#include <cstdint>

#define BB 2
#define TT 2048
#define EE 768
#define SS 96
#define HH 150
#define HS 168
#define WW 8
#define E3 2304
#define NSPAN (BB*SS)      // 192
#define NPAIR 9312
#define NPAIRP 9344        // 73*128
#define KPR 6912           // 3*E3 interleaved split K
#define NCHA 72            // chunks of 96 k' (= 32 original k)
#define ABUF 26624         // 128 rows * 208 B
#define WBUF 33280         // 160 rows * 208 B
#define SMEMG (2*ABUF + 2*WBUF)   // 119808

// -------- device scratch --------
__device__ int   d_starts[NSPAN];
__device__ __align__(16) float d_g[NSPAN * E3];
__device__ float d_part[3 * 16 * NSPAN * HH];
__device__ float d_A[NSPAN * HH];
__device__ float d_Bt[NSPAN * HH];
__device__ float d_m1[NSPAN * HH];
__device__ float d_ms[NSPAN];
__device__ int   d_pi[NPAIRP], d_pj[NPAIRP];
__device__ __align__(16) __nv_bfloat16 d_Wi[160 * KPR];   // interleaved split W
__device__ float d_Cg[(size_t)NPAIRP * 160];

// -------- generic-PTX helpers --------
__device__ __forceinline__ uint32_t smem_u32(const void* p) {
    uint32_t a;
    asm("{ .reg .u64 t; cvta.to.shared.u64 t, %1; cvt.u32.u64 %0, t; }"
        : "=r"(a) : "l"(p));
    return a;
}
#define CP_ASYNC16(dst, src) \
    asm volatile("cp.async.cg.shared.global [%0], [%1], 16;" \
                 :: "r"(dst), "l"(src) : "memory")
#define CP_COMMIT() asm volatile("cp.async.commit_group;" ::: "memory")
#define CP_WAIT0()  asm volatile("cp.async.wait_group 0;" ::: "memory")

__device__ __forceinline__ void mma16816(float c[4], uint32_t a0, uint32_t a1,
                                         uint32_t a2, uint32_t a3,
                                         uint32_t b0, uint32_t b1) {
    asm volatile(
        "mma.sync.aligned.m16n8k16.row.col.f32.bf16.bf16.f32 "
        "{%0,%1,%2,%3}, {%4,%5,%6,%7}, {%8,%9}, {%0,%1,%2,%3};"
        : "+f"(c[0]), "+f"(c[1]), "+f"(c[2]), "+f"(c[3])
        : "r"(a0), "r"(a1), "r"(a2), "r"(a3), "r"(b0), "r"(b1));
}

// ---------------------------------------------------------------------------
__global__ void k_init(const void* sp) {
    __shared__ int is64;
    if (threadIdx.x == 0) {
        const int* w32 = (const int*)sp;
        int z = 1;
        for (int i = 1; i < 64; i += 2) if (w32[i] != 0) { z = 0; break; }
        is64 = z;
    }
    __syncthreads();
    int i = threadIdx.x;
    if (i < NSPAN) {
        if (is64) d_starts[i] = (int)((const long long*)sp)[i];
        else      d_starts[i] = ((const int*)sp)[i];
    }
}

// ---------------------------------------------------------------------------
__global__ void k_plist() {
    int idx = blockIdx.x * blockDim.x + threadIdx.x;
    if (idx < 2 * SS * SS) {
        int b = idx / (SS * SS), r = idx % (SS * SS);
        int i = r / SS, j = r % SS;
        if (j >= i) {
            int row = b * 4656 + i * SS - i * (i - 1) / 2 + (j - i);
            d_pi[row] = b * SS + i;
            d_pj[row] = b * SS + j;
        }
    }
    if (idx < NPAIRP - NPAIR) {
        d_pi[NPAIR + idx] = NSPAN - 1;
        d_pj[NPAIR + idx] = NSPAN - 1;
    }
}

// ---------------------------------------------------------------------------
// k_wprep: interleaved split of WcT:  S[n][3k+0]=hi, [3k+1]=lo, [3k+2]=hi
// ---------------------------------------------------------------------------
__global__ void k_wprep(const float* __restrict__ pw1) {
    int idx = blockIdx.x * blockDim.x + threadIdx.x;
    if (idx >= 160 * KPR) return;
    int n = idx / KPR, kp = idx % KPR;
    int k = kp / 3, r = kp - 3 * k;
    float w = (n < HH) ? pw1[(size_t)2 * E3 * HH + (size_t)k * HH + n] : 0.f;
    unsigned short hu;
    asm("cvt.rn.bf16.f32 %0, %1;" : "=h"(hu) : "f"(w));
    if (r == 1) {
        float hf = __uint_as_float(((uint32_t)hu) << 16);
        float l = w - hf;
        asm("cvt.rn.bf16.f32 %0, %1;" : "=h"(hu) : "f"(l));
    }
    ((unsigned short*)d_Wi)[idx] = hu;
}

// ---------------------------------------------------------------------------
__global__ void __launch_bounds__(320) k_span(
    const float* __restrict__ X,
    const float* __restrict__ aw1, const float* __restrict__ ab1,
    const float* __restrict__ aw2, const float* __restrict__ ab2,
    const float* __restrict__ aw3, const float* __restrict__ ab3)
{
    int bi = blockIdx.x;
    int b = bi / SS;
    int st = d_starts[bi];
    int tid = threadIdx.x;

    __shared__ __align__(16) float xs[WW * EE];
    __shared__ float part[2][WW][152];
    __shared__ float s1[WW][152];
    __shared__ float s2[WW][152];
    __shared__ float at[WW];

    const float* Xb = X + ((size_t)b * TT + st) * EE;
    for (int i = tid; i < WW * EE; i += 320) xs[i] = Xb[i];
    __syncthreads();

    int half = tid / 160;
    int h = tid - half * 160;
    if (half < 2 && h < HH) {
        float acc[WW];
        #pragma unroll
        for (int w = 0; w < WW; w++) acc[w] = half ? 0.f : ab1[h];
        int kb = half * 384;
        for (int k = kb; k < kb + 384; k += 4) {
            float w0 = aw1[(k + 0) * HH + h];
            float w1 = aw1[(k + 1) * HH + h];
            float w2 = aw1[(k + 2) * HH + h];
            float w3 = aw1[(k + 3) * HH + h];
            #pragma unroll
            for (int w = 0; w < WW; w++) {
                float4 xv = *(const float4*)&xs[w * EE + k];
                acc[w] += xv.x * w0 + xv.y * w1 + xv.z * w2 + xv.w * w3;
            }
        }
        #pragma unroll
        for (int w = 0; w < WW; w++) part[half][w][h] = acc[w];
    }
    __syncthreads();

    if (tid < HH) {
        #pragma unroll
        for (int w = 0; w < WW; w++)
            s1[w][tid] = fmaxf(part[0][w][tid] + part[1][w][tid], 0.f);
    }
    __syncthreads();

    if (tid < HH) {
        float acc[WW];
        #pragma unroll
        for (int w = 0; w < WW; w++) acc[w] = ab2[tid];
        #pragma unroll 2
        for (int k = 0; k < HH; k++) {
            float wg = aw2[k * HH + tid];
            #pragma unroll
            for (int w = 0; w < WW; w++) acc[w] += s1[w][k] * wg;
        }
        #pragma unroll
        for (int w = 0; w < WW; w++) s2[w][tid] = fmaxf(acc[w], 0.f);
    }
    __syncthreads();
    if (tid < WW) {
        float a = ab3[0];
        for (int hh = 0; hh < HH; hh++) a += s2[tid][hh] * aw3[hh];
        at[tid] = a;
    }
    __syncthreads();

    float* gp = d_g + (size_t)bi * E3;
    for (int e = tid; e < EE; e += 320) {
        gp[e]          = xs[e];
        gp[EE + e]     = xs[7 * EE + e];
        float s = 0.f;
        #pragma unroll
        for (int w = 0; w < WW; w++) s += xs[w * EE + e] * at[w];
        gp[2 * EE + e] = s;
    }
}

// ---------------------------------------------------------------------------
__global__ void __launch_bounds__(256) k_terms(
    const float* __restrict__ pw1, const float* __restrict__ mw1)
{
    int x = blockIdx.x;
    int sc  = x % 6;
    int mat = (x / 6) % 3;
    int ks  = x / 18;
    const float* Wm = (mat == 0) ? pw1 : (mat == 1 ? pw1 + (size_t)E3 * HH : mw1);
    int s0 = sc * 32;
    int kbase = ks * 144;
    int tid = threadIdx.x;
    int jg = tid >> 5;
    int hg = tid & 31;
    int h0 = 5 * hg;
    int kk2 = tid >> 4;
    int hb2 = tid & 15;

    __shared__ __align__(16) float wst[16 * HS];
    __shared__ __align__(16) float pst[16 * 36];

    float acc[4][5];
    #pragma unroll
    for (int jj = 0; jj < 4; jj++)
        #pragma unroll
        for (int q = 0; q < 5; q++) acc[jj][q] = 0.f;

    for (int kc = 0; kc < 144; kc += 16) {
        int k0 = kbase + kc;
        __syncthreads();
        #pragma unroll
        for (int q = 0; q < 10; q++) {
            int h = hb2 + 16 * q;
            if (h < 160)
                wst[kk2 * HS + h] = (h < HH) ? Wm[(size_t)(k0 + kk2) * HH + h] : 0.f;
        }
        #pragma unroll
        for (int r = 0; r < 2; r++) {
            int idx = tid + 256 * r;
            int t = idx >> 4, kk = idx & 15;
            pst[kk * 36 + t] = d_g[(size_t)(s0 + t) * E3 + k0 + kk];
        }
        __syncthreads();
        #pragma unroll
        for (int kk = 0; kk < 16; kk++) {
            float4 p = *(const float4*)&pst[kk * 36 + 4 * jg];
            const float* wr = &wst[kk * HS + h0];
            float w0 = wr[0], w1 = wr[1], w2 = wr[2], w3 = wr[3], w4 = wr[4];
            acc[0][0] += p.x * w0; acc[0][1] += p.x * w1; acc[0][2] += p.x * w2;
            acc[0][3] += p.x * w3; acc[0][4] += p.x * w4;
            acc[1][0] += p.y * w0; acc[1][1] += p.y * w1; acc[1][2] += p.y * w2;
            acc[1][3] += p.y * w3; acc[1][4] += p.y * w4;
            acc[2][0] += p.z * w0; acc[2][1] += p.z * w1; acc[2][2] += p.z * w2;
            acc[2][3] += p.z * w3; acc[2][4] += p.z * w4;
            acc[3][0] += p.w * w0; acc[3][1] += p.w * w1; acc[3][2] += p.w * w2;
            acc[3][3] += p.w * w3; acc[3][4] += p.w * w4;
        }
    }
    #pragma unroll
    for (int jj = 0; jj < 4; jj++) {
        int t = 4 * jg + jj;
        float* op = d_part + (((size_t)mat * 16 + ks) * NSPAN + s0 + t) * HH;
        #pragma unroll
        for (int q = 0; q < 5; q++) {
            int h = h0 + q;
            if (h < HH) op[h] = acc[jj][q];
        }
    }
}

// ---------------------------------------------------------------------------
__global__ void k_reduce() {
    int i = blockIdx.x * blockDim.x + threadIdx.x;
    if (i >= NSPAN * HH) return;
    #pragma unroll
    for (int mat = 0; mat < 3; mat++) {
        float s = 0.f;
        #pragma unroll
        for (int ks = 0; ks < 16; ks++)
            s += d_part[((size_t)mat * 16 + ks) * (NSPAN * HH) + i];
        if (mat == 0)      d_A[i]  = s;
        else if (mat == 1) d_Bt[i] = s;
        else               d_m1[i] = s;
    }
}

// ---------------------------------------------------------------------------
__global__ void __launch_bounds__(160) k_ment(
    const float* __restrict__ mb1, const float* __restrict__ mw2,
    const float* __restrict__ mb2, const float* __restrict__ mw3,
    const float* __restrict__ mb3)
{
    int s = blockIdx.x;
    int tid = threadIdx.x;
    __shared__ float s1[HH];
    __shared__ float warpsum[8];

    if (tid < HH) s1[tid] = fmaxf(d_m1[s * HH + tid] + mb1[tid], 0.f);
    __syncthreads();
    float p = 0.f;
    if (tid < HH) {
        float v = mb2[tid];
        for (int k = 0; k < HH; k++) v += s1[k] * mw2[k * HH + tid];
        p = fmaxf(v, 0.f) * mw3[tid];
    }
    #pragma unroll
    for (int o = 16; o > 0; o >>= 1) p += __shfl_down_sync(0xffffffffu, p, o);
    if ((tid & 31) == 0) warpsum[tid >> 5] = p;
    __syncthreads();
    if (tid == 0) {
        float t = mb3[0];
        for (int w = 0; w < 5; w++) t += warpsum[w];
        d_ms[s] = t;
    }
}

// ---------------------------------------------------------------------------
// k_gemm helpers
// ---------------------------------------------------------------------------
__device__ __forceinline__ void lda_regs(const float* gi, const float* gj,
                                         int ch, float* gir, float* gjr) {
    const float4* a4 = (const float4*)(gi + ch * 32);
    const float4* b4 = (const float4*)(gj + ch * 32);
    #pragma unroll
    for (int u = 0; u < 4; u++) {
        float4 a = a4[u], b = b4[u];
        gir[4*u+0] = a.x; gir[4*u+1] = a.y; gir[4*u+2] = a.z; gir[4*u+3] = a.w;
        gjr[4*u+0] = b.x; gjr[4*u+1] = b.y; gjr[4*u+2] = b.z; gjr[4*u+3] = b.w;
    }
}

__device__ __forceinline__ void sta_smem(char* dst, int aoff,
                                         const float* gir, const float* gjr) {
    unsigned short us[48];
    #pragma unroll
    for (int k = 0; k < 16; k++) {
        float p = gir[k] * gjr[k];
        unsigned short hu;
        asm("cvt.rn.bf16.f32 %0, %1;" : "=h"(hu) : "f"(p));
        float hf = __uint_as_float(((uint32_t)hu) << 16);
        float l = p - hf;
        unsigned short lu;
        asm("cvt.rn.bf16.f32 %0, %1;" : "=h"(lu) : "f"(l));
        us[3*k+0] = hu; us[3*k+1] = hu; us[3*k+2] = lu;
    }
    uint32_t u[24];
    #pragma unroll
    for (int j = 0; j < 24; j++)
        u[j] = (uint32_t)us[2*j] | ((uint32_t)us[2*j+1] << 16);
    uint4* d = (uint4*)(dst + aoff);
    d[0] = make_uint4(u[0],  u[1],  u[2],  u[3]);
    d[1] = make_uint4(u[4],  u[5],  u[6],  u[7]);
    d[2] = make_uint4(u[8],  u[9],  u[10], u[11]);
    d[3] = make_uint4(u[12], u[13], u[14], u[15]);
    d[4] = make_uint4(u[16], u[17], u[18], u[19]);
    d[5] = make_uint4(u[20], u[21], u[22], u[23]);
}

__device__ __forceinline__ void cpw_chunk(uint32_t wdst, int ch, int tid) {
    #pragma unroll
    for (int v = 0; v < 2; v++) {
        int unit = tid + 256 * v;
        if (unit < 320) {
            int n = unit >> 1, kh = unit & 1;
            const char* src = (const char*)d_Wi + (size_t)n * (KPR * 2)
                              + ch * 192 + kh * 96;
            uint32_t dst = wdst + n * 208 + kh * 96;
            #pragma unroll
            for (int q = 0; q < 6; q++)
                CP_ASYNC16(dst + q * 16, src + q * 16);
        }
    }
}

// ---------------------------------------------------------------------------
// k_gemm: C[NPAIRP,160] = A'(pair products, split-interleaved) @ W' via
// mma.sync m16n8k16 bf16. 73 blocks, 8 warps x m16, N=160 (20 n8-tiles).
// ---------------------------------------------------------------------------
__global__ void __launch_bounds__(256) k_gemm()
{
    extern __shared__ __align__(16) char smg[];
    char* Ab[2] = { smg, smg + ABUF };
    char* Wb[2] = { smg + 2 * ABUF, smg + 2 * ABUF + WBUF };
    uint32_t Wbu[2] = { smem_u32(Wb[0]), smem_u32(Wb[1]) };

    int tid = threadIdx.x, wid = tid >> 5, lane = tid & 31;
    int g = lane >> 2, tg = lane & 3;
    int m0 = blockIdx.x * 128;

    int arow = tid >> 1, akh = tid & 1;
    const float* gi = d_g + (size_t)d_pi[m0 + arow] * E3 + akh * 16;
    const float* gj = d_g + (size_t)d_pj[m0 + arow] * E3 + akh * 16;
    int aoff = arow * 208 + akh * 96;

    float c[20][4];
    #pragma unroll
    for (int t = 0; t < 20; t++)
        #pragma unroll
        for (int q = 0; q < 4; q++) c[t][q] = 0.f;

    float gir[16], gjr[16];

    // ---- prologue: chunk 0 ----
    cpw_chunk(Wbu[0], 0, tid);
    CP_COMMIT();
    lda_regs(gi, gj, 0, gir, gjr);
    sta_smem(Ab[0], aoff, gir, gjr);
    CP_WAIT0();
    __syncthreads();

    for (int ch = 0; ch < NCHA; ch++) {
        int buf = ch & 1, nb = buf ^ 1;
        bool more = (ch + 1 < NCHA);
        if (more) {
            cpw_chunk(Wbu[nb], ch + 1, tid);
            CP_COMMIT();
            lda_regs(gi, gj, ch + 1, gir, gjr);
        }
        const char* A = Ab[buf];
        const char* W = Wb[buf];
        #pragma unroll
        for (int s = 0; s < 6; s++) {
            int r0 = (16 * wid + g) * 208 + s * 32 + tg * 4;
            uint32_t a0 = *(const uint32_t*)(A + r0);
            uint32_t a2 = *(const uint32_t*)(A + r0 + 16);
            uint32_t a1 = *(const uint32_t*)(A + r0 + 8 * 208);
            uint32_t a3 = *(const uint32_t*)(A + r0 + 8 * 208 + 16);
            #pragma unroll
            for (int t = 0; t < 20; t++) {
                int wo = (8 * t + g) * 208 + s * 32 + tg * 4;
                uint32_t b0 = *(const uint32_t*)(W + wo);
                uint32_t b1 = *(const uint32_t*)(W + wo + 16);
                mma16816(c[t], a0, a1, a2, a3, b0, b1);
            }
        }
        if (more) sta_smem(Ab[nb], aoff, gir, gjr);
        CP_WAIT0();
        __syncthreads();
    }

    int rowa = m0 + 16 * wid + g;
    #pragma unroll
    for (int t = 0; t < 20; t++) {
        int col = 8 * t + tg * 2;
        *(float2*)&d_Cg[(size_t)rowa * 160 + col] = make_float2(c[t][0], c[t][1]);
        *(float2*)&d_Cg[(size_t)(rowa + 8) * 160 + col] = make_float2(c[t][2], c[t][3]);
    }
}

// ---------------------------------------------------------------------------
// k_pairE: dual fused epilogues per 32 pair-rows.
// ---------------------------------------------------------------------------
__device__ __forceinline__ void run_epi(
    const float acc[4][5], const int* fi, const int* se,
    const float* __restrict__ pb1, const float* __restrict__ pw2,
    const float* __restrict__ pb2, const float* __restrict__ pw3,
    const float* __restrict__ pb3,
    float* s1, float* ews, float* eps,
    int jg, int hg, int tid, float* __restrict__ out)
{
    int h0 = 5 * hg;
    int kk2 = tid >> 4;
    int hb2 = tid & 15;
    __syncthreads();
    #pragma unroll
    for (int q = 0; q < 5; q++) {
        int h = h0 + q;
        #pragma unroll
        for (int jj = 0; jj < 4; jj++) {
            int t = 4 * jg + jj;
            float v = 0.f;
            if (h < HH) {
                float cc = acc[jj][q] + pb1[h];
                cc = cc + d_A[fi[t] * HH + h];
                cc = cc + d_Bt[se[t] * HH + h];
                v = fmaxf(cc, 0.f);
            }
            s1[t * HS + h] = v;
        }
    }
    float acc2[4][5];
    #pragma unroll
    for (int jj = 0; jj < 4; jj++)
        #pragma unroll
        for (int q = 0; q < 5; q++) {
            int h = h0 + q;
            acc2[jj][q] = (h < HH) ? pb2[h] : 0.f;
        }
    for (int k0 = 0; k0 < 160; k0 += 16) {
        __syncthreads();
        #pragma unroll
        for (int q = 0; q < 10; q++) {
            int h = hb2 + 16 * q;
            if (h < 160) {
                float v = 0.f;
                if ((k0 + kk2) < HH && h < HH) v = pw2[(k0 + kk2) * HH + h];
                ews[kk2 * HS + h] = v;
            }
        }
        #pragma unroll
        for (int r = 0; r < 2; r++) {
            int idx = tid + 256 * r;
            int t = idx >> 4, kk = idx & 15;
            eps[kk * 36 + t] = s1[t * HS + k0 + kk];
        }
        __syncthreads();
        #pragma unroll
        for (int kk = 0; kk < 16; kk++) {
            float4 p = *(const float4*)&eps[kk * 36 + 4 * jg];
            const float* wr = &ews[kk * HS + h0];
            float w0 = wr[0], w1 = wr[1], w2 = wr[2], w3 = wr[3], w4 = wr[4];
            acc2[0][0] += p.x * w0; acc2[0][1] += p.x * w1; acc2[0][2] += p.x * w2;
            acc2[0][3] += p.x * w3; acc2[0][4] += p.x * w4;
            acc2[1][0] += p.y * w0; acc2[1][1] += p.y * w1; acc2[1][2] += p.y * w2;
            acc2[1][3] += p.y * w3; acc2[1][4] += p.y * w4;
            acc2[2][0] += p.z * w0; acc2[2][1] += p.z * w1; acc2[2][2] += p.z * w2;
            acc2[2][3] += p.z * w3; acc2[2][4] += p.z * w4;
            acc2[3][0] += p.w * w0; acc2[3][1] += p.w * w1; acc2[3][2] += p.w * w2;
            acc2[3][3] += p.w * w3; acc2[3][4] += p.w * w4;
        }
    }
    float part[4];
    #pragma unroll
    for (int jj = 0; jj < 4; jj++) {
        float s = 0.f;
        #pragma unroll
        for (int q = 0; q < 5; q++) {
            int h = h0 + q;
            if (h < HH) s += fmaxf(acc2[jj][q], 0.f) * pw3[h];
        }
        part[jj] = s;
    }
    #pragma unroll
    for (int jj = 0; jj < 4; jj++)
        #pragma unroll
        for (int off = 16; off > 0; off >>= 1)
            part[jj] += __shfl_xor_sync(0xffffffffu, part[jj], off);
    if (hg == 0) {
        #pragma unroll
        for (int jj = 0; jj < 4; jj++) {
            int t = 4 * jg + jj;
            float sc = part[jj] + pb3[0];
            float v = ((d_ms[fi[t]] + d_ms[se[t]]) + sc) * (1.f / 3.f);
            v = fminf(fmaxf(v, 0.f), 1.f);
            out[(size_t)fi[t] * SS + (se[t] % SS)] = v;
        }
    }
}

__global__ void __launch_bounds__(256) k_pairE(
    const float* __restrict__ pb1, const float* __restrict__ pw2,
    const float* __restrict__ pb2, const float* __restrict__ pw3,
    const float* __restrict__ pb3, float* __restrict__ out)
{
    __shared__ __align__(16) float s1[32 * HS];
    __shared__ __align__(16) float ews[16 * HS];
    __shared__ __align__(16) float eps[16 * 36];
    __shared__ int pis[32], pjs[32];

    int r0 = blockIdx.x * 32;
    int tid = threadIdx.x;
    int jg = tid >> 5;
    int hg = tid & 31;
    int h0 = 5 * hg;

    if (tid < 32) { pis[tid] = d_pi[r0 + tid]; pjs[tid] = d_pj[r0 + tid]; }
    __syncthreads();

    float acc[4][5];
    #pragma unroll
    for (int jj = 0; jj < 4; jj++) {
        int r = r0 + 4 * jg + jj;
        #pragma unroll
        for (int q = 0; q < 5; q++)
            acc[jj][q] = d_Cg[(size_t)r * 160 + h0 + q];
    }

    run_epi(acc, pis, pjs, pb1, pw2, pb2, pw3, pb3, s1, ews, eps, jg, hg, tid, out);
    run_epi(acc, pjs, pis, pb1, pw2, pb2, pw3, pb3, s1, ews, eps, jg, hg, tid, out);
}

// ---------------------------------------------------------------------------
extern "C" void kernel_launch(void* const* d_in, const int* in_sizes, int n_in,
                              void* d_out, int out_size)
{
    const float* X   = (const float*)d_in[0];
    const void*  sp  = d_in[1];
    const float* aw1 = (const float*)d_in[2];
    const float* ab1 = (const float*)d_in[3];
    const float* aw2 = (const float*)d_in[4];
    const float* ab2 = (const float*)d_in[5];
    const float* aw3 = (const float*)d_in[6];
    const float* ab3 = (const float*)d_in[7];
    const float* mw1 = (const float*)d_in[8];
    const float* mb1 = (const float*)d_in[9];
    const float* mw2 = (const float*)d_in[10];
    const float* mb2 = (const float*)d_in[11];
    const float* mw3 = (const float*)d_in[12];
    const float* mb3 = (const float*)d_in[13];
    const float* pw1 = (const float*)d_in[14];
    const float* pb1 = (const float*)d_in[15];
    const float* pw2 = (const float*)d_in[16];
    const float* pb2 = (const float*)d_in[17];
    const float* pw3 = (const float*)d_in[18];
    const float* pb3 = (const float*)d_in[19];
    float* out = (float*)d_out;

    cudaFuncSetAttribute(k_gemm, cudaFuncAttributeMaxDynamicSharedMemorySize,
                         SMEMG);

    k_init<<<1, 192>>>(sp);
    k_plist<<<72, 256>>>();
    k_wprep<<<(160 * KPR + 255) / 256, 256>>>(pw1);
    k_span<<<NSPAN, 320>>>(X, aw1, ab1, aw2, ab2, aw3, ab3);
    k_terms<<<288, 256>>>(pw1, mw1);
    k_reduce<<<(NSPAN * HH + 255) / 256, 256>>>();
    k_ment<<<NSPAN, 160>>>(mb1, mw2, mb2, mw3, mb3);
    k_gemm<<<NPAIRP / 128, 256, SMEMG>>>();
    k_pairE<<<NPAIR / 32, 256>>>(pb1, pw2, pb2, pw3, pb3, out);
}

// round 8
// speedup vs baseline: 5.0398x; 1.5099x over previous
#include <cuda_runtime.h>
#include <cuda_bf16.h>
#include <cstdint>

#define BB 2
#define TT 2048
#define EE 768
#define SS 96
#define HH 150
#define HS 168
#define WW 8
#define E3 2304
#define NSPAN (BB*SS)      // 192
#define NROW (NSPAN*WW)    // 1536 (span,token) rows
#define NPAIR 9312
#define NPAIRP 9344        // 73*128
#define KPR 6912           // 3*E3 interleaved split K
#define KSP2 2
#define NCHA2 36           // chunks of 96 k' per K-split
#define ABUF 26624         // 128 rows * 208 B
#define WBUF 33280         // 160 rows * 208 B
#define SMEMG (2*ABUF + 2*WBUF)   // 119808

// -------- device scratch --------
__device__ int   d_starts[NSPAN];
__device__ __align__(16) float d_g[NSPAN * E3];
__device__ float d_part[3 * 16 * NSPAN * HH];
__device__ float d_ap[8 * NROW * 160];      // attn layer-1 partials
__device__ float d_at[NROW];                // attn scalar per (span,w)
__device__ float d_A[NSPAN * HH];
__device__ float d_Bt[NSPAN * HH];
__device__ float d_m1[NSPAN * HH];
__device__ float d_ms[NSPAN];
__device__ int   d_pi[NPAIRP], d_pj[NPAIRP];
__device__ __align__(16) __nv_bfloat16 d_Wi[160 * KPR];
__device__ float d_Cg2[KSP2][(size_t)NPAIRP * 160];

// -------- generic-PTX helpers --------
__device__ __forceinline__ uint32_t smem_u32(const void* p) {
    uint32_t a;
    asm("{ .reg .u64 t; cvta.to.shared.u64 t, %1; cvt.u32.u64 %0, t; }"
        : "=r"(a) : "l"(p));
    return a;
}
#define CP_ASYNC16(dst, src) \
    asm volatile("cp.async.cg.shared.global [%0], [%1], 16;" \
                 :: "r"(dst), "l"(src) : "memory")
#define CP_COMMIT() asm volatile("cp.async.commit_group;" ::: "memory")
#define CP_WAIT0()  asm volatile("cp.async.wait_group 0;" ::: "memory")

__device__ __forceinline__ void mma16816(float c[4], uint32_t a0, uint32_t a1,
                                         uint32_t a2, uint32_t a3,
                                         uint32_t b0, uint32_t b1) {
    asm volatile(
        "mma.sync.aligned.m16n8k16.row.col.f32.bf16.bf16.f32 "
        "{%0,%1,%2,%3}, {%4,%5,%6,%7}, {%8,%9}, {%0,%1,%2,%3};"
        : "+f"(c[0]), "+f"(c[1]), "+f"(c[2]), "+f"(c[3])
        : "r"(a0), "r"(a1), "r"(a2), "r"(a3), "r"(b0), "r"(b1));
}

// ---------------------------------------------------------------------------
__global__ void k_init(const void* sp) {
    __shared__ int is64;
    if (threadIdx.x == 0) {
        const int* w32 = (const int*)sp;
        int z = 1;
        for (int i = 1; i < 64; i += 2) if (w32[i] != 0) { z = 0; break; }
        is64 = z;
    }
    __syncthreads();
    int i = threadIdx.x;
    if (i < NSPAN) {
        if (is64) d_starts[i] = (int)((const long long*)sp)[i];
        else      d_starts[i] = ((const int*)sp)[i];
    }
}

// ---------------------------------------------------------------------------
__global__ void k_plist() {
    int idx = blockIdx.x * blockDim.x + threadIdx.x;
    if (idx < 2 * SS * SS) {
        int b = idx / (SS * SS), r = idx % (SS * SS);
        int i = r / SS, j = r % SS;
        if (j >= i) {
            int row = b * 4656 + i * SS - i * (i - 1) / 2 + (j - i);
            d_pi[row] = b * SS + i;
            d_pj[row] = b * SS + j;
        }
    }
    if (idx < NPAIRP - NPAIR) {
        d_pi[NPAIR + idx] = NSPAN - 1;
        d_pj[NPAIR + idx] = NSPAN - 1;
    }
}

// ---------------------------------------------------------------------------
__global__ void k_wprep(const float* __restrict__ pw1) {
    int idx = blockIdx.x * blockDim.x + threadIdx.x;
    if (idx >= 160 * KPR) return;
    int n = idx / KPR, kp = idx % KPR;
    int k = kp / 3, r = kp - 3 * k;
    float w = (n < HH) ? pw1[(size_t)2 * E3 * HH + (size_t)k * HH + n] : 0.f;
    unsigned short hu;
    asm("cvt.rn.bf16.f32 %0, %1;" : "=h"(hu) : "f"(w));
    if (r == 1) {
        float hf = __uint_as_float(((uint32_t)hu) << 16);
        float l = w - hf;
        asm("cvt.rn.bf16.f32 %0, %1;" : "=h"(hu) : "f"(l));
    }
    ((unsigned short*)d_Wi)[idx] = hu;
}

// ---------------------------------------------------------------------------
// k_attn1: h1 partials for 1536 rows: [1536,768]@aw1 — 48 rowchunks x 8 ksplits
// ---------------------------------------------------------------------------
__global__ void __launch_bounds__(256) k_attn1(
    const float* __restrict__ X, const float* __restrict__ aw1)
{
    int bx = blockIdx.x;
    int rc = bx % 48, ks = bx / 48;
    int r0 = rc * 32;
    int kbase = ks * 96;
    int tid = threadIdx.x;
    int jg = tid >> 5, hg = tid & 31;
    int h0 = 5 * hg;
    int kk2 = tid >> 4, hb2 = tid & 15;

    __shared__ __align__(16) float wst[16 * HS];
    __shared__ __align__(16) float pst[16 * 36];
    __shared__ size_t rowoff[32];

    if (tid < 32) {
        int rr = r0 + tid;
        int si = rr >> 3, w = rr & 7;
        int b = si / SS;
        rowoff[tid] = ((size_t)(b * TT + d_starts[si] + w)) * EE;
    }
    __syncthreads();

    float acc[4][5];
    #pragma unroll
    for (int jj = 0; jj < 4; jj++)
        #pragma unroll
        for (int q = 0; q < 5; q++) acc[jj][q] = 0.f;

    for (int kc = 0; kc < 96; kc += 16) {
        int k0 = kbase + kc;
        __syncthreads();
        #pragma unroll
        for (int q = 0; q < 10; q++) {
            int h = hb2 + 16 * q;
            if (h < 160)
                wst[kk2 * HS + h] = (h < HH) ? aw1[(size_t)(k0 + kk2) * HH + h] : 0.f;
        }
        #pragma unroll
        for (int r = 0; r < 2; r++) {
            int idx = tid + 256 * r;
            int t = idx >> 4, kk = idx & 15;
            pst[kk * 36 + t] = X[rowoff[t] + k0 + kk];
        }
        __syncthreads();
        #pragma unroll
        for (int kk = 0; kk < 16; kk++) {
            float4 p = *(const float4*)&pst[kk * 36 + 4 * jg];
            const float* wr = &wst[kk * HS + h0];
            float w0 = wr[0], w1 = wr[1], w2 = wr[2], w3 = wr[3], w4 = wr[4];
            acc[0][0] += p.x * w0; acc[0][1] += p.x * w1; acc[0][2] += p.x * w2;
            acc[0][3] += p.x * w3; acc[0][4] += p.x * w4;
            acc[1][0] += p.y * w0; acc[1][1] += p.y * w1; acc[1][2] += p.y * w2;
            acc[1][3] += p.y * w3; acc[1][4] += p.y * w4;
            acc[2][0] += p.z * w0; acc[2][1] += p.z * w1; acc[2][2] += p.z * w2;
            acc[2][3] += p.z * w3; acc[2][4] += p.z * w4;
            acc[3][0] += p.w * w0; acc[3][1] += p.w * w1; acc[3][2] += p.w * w2;
            acc[3][3] += p.w * w3; acc[3][4] += p.w * w4;
        }
    }
    #pragma unroll
    for (int jj = 0; jj < 4; jj++) {
        int t = 4 * jg + jj;
        float* op = d_ap + ((size_t)ks * NROW + r0 + t) * 160;
        #pragma unroll
        for (int q = 0; q < 5; q++) op[h0 + q] = acc[jj][q];
    }
}

// ---------------------------------------------------------------------------
// k_attn2: reduce partials + bias + relu -> layer2 -> relu -> dot aw3 -> d_at
// ---------------------------------------------------------------------------
__global__ void __launch_bounds__(256) k_attn2(
    const float* __restrict__ ab1, const float* __restrict__ aw2,
    const float* __restrict__ ab2, const float* __restrict__ aw3,
    const float* __restrict__ ab3)
{
    int r0 = blockIdx.x * 32;
    int tid = threadIdx.x;
    int jg = tid >> 5, hg = tid & 31;
    int h0 = 5 * hg;
    int kk2 = tid >> 4, hb2 = tid & 15;

    __shared__ __align__(16) float s1[32 * HS];
    __shared__ __align__(16) float ews[16 * HS];
    __shared__ __align__(16) float eps[16 * 36];

    for (int idx = tid; idx < 32 * 160; idx += 256) {
        int t = idx / 160, h = idx - (idx / 160) * 160;
        float v = 0.f;
        if (h < HH) {
            float s = ab1[h];
            #pragma unroll
            for (int ks = 0; ks < 8; ks++)
                s += d_ap[((size_t)ks * NROW + r0 + t) * 160 + h];
            v = fmaxf(s, 0.f);
        }
        s1[t * HS + h] = v;
    }

    float acc2[4][5];
    #pragma unroll
    for (int jj = 0; jj < 4; jj++)
        #pragma unroll
        for (int q = 0; q < 5; q++) {
            int h = h0 + q;
            acc2[jj][q] = (h < HH) ? ab2[h] : 0.f;
        }
    for (int k0 = 0; k0 < 160; k0 += 16) {
        __syncthreads();
        #pragma unroll
        for (int q = 0; q < 10; q++) {
            int h = hb2 + 16 * q;
            if (h < 160) {
                float v = 0.f;
                if ((k0 + kk2) < HH && h < HH) v = aw2[(k0 + kk2) * HH + h];
                ews[kk2 * HS + h] = v;
            }
        }
        #pragma unroll
        for (int r = 0; r < 2; r++) {
            int idx = tid + 256 * r;
            int t = idx >> 4, kk = idx & 15;
            eps[kk * 36 + t] = s1[t * HS + k0 + kk];
        }
        __syncthreads();
        #pragma unroll
        for (int kk = 0; kk < 16; kk++) {
            float4 p = *(const float4*)&eps[kk * 36 + 4 * jg];
            const float* wr = &ews[kk * HS + h0];
            float w0 = wr[0], w1 = wr[1], w2 = wr[2], w3 = wr[3], w4 = wr[4];
            acc2[0][0] += p.x * w0; acc2[0][1] += p.x * w1; acc2[0][2] += p.x * w2;
            acc2[0][3] += p.x * w3; acc2[0][4] += p.x * w4;
            acc2[1][0] += p.y * w0; acc2[1][1] += p.y * w1; acc2[1][2] += p.y * w2;
            acc2[1][3] += p.y * w3; acc2[1][4] += p.y * w4;
            acc2[2][0] += p.z * w0; acc2[2][1] += p.z * w1; acc2[2][2] += p.z * w2;
            acc2[2][3] += p.z * w3; acc2[2][4] += p.z * w4;
            acc2[3][0] += p.w * w0; acc2[3][1] += p.w * w1; acc2[3][2] += p.w * w2;
            acc2[3][3] += p.w * w3; acc2[3][4] += p.w * w4;
        }
    }
    float part[4];
    #pragma unroll
    for (int jj = 0; jj < 4; jj++) {
        float s = 0.f;
        #pragma unroll
        for (int q = 0; q < 5; q++) {
            int h = h0 + q;
            if (h < HH) s += fmaxf(acc2[jj][q], 0.f) * aw3[h];
        }
        part[jj] = s;
    }
    #pragma unroll
    for (int jj = 0; jj < 4; jj++)
        #pragma unroll
        for (int off = 16; off > 0; off >>= 1)
            part[jj] += __shfl_xor_sync(0xffffffffu, part[jj], off);
    if (hg == 0) {
        #pragma unroll
        for (int jj = 0; jj < 4; jj++)
            d_at[r0 + 4 * jg + jj] = part[jj] + ab3[0];
    }
}

// ---------------------------------------------------------------------------
// k_gather: build g_i = [start | end | sum_w x_w * at_w]
// ---------------------------------------------------------------------------
__global__ void __launch_bounds__(256) k_gather(const float* __restrict__ X)
{
    int si = blockIdx.x;
    int b = si / SS;
    int st = d_starts[si];
    int tid = threadIdx.x;
    __shared__ float atv[8];
    if (tid < 8) atv[tid] = d_at[si * 8 + tid];
    __syncthreads();

    const float* Xb = X + ((size_t)b * TT + st) * EE;
    float* gp = d_g + (size_t)si * E3;
    for (int e = tid; e < EE; e += 256) {
        float s = 0.f;
        float x0 = 0.f, x7 = 0.f;
        #pragma unroll
        for (int w = 0; w < WW; w++) {
            float xv = Xb[w * EE + e];
            if (w == 0) x0 = xv;
            if (w == 7) x7 = xv;
            s += xv * atv[w];
        }
        gp[e]          = x0;
        gp[EE + e]     = x7;
        gp[2 * EE + e] = s;
    }
}

// ---------------------------------------------------------------------------
__global__ void __launch_bounds__(256) k_terms(
    const float* __restrict__ pw1, const float* __restrict__ mw1)
{
    int x = blockIdx.x;
    int sc  = x % 6;
    int mat = (x / 6) % 3;
    int ks  = x / 18;
    const float* Wm = (mat == 0) ? pw1 : (mat == 1 ? pw1 + (size_t)E3 * HH : mw1);
    int s0 = sc * 32;
    int kbase = ks * 144;
    int tid = threadIdx.x;
    int jg = tid >> 5;
    int hg = tid & 31;
    int h0 = 5 * hg;
    int kk2 = tid >> 4;
    int hb2 = tid & 15;

    __shared__ __align__(16) float wst[16 * HS];
    __shared__ __align__(16) float pst[16 * 36];

    float acc[4][5];
    #pragma unroll
    for (int jj = 0; jj < 4; jj++)
        #pragma unroll
        for (int q = 0; q < 5; q++) acc[jj][q] = 0.f;

    for (int kc = 0; kc < 144; kc += 16) {
        int k0 = kbase + kc;
        __syncthreads();
        #pragma unroll
        for (int q = 0; q < 10; q++) {
            int h = hb2 + 16 * q;
            if (h < 160)
                wst[kk2 * HS + h] = (h < HH) ? Wm[(size_t)(k0 + kk2) * HH + h] : 0.f;
        }
        #pragma unroll
        for (int r = 0; r < 2; r++) {
            int idx = tid + 256 * r;
            int t = idx >> 4, kk = idx & 15;
            pst[kk * 36 + t] = d_g[(size_t)(s0 + t) * E3 + k0 + kk];
        }
        __syncthreads();
        #pragma unroll
        for (int kk = 0; kk < 16; kk++) {
            float4 p = *(const float4*)&pst[kk * 36 + 4 * jg];
            const float* wr = &wst[kk * HS + h0];
            float w0 = wr[0], w1 = wr[1], w2 = wr[2], w3 = wr[3], w4 = wr[4];
            acc[0][0] += p.x * w0; acc[0][1] += p.x * w1; acc[0][2] += p.x * w2;
            acc[0][3] += p.x * w3; acc[0][4] += p.x * w4;
            acc[1][0] += p.y * w0; acc[1][1] += p.y * w1; acc[1][2] += p.y * w2;
            acc[1][3] += p.y * w3; acc[1][4] += p.y * w4;
            acc[2][0] += p.z * w0; acc[2][1] += p.z * w1; acc[2][2] += p.z * w2;
            acc[2][3] += p.z * w3; acc[2][4] += p.z * w4;
            acc[3][0] += p.w * w0; acc[3][1] += p.w * w1; acc[3][2] += p.w * w2;
            acc[3][3] += p.w * w3; acc[3][4] += p.w * w4;
        }
    }
    #pragma unroll
    for (int jj = 0; jj < 4; jj++) {
        int t = 4 * jg + jj;
        float* op = d_part + (((size_t)mat * 16 + ks) * NSPAN + s0 + t) * HH;
        #pragma unroll
        for (int q = 0; q < 5; q++) {
            int h = h0 + q;
            if (h < HH) op[h] = acc[jj][q];
        }
    }
}

// ---------------------------------------------------------------------------
__global__ void k_reduce() {
    int i = blockIdx.x * blockDim.x + threadIdx.x;
    if (i >= NSPAN * HH) return;
    #pragma unroll
    for (int mat = 0; mat < 3; mat++) {
        float s = 0.f;
        #pragma unroll
        for (int ks = 0; ks < 16; ks++)
            s += d_part[((size_t)mat * 16 + ks) * (NSPAN * HH) + i];
        if (mat == 0)      d_A[i]  = s;
        else if (mat == 1) d_Bt[i] = s;
        else               d_m1[i] = s;
    }
}

// ---------------------------------------------------------------------------
__global__ void __launch_bounds__(160) k_ment(
    const float* __restrict__ mb1, const float* __restrict__ mw2,
    const float* __restrict__ mb2, const float* __restrict__ mw3,
    const float* __restrict__ mb3)
{
    int s = blockIdx.x;
    int tid = threadIdx.x;
    __shared__ float s1[HH];
    __shared__ float warpsum[8];

    if (tid < HH) s1[tid] = fmaxf(d_m1[s * HH + tid] + mb1[tid], 0.f);
    __syncthreads();
    float p = 0.f;
    if (tid < HH) {
        float v = mb2[tid];
        for (int k = 0; k < HH; k++) v += s1[k] * mw2[k * HH + tid];
        p = fmaxf(v, 0.f) * mw3[tid];
    }
    #pragma unroll
    for (int o = 16; o > 0; o >>= 1) p += __shfl_down_sync(0xffffffffu, p, o);
    if ((tid & 31) == 0) warpsum[tid >> 5] = p;
    __syncthreads();
    if (tid == 0) {
        float t = mb3[0];
        for (int w = 0; w < 5; w++) t += warpsum[w];
        d_ms[s] = t;
    }
}

// ---------------------------------------------------------------------------
// k_gemm helpers
// ---------------------------------------------------------------------------
__device__ __forceinline__ void lda_regs(const float* gi, const float* gj,
                                         int ch, float* gir, float* gjr) {
    const float4* a4 = (const float4*)(gi + ch * 32);
    const float4* b4 = (const float4*)(gj + ch * 32);
    #pragma unroll
    for (int u = 0; u < 4; u++) {
        float4 a = a4[u], b = b4[u];
        gir[4*u+0] = a.x; gir[4*u+1] = a.y; gir[4*u+2] = a.z; gir[4*u+3] = a.w;
        gjr[4*u+0] = b.x; gjr[4*u+1] = b.y; gjr[4*u+2] = b.z; gjr[4*u+3] = b.w;
    }
}

__device__ __forceinline__ void sta_smem(char* dst, int aoff,
                                         const float* gir, const float* gjr) {
    unsigned short us[48];
    #pragma unroll
    for (int k = 0; k < 16; k++) {
        float p = gir[k] * gjr[k];
        unsigned short hu;
        asm("cvt.rn.bf16.f32 %0, %1;" : "=h"(hu) : "f"(p));
        float hf = __uint_as_float(((uint32_t)hu) << 16);
        float l = p - hf;
        unsigned short lu;
        asm("cvt.rn.bf16.f32 %0, %1;" : "=h"(lu) : "f"(l));
        us[3*k+0] = hu; us[3*k+1] = hu; us[3*k+2] = lu;
    }
    uint32_t u[24];
    #pragma unroll
    for (int j = 0; j < 24; j++)
        u[j] = (uint32_t)us[2*j] | ((uint32_t)us[2*j+1] << 16);
    uint4* d = (uint4*)(dst + aoff);
    d[0] = make_uint4(u[0],  u[1],  u[2],  u[3]);
    d[1] = make_uint4(u[4],  u[5],  u[6],  u[7]);
    d[2] = make_uint4(u[8],  u[9],  u[10], u[11]);
    d[3] = make_uint4(u[12], u[13], u[14], u[15]);
    d[4] = make_uint4(u[16], u[17], u[18], u[19]);
    d[5] = make_uint4(u[20], u[21], u[22], u[23]);
}

__device__ __forceinline__ void cpw_chunk(uint32_t wdst, int wkoff, int ch, int tid) {
    #pragma unroll
    for (int v = 0; v < 2; v++) {
        int unit = tid + 256 * v;
        if (unit < 320) {
            int n = unit >> 1, kh = unit & 1;
            const char* src = (const char*)d_Wi + (size_t)n * (KPR * 2)
                              + wkoff + ch * 192 + kh * 96;
            uint32_t dst = wdst + n * 208 + kh * 96;
            #pragma unroll
            for (int q = 0; q < 6; q++)
                CP_ASYNC16(dst + q * 16, src + q * 16);
        }
    }
}

// ---------------------------------------------------------------------------
// k_gemm: C-partials via mma.sync bf16, split-interleaved K. 146 blocks
// (73 M-tiles x 2 K-splits of 3456 k').
// ---------------------------------------------------------------------------
__global__ void __launch_bounds__(256) k_gemm()
{
    extern __shared__ __align__(16) char smg[];
    char* Ab[2] = { smg, smg + ABUF };
    char* Wb[2] = { smg + 2 * ABUF, smg + 2 * ABUF + WBUF };
    uint32_t Wbu[2] = { smem_u32(Wb[0]), smem_u32(Wb[1]) };

    int tid = threadIdx.x, wid = tid >> 5, lane = tid & 31;
    int g = lane >> 2, tg = lane & 3;
    int mt = blockIdx.x >> 1, ksp = blockIdx.x & 1;
    int m0 = mt * 128;
    int wkoff = ksp * (KPR / 2);          // byte offset = ksp*3456 shorts*2 = ksp*6912... careful
    // KPR/2 k' per split = 3456 shorts = 6912 bytes:
    wkoff = ksp * 3456 * 2;

    int arow = tid >> 1, akh = tid & 1;
    const float* gi = d_g + (size_t)d_pi[m0 + arow] * E3 + ksp * 1152 + akh * 16;
    const float* gj = d_g + (size_t)d_pj[m0 + arow] * E3 + ksp * 1152 + akh * 16;
    int aoff = arow * 208 + akh * 96;

    float c[20][4];
    #pragma unroll
    for (int t = 0; t < 20; t++)
        #pragma unroll
        for (int q = 0; q < 4; q++) c[t][q] = 0.f;

    float gir[16], gjr[16];

    cpw_chunk(Wbu[0], wkoff, 0, tid);
    CP_COMMIT();
    lda_regs(gi, gj, 0, gir, gjr);
    sta_smem(Ab[0], aoff, gir, gjr);
    CP_WAIT0();
    __syncthreads();

    for (int ch = 0; ch < NCHA2; ch++) {
        int buf = ch & 1, nb = buf ^ 1;
        bool more = (ch + 1 < NCHA2);
        if (more) {
            cpw_chunk(Wbu[nb], wkoff, ch + 1, tid);
            CP_COMMIT();
            lda_regs(gi, gj, ch + 1, gir, gjr);
        }
        const char* A = Ab[buf];
        const char* W = Wb[buf];
        #pragma unroll
        for (int s = 0; s < 6; s++) {
            int r0 = (16 * wid + g) * 208 + s * 32 + tg * 4;
            uint32_t a0 = *(const uint32_t*)(A + r0);
            uint32_t a2 = *(const uint32_t*)(A + r0 + 16);
            uint32_t a1 = *(const uint32_t*)(A + r0 + 8 * 208);
            uint32_t a3 = *(const uint32_t*)(A + r0 + 8 * 208 + 16);
            #pragma unroll
            for (int t = 0; t < 20; t++) {
                int wo = (8 * t + g) * 208 + s * 32 + tg * 4;
                uint32_t b0 = *(const uint32_t*)(W + wo);
                uint32_t b1 = *(const uint32_t*)(W + wo + 16);
                mma16816(c[t], a0, a1, a2, a3, b0, b1);
            }
        }
        if (more) sta_smem(Ab[nb], aoff, gir, gjr);
        CP_WAIT0();
        __syncthreads();
    }

    int rowa = m0 + 16 * wid + g;
    float* Cd = d_Cg2[ksp];
    #pragma unroll
    for (int t = 0; t < 20; t++) {
        int col = 8 * t + tg * 2;
        *(float2*)&Cd[(size_t)rowa * 160 + col] = make_float2(c[t][0], c[t][1]);
        *(float2*)&Cd[(size_t)(rowa + 8) * 160 + col] = make_float2(c[t][2], c[t][3]);
    }
}

// ---------------------------------------------------------------------------
// k_pairE: dual fused epilogues per 32 pair-rows (sums 2 K-split partials).
// ---------------------------------------------------------------------------
__device__ __forceinline__ void run_epi(
    const float acc[4][5], const int* fi, const int* se,
    const float* __restrict__ pb1, const float* __restrict__ pw2,
    const float* __restrict__ pb2, const float* __restrict__ pw3,
    const float* __restrict__ pb3,
    float* s1, float* ews, float* eps,
    int jg, int hg, int tid, float* __restrict__ out)
{
    int h0 = 5 * hg;
    int kk2 = tid >> 4;
    int hb2 = tid & 15;
    __syncthreads();
    #pragma unroll
    for (int q = 0; q < 5; q++) {
        int h = h0 + q;
        #pragma unroll
        for (int jj = 0; jj < 4; jj++) {
            int t = 4 * jg + jj;
            float v = 0.f;
            if (h < HH) {
                float cc = acc[jj][q] + pb1[h];
                cc = cc + d_A[fi[t] * HH + h];
                cc = cc + d_Bt[se[t] * HH + h];
                v = fmaxf(cc, 0.f);
            }
            s1[t * HS + h] = v;
        }
    }
    float acc2[4][5];
    #pragma unroll
    for (int jj = 0; jj < 4; jj++)
        #pragma unroll
        for (int q = 0; q < 5; q++) {
            int h = h0 + q;
            acc2[jj][q] = (h < HH) ? pb2[h] : 0.f;
        }
    for (int k0 = 0; k0 < 160; k0 += 16) {
        __syncthreads();
        #pragma unroll
        for (int q = 0; q < 10; q++) {
            int h = hb2 + 16 * q;
            if (h < 160) {
                float v = 0.f;
                if ((k0 + kk2) < HH && h < HH) v = pw2[(k0 + kk2) * HH + h];
                ews[kk2 * HS + h] = v;
            }
        }
        #pragma unroll
        for (int r = 0; r < 2; r++) {
            int idx = tid + 256 * r;
            int t = idx >> 4, kk = idx & 15;
            eps[kk * 36 + t] = s1[t * HS + k0 + kk];
        }
        __syncthreads();
        #pragma unroll
        for (int kk = 0; kk < 16; kk++) {
            float4 p = *(const float4*)&eps[kk * 36 + 4 * jg];
            const float* wr = &ews[kk * HS + h0];
            float w0 = wr[0], w1 = wr[1], w2 = wr[2], w3 = wr[3], w4 = wr[4];
            acc2[0][0] += p.x * w0; acc2[0][1] += p.x * w1; acc2[0][2] += p.x * w2;
            acc2[0][3] += p.x * w3; acc2[0][4] += p.x * w4;
            acc2[1][0] += p.y * w0; acc2[1][1] += p.y * w1; acc2[1][2] += p.y * w2;
            acc2[1][3] += p.y * w3; acc2[1][4] += p.y * w4;
            acc2[2][0] += p.z * w0; acc2[2][1] += p.z * w1; acc2[2][2] += p.z * w2;
            acc2[2][3] += p.z * w3; acc2[2][4] += p.z * w4;
            acc2[3][0] += p.w * w0; acc2[3][1] += p.w * w1; acc2[3][2] += p.w * w2;
            acc2[3][3] += p.w * w3; acc2[3][4] += p.w * w4;
        }
    }
    float part[4];
    #pragma unroll
    for (int jj = 0; jj < 4; jj++) {
        float s = 0.f;
        #pragma unroll
        for (int q = 0; q < 5; q++) {
            int h = h0 + q;
            if (h < HH) s += fmaxf(acc2[jj][q], 0.f) * pw3[h];
        }
        part[jj] = s;
    }
    #pragma unroll
    for (int jj = 0; jj < 4; jj++)
        #pragma unroll
        for (int off = 16; off > 0; off >>= 1)
            part[jj] += __shfl_xor_sync(0xffffffffu, part[jj], off);
    if (hg == 0) {
        #pragma unroll
        for (int jj = 0; jj < 4; jj++) {
            int t = 4 * jg + jj;
            float sc = part[jj] + pb3[0];
            float v = ((d_ms[fi[t]] + d_ms[se[t]]) + sc) * (1.f / 3.f);
            v = fminf(fmaxf(v, 0.f), 1.f);
            out[(size_t)fi[t] * SS + (se[t] % SS)] = v;
        }
    }
}

__global__ void __launch_bounds__(256) k_pairE(
    const float* __restrict__ pb1, const float* __restrict__ pw2,
    const float* __restrict__ pb2, const float* __restrict__ pw3,
    const float* __restrict__ pb3, float* __restrict__ out)
{
    __shared__ __align__(16) float s1[32 * HS];
    __shared__ __align__(16) float ews[16 * HS];
    __shared__ __align__(16) float eps[16 * 36];
    __shared__ int pis[32], pjs[32];

    int r0 = blockIdx.x * 32;
    int tid = threadIdx.x;
    int jg = tid >> 5;
    int hg = tid & 31;
    int h0 = 5 * hg;

    if (tid < 32) { pis[tid] = d_pi[r0 + tid]; pjs[tid] = d_pj[r0 + tid]; }
    __syncthreads();

    float acc[4][5];
    #pragma unroll
    for (int jj = 0; jj < 4; jj++) {
        int r = r0 + 4 * jg + jj;
        #pragma unroll
        for (int q = 0; q < 5; q++) {
            size_t idx = (size_t)r * 160 + h0 + q;
            acc[jj][q] = d_Cg2[0][idx] + d_Cg2[1][idx];
        }
    }

    run_epi(acc, pis, pjs, pb1, pw2, pb2, pw3, pb3, s1, ews, eps, jg, hg, tid, out);
    run_epi(acc, pjs, pis, pb1, pw2, pb2, pw3, pb3, s1, ews, eps, jg, hg, tid, out);
}

// ---------------------------------------------------------------------------
extern "C" void kernel_launch(void* const* d_in, const int* in_sizes, int n_in,
                              void* d_out, int out_size)
{
    const float* X   = (const float*)d_in[0];
    const void*  sp  = d_in[1];
    const float* aw1 = (const float*)d_in[2];
    const float* ab1 = (const float*)d_in[3];
    const float* aw2 = (const float*)d_in[4];
    const float* ab2 = (const float*)d_in[5];
    const float* aw3 = (const float*)d_in[6];
    const float* ab3 = (const float*)d_in[7];
    const float* mw1 = (const float*)d_in[8];
    const float* mb1 = (const float*)d_in[9];
    const float* mw2 = (const float*)d_in[10];
    const float* mb2 = (const float*)d_in[11];
    const float* mw3 = (const float*)d_in[12];
    const float* mb3 = (const float*)d_in[13];
    const float* pw1 = (const float*)d_in[14];
    const float* pb1 = (const float*)d_in[15];
    const float* pw2 = (const float*)d_in[16];
    const float* pb2 = (const float*)d_in[17];
    const float* pw3 = (const float*)d_in[18];
    const float* pb3 = (const float*)d_in[19];
    float* out = (float*)d_out;

    cudaFuncSetAttribute(k_gemm, cudaFuncAttributeMaxDynamicSharedMemorySize,
                         SMEMG);

    k_init<<<1, 192>>>(sp);
    k_plist<<<72, 256>>>();
    k_wprep<<<(160 * KPR + 255) / 256, 256>>>(pw1);
    k_attn1<<<384, 256>>>(X, aw1);
    k_attn2<<<48, 256>>>(ab1, aw2, ab2, aw3, ab3);
    k_gather<<<NSPAN, 256>>>(X);
    k_terms<<<288, 256>>>(pw1, mw1);
    k_reduce<<<(NSPAN * HH + 255) / 256, 256>>>();
    k_ment<<<NSPAN, 160>>>(mb1, mw2, mb2, mw3, mb3);
    k_gemm<<<146, 256, SMEMG>>>();
    k_pairE<<<NPAIR / 32, 256>>>(pb1, pw2, pb2, pw3, pb3, out);
}

// round 9
// speedup vs baseline: 5.5977x; 1.1107x over previous
#include <cuda_runtime.h>
#include <cuda_bf16.h>
#include <cstdint>

#define BB 2
#define TT 2048
#define EE 768
#define SS 96
#define HH 150
#define HS 168
#define WW 8
#define E3 2304
#define NSPAN (BB*SS)      // 192
#define NROW (NSPAN*WW)    // 1536
#define NPAIR 9312
#define NPAIRP 9344        // 73*128
#define KPR 6912           // 3*E3 interleaved split K
#define KSP2 2
#define NCHA2 36
#define ABUF 26624         // 128 rows * 208 B
#define WBUF 33280         // 160 rows * 208 B
#define SMEMG (2*ABUF + 2*WBUF)   // 119808
#define SMEMPE ((64*HS + 16*HS + 16*68) * 4)   // 58112

// -------- device scratch --------
__device__ int   d_starts[NSPAN];
__device__ __align__(16) float d_g[NSPAN * E3];
__device__ float d_part[3 * 16 * NSPAN * HH];
__device__ float d_ap[8 * NROW * 160];
__device__ float d_at[NROW];
__device__ float d_A[NSPAN * HH];
__device__ float d_Bt[NSPAN * HH];
__device__ float d_m1[NSPAN * HH];
__device__ float d_ms[NSPAN];
__device__ int   d_pi[NPAIRP], d_pj[NPAIRP];
__device__ __align__(16) __nv_bfloat16 d_Wi[160 * KPR];
__device__ float d_Cg2[KSP2][(size_t)NPAIRP * 160];

// -------- generic-PTX helpers --------
__device__ __forceinline__ uint32_t smem_u32(const void* p) {
    uint32_t a;
    asm("{ .reg .u64 t; cvta.to.shared.u64 t, %1; cvt.u32.u64 %0, t; }"
        : "=r"(a) : "l"(p));
    return a;
}
#define CP_ASYNC16(dst, src) \
    asm volatile("cp.async.cg.shared.global [%0], [%1], 16;" \
                 :: "r"(dst), "l"(src) : "memory")
#define CP_COMMIT() asm volatile("cp.async.commit_group;" ::: "memory")
#define CP_WAIT0()  asm volatile("cp.async.wait_group 0;" ::: "memory")

__device__ __forceinline__ void mma16816(float c[4], uint32_t a0, uint32_t a1,
                                         uint32_t a2, uint32_t a3,
                                         uint32_t b0, uint32_t b1) {
    asm volatile(
        "mma.sync.aligned.m16n8k16.row.col.f32.bf16.bf16.f32 "
        "{%0,%1,%2,%3}, {%4,%5,%6,%7}, {%8,%9}, {%0,%1,%2,%3};"
        : "+f"(c[0]), "+f"(c[1]), "+f"(c[2]), "+f"(c[3])
        : "r"(a0), "r"(a1), "r"(a2), "r"(a3), "r"(b0), "r"(b1));
}

// ---------------------------------------------------------------------------
__global__ void k_init(const void* sp) {
    __shared__ int is64;
    if (threadIdx.x == 0) {
        const int* w32 = (const int*)sp;
        int z = 1;
        for (int i = 1; i < 64; i += 2) if (w32[i] != 0) { z = 0; break; }
        is64 = z;
    }
    __syncthreads();
    int i = threadIdx.x;
    if (i < NSPAN) {
        if (is64) d_starts[i] = (int)((const long long*)sp)[i];
        else      d_starts[i] = ((const int*)sp)[i];
    }
}

// ---------------------------------------------------------------------------
__global__ void k_plist() {
    int idx = blockIdx.x * blockDim.x + threadIdx.x;
    if (idx < 2 * SS * SS) {
        int b = idx / (SS * SS), r = idx % (SS * SS);
        int i = r / SS, j = r % SS;
        if (j >= i) {
            int row = b * 4656 + i * SS - i * (i - 1) / 2 + (j - i);
            d_pi[row] = b * SS + i;
            d_pj[row] = b * SS + j;
        }
    }
    if (idx < NPAIRP - NPAIR) {
        d_pi[NPAIR + idx] = NSPAN - 1;
        d_pj[NPAIR + idx] = NSPAN - 1;
    }
}

// ---------------------------------------------------------------------------
__global__ void k_wprep(const float* __restrict__ pw1) {
    int idx = blockIdx.x * blockDim.x + threadIdx.x;
    if (idx >= 160 * KPR) return;
    int n = idx / KPR, kp = idx % KPR;
    int k = kp / 3, r = kp - 3 * k;
    float w = (n < HH) ? pw1[(size_t)2 * E3 * HH + (size_t)k * HH + n] : 0.f;
    unsigned short hu;
    asm("cvt.rn.bf16.f32 %0, %1;" : "=h"(hu) : "f"(w));
    if (r == 1) {
        float hf = __uint_as_float(((uint32_t)hu) << 16);
        float l = w - hf;
        asm("cvt.rn.bf16.f32 %0, %1;" : "=h"(hu) : "f"(l));
    }
    ((unsigned short*)d_Wi)[idx] = hu;
}

// ---------------------------------------------------------------------------
// k_attn1: layer-1 partials, software-pipelined staging.
// ---------------------------------------------------------------------------
__global__ void __launch_bounds__(256) k_attn1(
    const float* __restrict__ X, const float* __restrict__ aw1)
{
    int bx = blockIdx.x;
    int rc = bx % 48, ks = bx / 48;
    int r0 = rc * 32;
    int kbase = ks * 96;
    int tid = threadIdx.x;
    int jg = tid >> 5, hg = tid & 31;
    int h0 = 5 * hg;
    int kk2 = tid >> 4, hb2 = tid & 15;
    int pt = tid >> 4, pk = tid & 15;
    int pt2 = (tid + 256) >> 4, pk2 = (tid + 256) & 15;

    __shared__ __align__(16) float wst[16 * HS];
    __shared__ __align__(16) float pst[16 * 36];
    __shared__ size_t rowoff[32];

    if (tid < 32) {
        int rr = r0 + tid;
        int si = rr >> 3, w = rr & 7;
        int b = si / SS;
        rowoff[tid] = ((size_t)(b * TT + d_starts[si] + w)) * EE;
    }
    __syncthreads();

    float acc[4][5];
    #pragma unroll
    for (int jj = 0; jj < 4; jj++)
        #pragma unroll
        for (int q = 0; q < 5; q++) acc[jj][q] = 0.f;

    float wpre[10], p0, p1;
    // prefetch chunk 0
    #pragma unroll
    for (int q = 0; q < 10; q++) {
        int h = hb2 + 16 * q;
        wpre[q] = (h < HH) ? aw1[(size_t)(kbase + kk2) * HH + h] : 0.f;
    }
    p0 = X[rowoff[pt] + kbase + pk];
    p1 = X[rowoff[pt2] + kbase + pk2];

    for (int kc = 0; kc < 96; kc += 16) {
        #pragma unroll
        for (int q = 0; q < 10; q++) {
            int h = hb2 + 16 * q;
            if (h < 160) wst[kk2 * HS + h] = wpre[q];
        }
        pst[pk * 36 + pt] = p0;
        pst[pk2 * 36 + pt2] = p1;
        __syncthreads();
        if (kc + 16 < 96) {
            int k0 = kbase + kc + 16;
            #pragma unroll
            for (int q = 0; q < 10; q++) {
                int h = hb2 + 16 * q;
                wpre[q] = (h < HH) ? aw1[(size_t)(k0 + kk2) * HH + h] : 0.f;
            }
            p0 = X[rowoff[pt] + k0 + pk];
            p1 = X[rowoff[pt2] + k0 + pk2];
        }
        #pragma unroll
        for (int kk = 0; kk < 16; kk++) {
            float4 p = *(const float4*)&pst[kk * 36 + 4 * jg];
            const float* wr = &wst[kk * HS + h0];
            float w0 = wr[0], w1 = wr[1], w2 = wr[2], w3 = wr[3], w4 = wr[4];
            acc[0][0] += p.x * w0; acc[0][1] += p.x * w1; acc[0][2] += p.x * w2;
            acc[0][3] += p.x * w3; acc[0][4] += p.x * w4;
            acc[1][0] += p.y * w0; acc[1][1] += p.y * w1; acc[1][2] += p.y * w2;
            acc[1][3] += p.y * w3; acc[1][4] += p.y * w4;
            acc[2][0] += p.z * w0; acc[2][1] += p.z * w1; acc[2][2] += p.z * w2;
            acc[2][3] += p.z * w3; acc[2][4] += p.z * w4;
            acc[3][0] += p.w * w0; acc[3][1] += p.w * w1; acc[3][2] += p.w * w2;
            acc[3][3] += p.w * w3; acc[3][4] += p.w * w4;
        }
        __syncthreads();
    }
    #pragma unroll
    for (int jj = 0; jj < 4; jj++) {
        int t = 4 * jg + jj;
        float* op = d_ap + ((size_t)ks * NROW + r0 + t) * 160;
        #pragma unroll
        for (int q = 0; q < 5; q++) op[h0 + q] = acc[jj][q];
    }
}

// ---------------------------------------------------------------------------
__global__ void __launch_bounds__(256) k_attn2(
    const float* __restrict__ ab1, const float* __restrict__ aw2,
    const float* __restrict__ ab2, const float* __restrict__ aw3,
    const float* __restrict__ ab3)
{
    int r0 = blockIdx.x * 32;
    int tid = threadIdx.x;
    int jg = tid >> 5, hg = tid & 31;
    int h0 = 5 * hg;
    int kk2 = tid >> 4, hb2 = tid & 15;

    __shared__ __align__(16) float s1[32 * HS];
    __shared__ __align__(16) float ews[16 * HS];
    __shared__ __align__(16) float eps[16 * 36];

    for (int idx = tid; idx < 32 * 160; idx += 256) {
        int t = idx / 160, h = idx - (idx / 160) * 160;
        float v = 0.f;
        if (h < HH) {
            float s = ab1[h];
            #pragma unroll
            for (int ks = 0; ks < 8; ks++)
                s += d_ap[((size_t)ks * NROW + r0 + t) * 160 + h];
            v = fmaxf(s, 0.f);
        }
        s1[t * HS + h] = v;
    }

    float acc2[4][5];
    #pragma unroll
    for (int jj = 0; jj < 4; jj++)
        #pragma unroll
        for (int q = 0; q < 5; q++) {
            int h = h0 + q;
            acc2[jj][q] = (h < HH) ? ab2[h] : 0.f;
        }
    for (int k0 = 0; k0 < 160; k0 += 16) {
        __syncthreads();
        #pragma unroll
        for (int q = 0; q < 10; q++) {
            int h = hb2 + 16 * q;
            if (h < 160) {
                float v = 0.f;
                if ((k0 + kk2) < HH && h < HH) v = aw2[(k0 + kk2) * HH + h];
                ews[kk2 * HS + h] = v;
            }
        }
        #pragma unroll
        for (int r = 0; r < 2; r++) {
            int idx = tid + 256 * r;
            int t = idx >> 4, kk = idx & 15;
            eps[kk * 36 + t] = s1[t * HS + k0 + kk];
        }
        __syncthreads();
        #pragma unroll
        for (int kk = 0; kk < 16; kk++) {
            float4 p = *(const float4*)&eps[kk * 36 + 4 * jg];
            const float* wr = &ews[kk * HS + h0];
            float w0 = wr[0], w1 = wr[1], w2 = wr[2], w3 = wr[3], w4 = wr[4];
            acc2[0][0] += p.x * w0; acc2[0][1] += p.x * w1; acc2[0][2] += p.x * w2;
            acc2[0][3] += p.x * w3; acc2[0][4] += p.x * w4;
            acc2[1][0] += p.y * w0; acc2[1][1] += p.y * w1; acc2[1][2] += p.y * w2;
            acc2[1][3] += p.y * w3; acc2[1][4] += p.y * w4;
            acc2[2][0] += p.z * w0; acc2[2][1] += p.z * w1; acc2[2][2] += p.z * w2;
            acc2[2][3] += p.z * w3; acc2[2][4] += p.z * w4;
            acc2[3][0] += p.w * w0; acc2[3][1] += p.w * w1; acc2[3][2] += p.w * w2;
            acc2[3][3] += p.w * w3; acc2[3][4] += p.w * w4;
        }
    }
    float part[4];
    #pragma unroll
    for (int jj = 0; jj < 4; jj++) {
        float s = 0.f;
        #pragma unroll
        for (int q = 0; q < 5; q++) {
            int h = h0 + q;
            if (h < HH) s += fmaxf(acc2[jj][q], 0.f) * aw3[h];
        }
        part[jj] = s;
    }
    #pragma unroll
    for (int jj = 0; jj < 4; jj++)
        #pragma unroll
        for (int off = 16; off > 0; off >>= 1)
            part[jj] += __shfl_xor_sync(0xffffffffu, part[jj], off);
    if (hg == 0) {
        #pragma unroll
        for (int jj = 0; jj < 4; jj++)
            d_at[r0 + 4 * jg + jj] = part[jj] + ab3[0];
    }
}

// ---------------------------------------------------------------------------
__global__ void __launch_bounds__(256) k_gather(const float* __restrict__ X)
{
    int si = blockIdx.x;
    int b = si / SS;
    int st = d_starts[si];
    int tid = threadIdx.x;
    __shared__ float atv[8];
    if (tid < 8) atv[tid] = d_at[si * 8 + tid];
    __syncthreads();

    const float* Xb = X + ((size_t)b * TT + st) * EE;
    float* gp = d_g + (size_t)si * E3;
    for (int e = tid; e < EE; e += 256) {
        float s = 0.f;
        float x0 = 0.f, x7 = 0.f;
        #pragma unroll
        for (int w = 0; w < WW; w++) {
            float xv = Xb[w * EE + e];
            if (w == 0) x0 = xv;
            if (w == 7) x7 = xv;
            s += xv * atv[w];
        }
        gp[e]          = x0;
        gp[EE + e]     = x7;
        gp[2 * EE + e] = s;
    }
}

// ---------------------------------------------------------------------------
__global__ void __launch_bounds__(256) k_terms(
    const float* __restrict__ pw1, const float* __restrict__ mw1)
{
    int x = blockIdx.x;
    int sc  = x % 6;
    int mat = (x / 6) % 3;
    int ks  = x / 18;
    const float* Wm = (mat == 0) ? pw1 : (mat == 1 ? pw1 + (size_t)E3 * HH : mw1);
    int s0 = sc * 32;
    int kbase = ks * 144;
    int tid = threadIdx.x;
    int jg = tid >> 5;
    int hg = tid & 31;
    int h0 = 5 * hg;
    int kk2 = tid >> 4;
    int hb2 = tid & 15;

    __shared__ __align__(16) float wst[16 * HS];
    __shared__ __align__(16) float pst[16 * 36];

    float acc[4][5];
    #pragma unroll
    for (int jj = 0; jj < 4; jj++)
        #pragma unroll
        for (int q = 0; q < 5; q++) acc[jj][q] = 0.f;

    for (int kc = 0; kc < 144; kc += 16) {
        int k0 = kbase + kc;
        __syncthreads();
        #pragma unroll
        for (int q = 0; q < 10; q++) {
            int h = hb2 + 16 * q;
            if (h < 160)
                wst[kk2 * HS + h] = (h < HH) ? Wm[(size_t)(k0 + kk2) * HH + h] : 0.f;
        }
        #pragma unroll
        for (int r = 0; r < 2; r++) {
            int idx = tid + 256 * r;
            int t = idx >> 4, kk = idx & 15;
            pst[kk * 36 + t] = d_g[(size_t)(s0 + t) * E3 + k0 + kk];
        }
        __syncthreads();
        #pragma unroll
        for (int kk = 0; kk < 16; kk++) {
            float4 p = *(const float4*)&pst[kk * 36 + 4 * jg];
            const float* wr = &wst[kk * HS + h0];
            float w0 = wr[0], w1 = wr[1], w2 = wr[2], w3 = wr[3], w4 = wr[4];
            acc[0][0] += p.x * w0; acc[0][1] += p.x * w1; acc[0][2] += p.x * w2;
            acc[0][3] += p.x * w3; acc[0][4] += p.x * w4;
            acc[1][0] += p.y * w0; acc[1][1] += p.y * w1; acc[1][2] += p.y * w2;
            acc[1][3] += p.y * w3; acc[1][4] += p.y * w4;
            acc[2][0] += p.z * w0; acc[2][1] += p.z * w1; acc[2][2] += p.z * w2;
            acc[2][3] += p.z * w3; acc[2][4] += p.z * w4;
            acc[3][0] += p.w * w0; acc[3][1] += p.w * w1; acc[3][2] += p.w * w2;
            acc[3][3] += p.w * w3; acc[3][4] += p.w * w4;
        }
    }
    #pragma unroll
    for (int jj = 0; jj < 4; jj++) {
        int t = 4 * jg + jj;
        float* op = d_part + (((size_t)mat * 16 + ks) * NSPAN + s0 + t) * HH;
        #pragma unroll
        for (int q = 0; q < 5; q++) {
            int h = h0 + q;
            if (h < HH) op[h] = acc[jj][q];
        }
    }
}

// ---------------------------------------------------------------------------
__global__ void k_reduce() {
    int i = blockIdx.x * blockDim.x + threadIdx.x;
    if (i >= NSPAN * HH) return;
    #pragma unroll
    for (int mat = 0; mat < 3; mat++) {
        float s = 0.f;
        #pragma unroll
        for (int ks = 0; ks < 16; ks++)
            s += d_part[((size_t)mat * 16 + ks) * (NSPAN * HH) + i];
        if (mat == 0)      d_A[i]  = s;
        else if (mat == 1) d_Bt[i] = s;
        else               d_m1[i] = s;
    }
}

// ---------------------------------------------------------------------------
__global__ void __launch_bounds__(160) k_ment(
    const float* __restrict__ mb1, const float* __restrict__ mw2,
    const float* __restrict__ mb2, const float* __restrict__ mw3,
    const float* __restrict__ mb3)
{
    int s = blockIdx.x;
    int tid = threadIdx.x;
    __shared__ float s1[HH];
    __shared__ float warpsum[8];

    if (tid < HH) s1[tid] = fmaxf(d_m1[s * HH + tid] + mb1[tid], 0.f);
    __syncthreads();
    float p = 0.f;
    if (tid < HH) {
        float v = mb2[tid];
        for (int k = 0; k < HH; k++) v += s1[k] * mw2[k * HH + tid];
        p = fmaxf(v, 0.f) * mw3[tid];
    }
    #pragma unroll
    for (int o = 16; o > 0; o >>= 1) p += __shfl_down_sync(0xffffffffu, p, o);
    if ((tid & 31) == 0) warpsum[tid >> 5] = p;
    __syncthreads();
    if (tid == 0) {
        float t = mb3[0];
        for (int w = 0; w < 5; w++) t += warpsum[w];
        d_ms[s] = t;
    }
}

// ---------------------------------------------------------------------------
// k_gemm helpers
// ---------------------------------------------------------------------------
__device__ __forceinline__ void lda_regs(const float* gi, const float* gj,
                                         int ch, float* gir, float* gjr) {
    const float4* a4 = (const float4*)(gi + ch * 32);
    const float4* b4 = (const float4*)(gj + ch * 32);
    #pragma unroll
    for (int u = 0; u < 4; u++) {
        float4 a = a4[u], b = b4[u];
        gir[4*u+0] = a.x; gir[4*u+1] = a.y; gir[4*u+2] = a.z; gir[4*u+3] = a.w;
        gjr[4*u+0] = b.x; gjr[4*u+1] = b.y; gjr[4*u+2] = b.z; gjr[4*u+3] = b.w;
    }
}

__device__ __forceinline__ void sta_smem(char* dst, int aoff,
                                         const float* gir, const float* gjr) {
    unsigned short us[48];
    #pragma unroll
    for (int k = 0; k < 16; k++) {
        float p = gir[k] * gjr[k];
        unsigned short hu;
        asm("cvt.rn.bf16.f32 %0, %1;" : "=h"(hu) : "f"(p));
        float hf = __uint_as_float(((uint32_t)hu) << 16);
        float l = p - hf;
        unsigned short lu;
        asm("cvt.rn.bf16.f32 %0, %1;" : "=h"(lu) : "f"(l));
        us[3*k+0] = hu; us[3*k+1] = hu; us[3*k+2] = lu;
    }
    uint32_t u[24];
    #pragma unroll
    for (int j = 0; j < 24; j++)
        u[j] = (uint32_t)us[2*j] | ((uint32_t)us[2*j+1] << 16);
    uint4* d = (uint4*)(dst + aoff);
    d[0] = make_uint4(u[0],  u[1],  u[2],  u[3]);
    d[1] = make_uint4(u[4],  u[5],  u[6],  u[7]);
    d[2] = make_uint4(u[8],  u[9],  u[10], u[11]);
    d[3] = make_uint4(u[12], u[13], u[14], u[15]);
    d[4] = make_uint4(u[16], u[17], u[18], u[19]);
    d[5] = make_uint4(u[20], u[21], u[22], u[23]);
}

__device__ __forceinline__ void cpw_chunk(uint32_t wdst, int wkoff, int ch, int tid) {
    #pragma unroll
    for (int v = 0; v < 2; v++) {
        int unit = tid + 256 * v;
        if (unit < 320) {
            int n = unit >> 1, kh = unit & 1;
            const char* src = (const char*)d_Wi + (size_t)n * (KPR * 2)
                              + wkoff + ch * 192 + kh * 96;
            uint32_t dst = wdst + n * 208 + kh * 96;
            #pragma unroll
            for (int q = 0; q < 6; q++)
                CP_ASYNC16(dst + q * 16, src + q * 16);
        }
    }
}

// ---------------------------------------------------------------------------
// k_gemm: mma.sync bf16 split-interleaved. Warp layout: 4 m-groups (2 m16
// tiles each) x 2 n-halves (10 n8 tiles) -> 8/20 A/B LDS per s-step.
// ---------------------------------------------------------------------------
__global__ void __launch_bounds__(256) k_gemm()
{
    extern __shared__ __align__(16) char smg[];
    char* Ab[2] = { smg, smg + ABUF };
    char* Wb[2] = { smg + 2 * ABUF, smg + 2 * ABUF + WBUF };
    uint32_t Wbu[2] = { smem_u32(Wb[0]), smem_u32(Wb[1]) };

    int tid = threadIdx.x, wid = tid >> 5, lane = tid & 31;
    int g = lane >> 2, tg = lane & 3;
    int wm = wid & 3, wn = wid >> 2;      // m-group, n-half
    int mt = blockIdx.x >> 1, ksp = blockIdx.x & 1;
    int m0 = mt * 128;
    int wkoff = ksp * 3456 * 2;

    int arow = tid >> 1, akh = tid & 1;
    const float* gi = d_g + (size_t)d_pi[m0 + arow] * E3 + ksp * 1152 + akh * 16;
    const float* gj = d_g + (size_t)d_pj[m0 + arow] * E3 + ksp * 1152 + akh * 16;
    int aoff = arow * 208 + akh * 96;

    float c[2][10][4];
    #pragma unroll
    for (int m2 = 0; m2 < 2; m2++)
        #pragma unroll
        for (int t = 0; t < 10; t++)
            #pragma unroll
            for (int q = 0; q < 4; q++) c[m2][t][q] = 0.f;

    float gir[16], gjr[16];

    cpw_chunk(Wbu[0], wkoff, 0, tid);
    CP_COMMIT();
    lda_regs(gi, gj, 0, gir, gjr);
    sta_smem(Ab[0], aoff, gir, gjr);
    CP_WAIT0();
    __syncthreads();

    for (int ch = 0; ch < NCHA2; ch++) {
        int buf = ch & 1, nb = buf ^ 1;
        bool more = (ch + 1 < NCHA2);
        if (more) {
            cpw_chunk(Wbu[nb], wkoff, ch + 1, tid);
            CP_COMMIT();
            lda_regs(gi, gj, ch + 1, gir, gjr);
        }
        const char* A = Ab[buf];
        const char* W = Wb[buf];
        #pragma unroll
        for (int s = 0; s < 6; s++) {
            uint32_t a[2][4];
            #pragma unroll
            for (int m2 = 0; m2 < 2; m2++) {
                int r0 = (wm * 32 + m2 * 16 + g) * 208 + s * 32 + tg * 4;
                a[m2][0] = *(const uint32_t*)(A + r0);
                a[m2][1] = *(const uint32_t*)(A + r0 + 8 * 208);
                a[m2][2] = *(const uint32_t*)(A + r0 + 16);
                a[m2][3] = *(const uint32_t*)(A + r0 + 8 * 208 + 16);
            }
            #pragma unroll
            for (int t = 0; t < 10; t++) {
                int wo = (wn * 80 + 8 * t + g) * 208 + s * 32 + tg * 4;
                uint32_t b0 = *(const uint32_t*)(W + wo);
                uint32_t b1 = *(const uint32_t*)(W + wo + 16);
                mma16816(c[0][t], a[0][0], a[0][1], a[0][2], a[0][3], b0, b1);
                mma16816(c[1][t], a[1][0], a[1][1], a[1][2], a[1][3], b0, b1);
            }
        }
        if (more) sta_smem(Ab[nb], aoff, gir, gjr);
        CP_WAIT0();
        __syncthreads();
    }

    float* Cd = d_Cg2[ksp];
    #pragma unroll
    for (int m2 = 0; m2 < 2; m2++) {
        int rowa = m0 + wm * 32 + m2 * 16 + g;
        #pragma unroll
        for (int t = 0; t < 10; t++) {
            int col = wn * 80 + 8 * t + tg * 2;
            *(float2*)&Cd[(size_t)rowa * 160 + col] = make_float2(c[m2][t][0], c[m2][t][1]);
            *(float2*)&Cd[(size_t)(rowa + 8) * 160 + col] = make_float2(c[m2][t][2], c[m2][t][3]);
        }
    }
}

// ---------------------------------------------------------------------------
// k_pairE: merged dual epilogue — 64 ordered rows, one layer-2 pass.
// ---------------------------------------------------------------------------
__global__ void __launch_bounds__(256) k_pairE(
    const float* __restrict__ pb1, const float* __restrict__ pw2,
    const float* __restrict__ pb2, const float* __restrict__ pw3,
    const float* __restrict__ pb3, float* __restrict__ out)
{
    extern __shared__ __align__(16) float smE[];
    float* s1  = smE;                    // 64*HS
    float* ews = smE + 64 * HS;          // 16*HS
    float* eps = ews + 16 * HS;          // 16*68
    __shared__ int pis[32], pjs[32];

    int r0 = blockIdx.x * 32;
    int tid = threadIdx.x;
    int jg = tid >> 5;
    int hg = tid & 31;
    int h0 = 5 * hg;
    int kk2 = tid >> 4, hb2 = tid & 15;

    if (tid < 32) { pis[tid] = d_pi[r0 + tid]; pjs[tid] = d_pj[r0 + tid]; }
    __syncthreads();

    // ---- layer-1 for both orderings -> s1[0:32] fwd, s1[32:64] trans ----
    #pragma unroll
    for (int jj = 0; jj < 4; jj++) {
        int t = 4 * jg + jj;
        int r = r0 + t;
        int pi = pis[t], pj = pjs[t];
        #pragma unroll
        for (int q = 0; q < 5; q++) {
            int h = h0 + q;
            float vf = 0.f, vt = 0.f;
            if (h < HH) {
                size_t idx = (size_t)r * 160 + h;
                float cc = d_Cg2[0][idx] + d_Cg2[1][idx] + pb1[h];
                vf = fmaxf(cc + d_A[pi * HH + h] + d_Bt[pj * HH + h], 0.f);
                vt = fmaxf(cc + d_A[pj * HH + h] + d_Bt[pi * HH + h], 0.f);
            }
            s1[t * HS + h] = vf;
            s1[(32 + t) * HS + h] = vt;
        }
    }

    // ---- layer-2: 64 rows x 150 h; warp jg owns rows 8jg..8jg+7 ----
    float acc2[8][5];
    #pragma unroll
    for (int rr = 0; rr < 8; rr++)
        #pragma unroll
        for (int q = 0; q < 5; q++) {
            int h = h0 + q;
            acc2[rr][q] = (h < HH) ? pb2[h] : 0.f;
        }
    for (int k0 = 0; k0 < 160; k0 += 16) {
        __syncthreads();
        #pragma unroll
        for (int q = 0; q < 10; q++) {
            int h = hb2 + 16 * q;
            if (h < 160) {
                float v = 0.f;
                if ((k0 + kk2) < HH && h < HH) v = pw2[(k0 + kk2) * HH + h];
                ews[kk2 * HS + h] = v;
            }
        }
        #pragma unroll
        for (int r = 0; r < 4; r++) {
            int idx = tid + 256 * r;
            int t = idx >> 4, kk = idx & 15;
            eps[kk * 68 + t] = s1[t * HS + k0 + kk];
        }
        __syncthreads();
        #pragma unroll
        for (int kk = 0; kk < 16; kk++) {
            float4 p0 = *(const float4*)&eps[kk * 68 + 8 * jg];
            float4 p1 = *(const float4*)&eps[kk * 68 + 8 * jg + 4];
            const float* wr = &ews[kk * HS + h0];
            float w0 = wr[0], w1 = wr[1], w2 = wr[2], w3 = wr[3], w4 = wr[4];
            acc2[0][0] += p0.x * w0; acc2[0][1] += p0.x * w1; acc2[0][2] += p0.x * w2;
            acc2[0][3] += p0.x * w3; acc2[0][4] += p0.x * w4;
            acc2[1][0] += p0.y * w0; acc2[1][1] += p0.y * w1; acc2[1][2] += p0.y * w2;
            acc2[1][3] += p0.y * w3; acc2[1][4] += p0.y * w4;
            acc2[2][0] += p0.z * w0; acc2[2][1] += p0.z * w1; acc2[2][2] += p0.z * w2;
            acc2[2][3] += p0.z * w3; acc2[2][4] += p0.z * w4;
            acc2[3][0] += p0.w * w0; acc2[3][1] += p0.w * w1; acc2[3][2] += p0.w * w2;
            acc2[3][3] += p0.w * w3; acc2[3][4] += p0.w * w4;
            acc2[4][0] += p1.x * w0; acc2[4][1] += p1.x * w1; acc2[4][2] += p1.x * w2;
            acc2[4][3] += p1.x * w3; acc2[4][4] += p1.x * w4;
            acc2[5][0] += p1.y * w0; acc2[5][1] += p1.y * w1; acc2[5][2] += p1.y * w2;
            acc2[5][3] += p1.y * w3; acc2[5][4] += p1.y * w4;
            acc2[6][0] += p1.z * w0; acc2[6][1] += p1.z * w1; acc2[6][2] += p1.z * w2;
            acc2[6][3] += p1.z * w3; acc2[6][4] += p1.z * w4;
            acc2[7][0] += p1.w * w0; acc2[7][1] += p1.w * w1; acc2[7][2] += p1.w * w2;
            acc2[7][3] += p1.w * w3; acc2[7][4] += p1.w * w4;
        }
    }

    // ---- layer-3 + combine + clip ----
    float part[8];
    #pragma unroll
    for (int rr = 0; rr < 8; rr++) {
        float s = 0.f;
        #pragma unroll
        for (int q = 0; q < 5; q++) {
            int h = h0 + q;
            if (h < HH) s += fmaxf(acc2[rr][q], 0.f) * pw3[h];
        }
        part[rr] = s;
    }
    #pragma unroll
    for (int rr = 0; rr < 8; rr++)
        #pragma unroll
        for (int off = 16; off > 0; off >>= 1)
            part[rr] += __shfl_xor_sync(0xffffffffu, part[rr], off);
    if (hg == 0) {
        #pragma unroll
        for (int rr = 0; rr < 8; rr++) {
            int row = 8 * jg + rr;
            int t = row & 31;
            int fi, se;
            if (row < 32) { fi = pis[t]; se = pjs[t]; }
            else          { fi = pjs[t]; se = pis[t]; }
            float sc = part[rr] + pb3[0];
            float v = ((d_ms[fi] + d_ms[se]) + sc) * (1.f / 3.f);
            v = fminf(fmaxf(v, 0.f), 1.f);
            out[(size_t)fi * SS + (se % SS)] = v;
        }
    }
}

// ---------------------------------------------------------------------------
extern "C" void kernel_launch(void* const* d_in, const int* in_sizes, int n_in,
                              void* d_out, int out_size)
{
    const float* X   = (const float*)d_in[0];
    const void*  sp  = d_in[1];
    const float* aw1 = (const float*)d_in[2];
    const float* ab1 = (const float*)d_in[3];
    const float* aw2 = (const float*)d_in[4];
    const float* ab2 = (const float*)d_in[5];
    const float* aw3 = (const float*)d_in[6];
    const float* ab3 = (const float*)d_in[7];
    const float* mw1 = (const float*)d_in[8];
    const float* mb1 = (const float*)d_in[9];
    const float* mw2 = (const float*)d_in[10];
    const float* mb2 = (const float*)d_in[11];
    const float* mw3 = (const float*)d_in[12];
    const float* mb3 = (const float*)d_in[13];
    const float* pw1 = (const float*)d_in[14];
    const float* pb1 = (const float*)d_in[15];
    const float* pw2 = (const float*)d_in[16];
    const float* pb2 = (const float*)d_in[17];
    const float* pw3 = (const float*)d_in[18];
    const float* pb3 = (const float*)d_in[19];
    float* out = (float*)d_out;

    cudaFuncSetAttribute(k_gemm, cudaFuncAttributeMaxDynamicSharedMemorySize,
                         SMEMG);
    cudaFuncSetAttribute(k_pairE, cudaFuncAttributeMaxDynamicSharedMemorySize,
                         SMEMPE);

    k_init<<<1, 192>>>(sp);
    k_plist<<<72, 256>>>();
    k_wprep<<<(160 * KPR + 255) / 256, 256>>>(pw1);
    k_attn1<<<384, 256>>>(X, aw1);
    k_attn2<<<48, 256>>>(ab1, aw2, ab2, aw3, ab3);
    k_gather<<<NSPAN, 256>>>(X);
    k_terms<<<288, 256>>>(pw1, mw1);
    k_reduce<<<(NSPAN * HH + 255) / 256, 256>>>();
    k_ment<<<NSPAN, 160>>>(mb1, mw2, mb2, mw3, mb3);
    k_gemm<<<146, 256, SMEMG>>>();
    k_pairE<<<NPAIR / 32, 256, SMEMPE>>>(pb1, pw2, pb2, pw3, pb3, out);
}

// round 10
// speedup vs baseline: 5.8007x; 1.0363x over previous
#include <cuda_runtime.h>
#include <cuda_bf16.h>
#include <cstdint>

#define BB 2
#define TT 2048
#define EE 768
#define SS 96
#define HH 150
#define HS 168
#define WW 8
#define E3 2304
#define NSPAN (BB*SS)      // 192
#define NROW (NSPAN*WW)    // 1536
#define NPAIR 9312
#define NPAIRP 9344        // 73*128
#define KPR 6912           // 3*E3 interleaved split K (pair GEMM)
#define KA 2304            // 3*768 interleaved split K (attn GEMM)
#define K2 480             // 3*150 interleaved split K (layer-2), padded 450->480
#define NCHA2 36
#define ABUF 26624         // 128 rows * 208 B
#define WBUF 33280         // 160 rows * 208 B
#define SMEMG (2*ABUF + 2*WBUF)        // 119808
#define A2RS 976           // pairE A' row stride bytes (488 shorts)
#define A2BYTES (64*A2RS)              // 62464
#define W2CB 12800         // 160 rows * 80 B per chunk buffer
#define SMEMPE (A2BYTES + 2*W2CB)      // 88064

// -------- device scratch --------
__device__ int   d_starts[NSPAN];
__device__ __align__(16) float d_g[NSPAN * E3];
__device__ float d_part[3 * 16 * NSPAN * HH];
__device__ float d_ap[4 * NROW * 160];
__device__ float d_A[NSPAN * HH];
__device__ float d_Bt[NSPAN * HH];
__device__ float d_m1[NSPAN * HH];
__device__ float d_ms[NSPAN];
__device__ int   d_pi[NPAIRP], d_pj[NPAIRP];
__device__ __align__(16) __nv_bfloat16 d_Wi[160 * KPR];
__device__ __align__(16) __nv_bfloat16 d_AWi[160 * KA];
__device__ __align__(16) __nv_bfloat16 d_W2i[160 * K2];
__device__ float d_Cg2[2][(size_t)NPAIRP * 160];

// -------- generic-PTX helpers --------
__device__ __forceinline__ uint32_t smem_u32(const void* p) {
    uint32_t a;
    asm("{ .reg .u64 t; cvta.to.shared.u64 t, %1; cvt.u32.u64 %0, t; }"
        : "=r"(a) : "l"(p));
    return a;
}
#define CP_ASYNC16(dst, src) \
    asm volatile("cp.async.cg.shared.global [%0], [%1], 16;" \
                 :: "r"(dst), "l"(src) : "memory")
#define CP_COMMIT() asm volatile("cp.async.commit_group;" ::: "memory")
#define CP_WAIT0()  asm volatile("cp.async.wait_group 0;" ::: "memory")

__device__ __forceinline__ void mma16816(float c[4], uint32_t a0, uint32_t a1,
                                         uint32_t a2, uint32_t a3,
                                         uint32_t b0, uint32_t b1) {
    asm volatile(
        "mma.sync.aligned.m16n8k16.row.col.f32.bf16.bf16.f32 "
        "{%0,%1,%2,%3}, {%4,%5,%6,%7}, {%8,%9}, {%0,%1,%2,%3};"
        : "+f"(c[0]), "+f"(c[1]), "+f"(c[2]), "+f"(c[3])
        : "r"(a0), "r"(a1), "r"(a2), "r"(a3), "r"(b0), "r"(b1));
}

__device__ __forceinline__ void split_bf16(float p, unsigned short& hu,
                                           unsigned short& lu) {
    asm("cvt.rn.bf16.f32 %0, %1;" : "=h"(hu) : "f"(p));
    float hf = __uint_as_float(((uint32_t)hu) << 16);
    float l = p - hf;
    asm("cvt.rn.bf16.f32 %0, %1;" : "=h"(lu) : "f"(l));
}

// ---------------------------------------------------------------------------
// k_prep0: pair list (blocks 0..71) + span_starts conversion (block 72)
// ---------------------------------------------------------------------------
__global__ void k_prep0(const void* sp) {
    if (blockIdx.x == 72) {
        __shared__ int is64;
        if (threadIdx.x == 0) {
            const int* w32 = (const int*)sp;
            int z = 1;
            for (int i = 1; i < 64; i += 2) if (w32[i] != 0) { z = 0; break; }
            is64 = z;
        }
        __syncthreads();
        int i = threadIdx.x;
        if (i < NSPAN) {
            if (is64) d_starts[i] = (int)((const long long*)sp)[i];
            else      d_starts[i] = ((const int*)sp)[i];
        }
        return;
    }
    int idx = blockIdx.x * 256 + threadIdx.x;
    int b = idx / (SS * SS), r = idx % (SS * SS);
    int i = r / SS, j = r % SS;
    if (j >= i) {
        int row = b * 4656 + i * SS - i * (i - 1) / 2 + (j - i);
        d_pi[row] = b * SS + i;
        d_pj[row] = b * SS + j;
    }
    if (idx < NPAIRP - NPAIR) {
        d_pi[NPAIR + idx] = NSPAN - 1;
        d_pj[NPAIR + idx] = NSPAN - 1;
    }
}

// ---------------------------------------------------------------------------
// k_wprep: interleaved bf16 splits of Wc (pw1 block C), aw1, pw2.
// pattern per original k: [hi, lo, hi] for W  (A side uses [hi, hi, lo])
// ---------------------------------------------------------------------------
__global__ void k_wprep(const float* __restrict__ pw1,
                        const float* __restrict__ aw1,
                        const float* __restrict__ pw2) {
    int idx = blockIdx.x * blockDim.x + threadIdx.x;
    const int S0 = 160 * KPR, S1 = 160 * KA, S2 = 160 * K2;
    if (idx >= S0 + S1 + S2) return;
    float w = 0.f;
    unsigned short* dst;
    int r;
    if (idx < S0) {
        int n = idx / KPR, kp = idx % KPR;
        int k = kp / 3; r = kp - 3 * k;
        if (n < HH) w = pw1[(size_t)2 * E3 * HH + (size_t)k * HH + n];
        dst = (unsigned short*)d_Wi + idx;
    } else if (idx < S0 + S1) {
        int i2 = idx - S0;
        int n = i2 / KA, kp = i2 % KA;
        int k = kp / 3; r = kp - 3 * k;
        if (n < HH) w = aw1[(size_t)k * HH + n];
        dst = (unsigned short*)d_AWi + i2;
    } else {
        int i3 = idx - S0 - S1;
        int n = i3 / K2, kp = i3 % K2;
        int k = kp / 3; r = kp - 3 * k;
        if (n < HH && kp < 450) w = pw2[(size_t)k * HH + n];
        dst = (unsigned short*)d_W2i + i3;
    }
    unsigned short hu, lu;
    split_bf16(w, hu, lu);
    *dst = (r == 1) ? lu : hu;
}

// ---------------------------------------------------------------------------
// shared staging helpers for the mma GEMM template
// ---------------------------------------------------------------------------
__device__ __forceinline__ void cpw_generic(uint32_t wdst, const char* srcbase,
                                            size_t rstride, int choff, int tid) {
    #pragma unroll
    for (int v = 0; v < 2; v++) {
        int unit = tid + 256 * v;
        if (unit < 320) {
            int n = unit >> 1, kh = unit & 1;
            const char* src = srcbase + (size_t)n * rstride + choff + kh * 96;
            uint32_t dst = wdst + n * 208 + kh * 96;
            #pragma unroll
            for (int q = 0; q < 6; q++)
                CP_ASYNC16(dst + q * 16, src + q * 16);
        }
    }
}

__device__ __forceinline__ void pack_store(char* dst, int aoff,
                                           const float* pv) {
    unsigned short us[48];
    #pragma unroll
    for (int k = 0; k < 16; k++) {
        unsigned short hu, lu;
        split_bf16(pv[k], hu, lu);
        us[3*k+0] = hu; us[3*k+1] = hu; us[3*k+2] = lu;
    }
    uint32_t u[24];
    #pragma unroll
    for (int j = 0; j < 24; j++)
        u[j] = (uint32_t)us[2*j] | ((uint32_t)us[2*j+1] << 16);
    uint4* d = (uint4*)(dst + aoff);
    d[0] = make_uint4(u[0],  u[1],  u[2],  u[3]);
    d[1] = make_uint4(u[4],  u[5],  u[6],  u[7]);
    d[2] = make_uint4(u[8],  u[9],  u[10], u[11]);
    d[3] = make_uint4(u[12], u[13], u[14], u[15]);
    d[4] = make_uint4(u[16], u[17], u[18], u[19]);
    d[5] = make_uint4(u[20], u[21], u[22], u[23]);
}

// ---------------------------------------------------------------------------
// k_attn1g: attn layer-1 via mma.sync. M=1536 (12 tiles), Ksplit=4.
// grid = 48.  out: d_ap[ksp][row][160]
// ---------------------------------------------------------------------------
__global__ void __launch_bounds__(256) k_attn1g(const float* __restrict__ X)
{
    extern __shared__ __align__(16) char smg[];
    char* Ab[2] = { smg, smg + ABUF };
    char* Wb[2] = { smg + 2 * ABUF, smg + 2 * ABUF + WBUF };
    uint32_t Wbu[2] = { smem_u32(Wb[0]), smem_u32(Wb[1]) };

    int tid = threadIdx.x, wid = tid >> 5, lane = tid & 31;
    int g = lane >> 2, tg = lane & 3;
    int wm = wid & 3, wn = wid >> 2;
    int mt = blockIdx.x >> 2, ksp = blockIdx.x & 3;
    int m0 = mt * 128;
    int wkoff = ksp * 1152;               // 576 k' * 2 bytes

    int arow = tid >> 1, akh = tid & 1;
    int grow = m0 + arow;
    int si = grow >> 3, w = grow & 7;
    int b = si / SS;
    const float* Xp = X + ((size_t)(b * TT + d_starts[si] + w)) * EE
                        + ksp * 192 + akh * 16;
    int aoff = arow * 208 + akh * 96;

    float c[2][10][4];
    #pragma unroll
    for (int m2 = 0; m2 < 2; m2++)
        #pragma unroll
        for (int t = 0; t < 10; t++)
            #pragma unroll
            for (int q = 0; q < 4; q++) c[m2][t][q] = 0.f;

    float xr[16];
    cpw_generic(Wbu[0], (const char*)d_AWi, KA * 2, wkoff, tid);
    CP_COMMIT();
    {
        const float4* x4 = (const float4*)Xp;
        #pragma unroll
        for (int u = 0; u < 4; u++) {
            float4 a = x4[u];
            xr[4*u] = a.x; xr[4*u+1] = a.y; xr[4*u+2] = a.z; xr[4*u+3] = a.w;
        }
    }
    pack_store(Ab[0], aoff, xr);
    CP_WAIT0();
    __syncthreads();

    for (int ch = 0; ch < 6; ch++) {
        int buf = ch & 1, nb = buf ^ 1;
        bool more = (ch + 1 < 6);
        if (more) {
            cpw_generic(Wbu[nb], (const char*)d_AWi, KA * 2,
                        wkoff + (ch + 1) * 192, tid);
            CP_COMMIT();
            const float4* x4 = (const float4*)(Xp + (ch + 1) * 32);
            #pragma unroll
            for (int u = 0; u < 4; u++) {
                float4 a = x4[u];
                xr[4*u] = a.x; xr[4*u+1] = a.y; xr[4*u+2] = a.z; xr[4*u+3] = a.w;
            }
        }
        const char* A = Ab[buf];
        const char* W = Wb[buf];
        #pragma unroll
        for (int s = 0; s < 6; s++) {
            uint32_t a[2][4];
            #pragma unroll
            for (int m2 = 0; m2 < 2; m2++) {
                int r0 = (wm * 32 + m2 * 16 + g) * 208 + s * 32 + tg * 4;
                a[m2][0] = *(const uint32_t*)(A + r0);
                a[m2][1] = *(const uint32_t*)(A + r0 + 8 * 208);
                a[m2][2] = *(const uint32_t*)(A + r0 + 16);
                a[m2][3] = *(const uint32_t*)(A + r0 + 8 * 208 + 16);
            }
            #pragma unroll
            for (int t = 0; t < 10; t++) {
                int wo = (wn * 80 + 8 * t + g) * 208 + s * 32 + tg * 4;
                uint32_t b0 = *(const uint32_t*)(W + wo);
                uint32_t b1 = *(const uint32_t*)(W + wo + 16);
                mma16816(c[0][t], a[0][0], a[0][1], a[0][2], a[0][3], b0, b1);
                mma16816(c[1][t], a[1][0], a[1][1], a[1][2], a[1][3], b0, b1);
            }
        }
        if (more) pack_store(Ab[nb], aoff, xr);
        CP_WAIT0();
        __syncthreads();
    }

    float* Cd = d_ap + (size_t)ksp * NROW * 160;
    #pragma unroll
    for (int m2 = 0; m2 < 2; m2++) {
        int rowa = m0 + wm * 32 + m2 * 16 + g;
        #pragma unroll
        for (int t = 0; t < 10; t++) {
            int col = wn * 80 + 8 * t + tg * 2;
            *(float2*)&Cd[(size_t)rowa * 160 + col] = make_float2(c[m2][t][0], c[m2][t][1]);
            *(float2*)&Cd[(size_t)(rowa + 8) * 160 + col] = make_float2(c[m2][t][2], c[m2][t][3]);
        }
    }
}

// ---------------------------------------------------------------------------
// k_attn2g: reduce 4 partials + layers 2,3 of attn MLP + gather g_i.
// 48 blocks x 32 rows (= 4 spans each).
// ---------------------------------------------------------------------------
__global__ void __launch_bounds__(256) k_attn2g(
    const float* __restrict__ X,
    const float* __restrict__ ab1, const float* __restrict__ aw2,
    const float* __restrict__ ab2, const float* __restrict__ aw3,
    const float* __restrict__ ab3)
{
    int r0 = blockIdx.x * 32;
    int tid = threadIdx.x;
    int jg = tid >> 5, hg = tid & 31;
    int h0 = 5 * hg;
    int kk2 = tid >> 4, hb2 = tid & 15;

    __shared__ __align__(16) float s1[32 * HS];
    __shared__ __align__(16) float ews[16 * HS];
    __shared__ __align__(16) float eps[16 * 36];
    __shared__ float atv[32];

    for (int idx = tid; idx < 32 * 160; idx += 256) {
        int t = idx / 160, h = idx - (idx / 160) * 160;
        float v = 0.f;
        if (h < HH) {
            float s = ab1[h];
            #pragma unroll
            for (int ks = 0; ks < 4; ks++)
                s += d_ap[((size_t)ks * NROW + r0 + t) * 160 + h];
            v = fmaxf(s, 0.f);
        }
        s1[t * HS + h] = v;
    }

    float acc2[4][5];
    #pragma unroll
    for (int jj = 0; jj < 4; jj++)
        #pragma unroll
        for (int q = 0; q < 5; q++) {
            int h = h0 + q;
            acc2[jj][q] = (h < HH) ? ab2[h] : 0.f;
        }
    for (int k0 = 0; k0 < 160; k0 += 16) {
        __syncthreads();
        #pragma unroll
        for (int q = 0; q < 10; q++) {
            int h = hb2 + 16 * q;
            if (h < 160) {
                float v = 0.f;
                if ((k0 + kk2) < HH && h < HH) v = aw2[(k0 + kk2) * HH + h];
                ews[kk2 * HS + h] = v;
            }
        }
        #pragma unroll
        for (int r = 0; r < 2; r++) {
            int idx = tid + 256 * r;
            int t = idx >> 4, kk = idx & 15;
            eps[kk * 36 + t] = s1[t * HS + k0 + kk];
        }
        __syncthreads();
        #pragma unroll
        for (int kk = 0; kk < 16; kk++) {
            float4 p = *(const float4*)&eps[kk * 36 + 4 * jg];
            const float* wr = &ews[kk * HS + h0];
            float w0 = wr[0], w1 = wr[1], w2 = wr[2], w3 = wr[3], w4 = wr[4];
            acc2[0][0] += p.x * w0; acc2[0][1] += p.x * w1; acc2[0][2] += p.x * w2;
            acc2[0][3] += p.x * w3; acc2[0][4] += p.x * w4;
            acc2[1][0] += p.y * w0; acc2[1][1] += p.y * w1; acc2[1][2] += p.y * w2;
            acc2[1][3] += p.y * w3; acc2[1][4] += p.y * w4;
            acc2[2][0] += p.z * w0; acc2[2][1] += p.z * w1; acc2[2][2] += p.z * w2;
            acc2[2][3] += p.z * w3; acc2[2][4] += p.z * w4;
            acc2[3][0] += p.w * w0; acc2[3][1] += p.w * w1; acc2[3][2] += p.w * w2;
            acc2[3][3] += p.w * w3; acc2[3][4] += p.w * w4;
        }
    }
    float part[4];
    #pragma unroll
    for (int jj = 0; jj < 4; jj++) {
        float s = 0.f;
        #pragma unroll
        for (int q = 0; q < 5; q++) {
            int h = h0 + q;
            if (h < HH) s += fmaxf(acc2[jj][q], 0.f) * aw3[h];
        }
        part[jj] = s;
    }
    #pragma unroll
    for (int jj = 0; jj < 4; jj++)
        #pragma unroll
        for (int off = 16; off > 0; off >>= 1)
            part[jj] += __shfl_xor_sync(0xffffffffu, part[jj], off);
    if (hg == 0) {
        #pragma unroll
        for (int jj = 0; jj < 4; jj++)
            atv[4 * jg + jj] = part[jj] + ab3[0];
    }
    __syncthreads();

    // ---- gather: 4 spans ----
    int sp0 = r0 >> 3;   // first span of this block
    for (int idx = tid; idx < 4 * EE; idx += 256) {
        int ls = idx / EE, e = idx - ls * EE;
        int si = sp0 + ls;
        int b = si / SS;
        const float* Xb = X + ((size_t)(b * TT + d_starts[si])) * EE;
        float s = 0.f, x0 = 0.f, x7 = 0.f;
        #pragma unroll
        for (int w = 0; w < WW; w++) {
            float xv = Xb[w * EE + e];
            if (w == 0) x0 = xv;
            if (w == 7) x7 = xv;
            s += xv * atv[ls * 8 + w];
        }
        float* gp = d_g + (size_t)si * E3;
        gp[e]          = x0;
        gp[EE + e]     = x7;
        gp[2 * EE + e] = s;
    }
}

// ---------------------------------------------------------------------------
__global__ void __launch_bounds__(256) k_terms(
    const float* __restrict__ pw1, const float* __restrict__ mw1)
{
    int x = blockIdx.x;
    int sc  = x % 6;
    int mat = (x / 6) % 3;
    int ks  = x / 18;
    const float* Wm = (mat == 0) ? pw1 : (mat == 1 ? pw1 + (size_t)E3 * HH : mw1);
    int s0 = sc * 32;
    int kbase = ks * 144;
    int tid = threadIdx.x;
    int jg = tid >> 5;
    int hg = tid & 31;
    int h0 = 5 * hg;
    int kk2 = tid >> 4;
    int hb2 = tid & 15;

    __shared__ __align__(16) float wst[16 * HS];
    __shared__ __align__(16) float pst[16 * 36];

    float acc[4][5];
    #pragma unroll
    for (int jj = 0; jj < 4; jj++)
        #pragma unroll
        for (int q = 0; q < 5; q++) acc[jj][q] = 0.f;

    for (int kc = 0; kc < 144; kc += 16) {
        int k0 = kbase + kc;
        __syncthreads();
        #pragma unroll
        for (int q = 0; q < 10; q++) {
            int h = hb2 + 16 * q;
            if (h < 160)
                wst[kk2 * HS + h] = (h < HH) ? Wm[(size_t)(k0 + kk2) * HH + h] : 0.f;
        }
        #pragma unroll
        for (int r = 0; r < 2; r++) {
            int idx = tid + 256 * r;
            int t = idx >> 4, kk = idx & 15;
            pst[kk * 36 + t] = d_g[(size_t)(s0 + t) * E3 + k0 + kk];
        }
        __syncthreads();
        #pragma unroll
        for (int kk = 0; kk < 16; kk++) {
            float4 p = *(const float4*)&pst[kk * 36 + 4 * jg];
            const float* wr = &wst[kk * HS + h0];
            float w0 = wr[0], w1 = wr[1], w2 = wr[2], w3 = wr[3], w4 = wr[4];
            acc[0][0] += p.x * w0; acc[0][1] += p.x * w1; acc[0][2] += p.x * w2;
            acc[0][3] += p.x * w3; acc[0][4] += p.x * w4;
            acc[1][0] += p.y * w0; acc[1][1] += p.y * w1; acc[1][2] += p.y * w2;
            acc[1][3] += p.y * w3; acc[1][4] += p.y * w4;
            acc[2][0] += p.z * w0; acc[2][1] += p.z * w1; acc[2][2] += p.z * w2;
            acc[2][3] += p.z * w3; acc[2][4] += p.z * w4;
            acc[3][0] += p.w * w0; acc[3][1] += p.w * w1; acc[3][2] += p.w * w2;
            acc[3][3] += p.w * w3; acc[3][4] += p.w * w4;
        }
    }
    #pragma unroll
    for (int jj = 0; jj < 4; jj++) {
        int t = 4 * jg + jj;
        float* op = d_part + (((size_t)mat * 16 + ks) * NSPAN + s0 + t) * HH;
        #pragma unroll
        for (int q = 0; q < 5; q++) {
            int h = h0 + q;
            if (h < HH) op[h] = acc[jj][q];
        }
    }
}

// ---------------------------------------------------------------------------
__global__ void k_reduce() {
    int i = blockIdx.x * blockDim.x + threadIdx.x;
    if (i >= NSPAN * HH) return;
    #pragma unroll
    for (int mat = 0; mat < 3; mat++) {
        float s = 0.f;
        #pragma unroll
        for (int ks = 0; ks < 16; ks++)
            s += d_part[((size_t)mat * 16 + ks) * (NSPAN * HH) + i];
        if (mat == 0)      d_A[i]  = s;
        else if (mat == 1) d_Bt[i] = s;
        else               d_m1[i] = s;
    }
}

// ---------------------------------------------------------------------------
__global__ void __launch_bounds__(160) k_ment(
    const float* __restrict__ mb1, const float* __restrict__ mw2,
    const float* __restrict__ mb2, const float* __restrict__ mw3,
    const float* __restrict__ mb3)
{
    int s = blockIdx.x;
    int tid = threadIdx.x;
    __shared__ float s1[HH];
    __shared__ float warpsum[8];

    if (tid < HH) s1[tid] = fmaxf(d_m1[s * HH + tid] + mb1[tid], 0.f);
    __syncthreads();
    float p = 0.f;
    if (tid < HH) {
        float v = mb2[tid];
        for (int k = 0; k < HH; k++) v += s1[k] * mw2[k * HH + tid];
        p = fmaxf(v, 0.f) * mw3[tid];
    }
    #pragma unroll
    for (int o = 16; o > 0; o >>= 1) p += __shfl_down_sync(0xffffffffu, p, o);
    if ((tid & 31) == 0) warpsum[tid >> 5] = p;
    __syncthreads();
    if (tid == 0) {
        float t = mb3[0];
        for (int w = 0; w < 5; w++) t += warpsum[w];
        d_ms[s] = t;
    }
}

// ---------------------------------------------------------------------------
// k_gemm: pair C-term via mma.sync (unchanged from R9 — validated).
// ---------------------------------------------------------------------------
__device__ __forceinline__ void lda_pair(const float* gi, const float* gj,
                                         int ch, float* pv) {
    const float4* a4 = (const float4*)(gi + ch * 32);
    const float4* b4 = (const float4*)(gj + ch * 32);
    #pragma unroll
    for (int u = 0; u < 4; u++) {
        float4 a = a4[u], b = b4[u];
        pv[4*u+0] = a.x * b.x; pv[4*u+1] = a.y * b.y;
        pv[4*u+2] = a.z * b.z; pv[4*u+3] = a.w * b.w;
    }
}

__global__ void __launch_bounds__(256) k_gemm()
{
    extern __shared__ __align__(16) char smg[];
    char* Ab[2] = { smg, smg + ABUF };
    char* Wb[2] = { smg + 2 * ABUF, smg + 2 * ABUF + WBUF };
    uint32_t Wbu[2] = { smem_u32(Wb[0]), smem_u32(Wb[1]) };

    int tid = threadIdx.x, wid = tid >> 5, lane = tid & 31;
    int g = lane >> 2, tg = lane & 3;
    int wm = wid & 3, wn = wid >> 2;
    int mt = blockIdx.x >> 1, ksp = blockIdx.x & 1;
    int m0 = mt * 128;
    int wkoff = ksp * 3456 * 2;

    int arow = tid >> 1, akh = tid & 1;
    const float* gi = d_g + (size_t)d_pi[m0 + arow] * E3 + ksp * 1152 + akh * 16;
    const float* gj = d_g + (size_t)d_pj[m0 + arow] * E3 + ksp * 1152 + akh * 16;
    int aoff = arow * 208 + akh * 96;

    float c[2][10][4];
    #pragma unroll
    for (int m2 = 0; m2 < 2; m2++)
        #pragma unroll
        for (int t = 0; t < 10; t++)
            #pragma unroll
            for (int q = 0; q < 4; q++) c[m2][t][q] = 0.f;

    float pv[16];
    cpw_generic(Wbu[0], (const char*)d_Wi, KPR * 2, wkoff, tid);
    CP_COMMIT();
    lda_pair(gi, gj, 0, pv);
    pack_store(Ab[0], aoff, pv);
    CP_WAIT0();
    __syncthreads();

    for (int ch = 0; ch < NCHA2; ch++) {
        int buf = ch & 1, nb = buf ^ 1;
        bool more = (ch + 1 < NCHA2);
        if (more) {
            cpw_generic(Wbu[nb], (const char*)d_Wi, KPR * 2,
                        wkoff + (ch + 1) * 192, tid);
            CP_COMMIT();
            lda_pair(gi, gj, ch + 1, pv);
        }
        const char* A = Ab[buf];
        const char* W = Wb[buf];
        #pragma unroll
        for (int s = 0; s < 6; s++) {
            uint32_t a[2][4];
            #pragma unroll
            for (int m2 = 0; m2 < 2; m2++) {
                int r0 = (wm * 32 + m2 * 16 + g) * 208 + s * 32 + tg * 4;
                a[m2][0] = *(const uint32_t*)(A + r0);
                a[m2][1] = *(const uint32_t*)(A + r0 + 8 * 208);
                a[m2][2] = *(const uint32_t*)(A + r0 + 16);
                a[m2][3] = *(const uint32_t*)(A + r0 + 8 * 208 + 16);
            }
            #pragma unroll
            for (int t = 0; t < 10; t++) {
                int wo = (wn * 80 + 8 * t + g) * 208 + s * 32 + tg * 4;
                uint32_t b0 = *(const uint32_t*)(W + wo);
                uint32_t b1 = *(const uint32_t*)(W + wo + 16);
                mma16816(c[0][t], a[0][0], a[0][1], a[0][2], a[0][3], b0, b1);
                mma16816(c[1][t], a[1][0], a[1][1], a[1][2], a[1][3], b0, b1);
            }
        }
        if (more) pack_store(Ab[nb], aoff, pv);
        CP_WAIT0();
        __syncthreads();
    }

    float* Cd = d_Cg2[ksp];
    #pragma unroll
    for (int m2 = 0; m2 < 2; m2++) {
        int rowa = m0 + wm * 32 + m2 * 16 + g;
        #pragma unroll
        for (int t = 0; t < 10; t++) {
            int col = wn * 80 + 8 * t + tg * 2;
            *(float2*)&Cd[(size_t)rowa * 160 + col] = make_float2(c[m2][t][0], c[m2][t][1]);
            *(float2*)&Cd[(size_t)(rowa + 8) * 160 + col] = make_float2(c[m2][t][2], c[m2][t][3]);
        }
    }
}

// ---------------------------------------------------------------------------
// k_pairE: layer-1 epilogue -> split-bf16 A' (64x488), tensor layer-2,
// fused relu*pw3 layer-3 from C fragments. 291 blocks.
// ---------------------------------------------------------------------------
__global__ void __launch_bounds__(256) k_pairE(
    const float* __restrict__ pb1, const float* __restrict__ pb2,
    const float* __restrict__ pw3, const float* __restrict__ pb3,
    float* __restrict__ out)
{
    extern __shared__ __align__(16) char smE[];
    unsigned short* A2 = (unsigned short*)smE;            // 64 x 488 shorts
    char* W2b[2] = { smE + A2BYTES, smE + A2BYTES + W2CB };
    uint32_t W2u[2] = { smem_u32(W2b[0]), smem_u32(W2b[1]) };
    __shared__ int pis[32], pjs[32];
    __shared__ float rsum[64][2];

    int r0 = blockIdx.x * 32;
    int tid = threadIdx.x;
    int jg = tid >> 5;
    int hg = tid & 31;
    int h0 = 5 * hg;
    int lane = tid & 31, wid = tid >> 5;
    int g = lane >> 2, tg = lane & 3;
    int wm = wid & 3, wn = wid >> 2;      // m-tile (16 rows), n-half

    if (tid < 32) { pis[tid] = d_pi[r0 + tid]; pjs[tid] = d_pj[r0 + tid]; }

    // prefetch W2 chunk 0
    #pragma unroll
    for (int v = 0; v < 3; v++) {
        int unit = tid + 256 * v;
        if (unit < 640) {
            int n = unit >> 2, q = unit & 3;
            CP_ASYNC16(W2u[0] + n * 80 + q * 16,
                       (const char*)d_W2i + (size_t)n * 960 + q * 16);
        }
    }
    CP_COMMIT();

    // zero A'
    {
        uint4 z = make_uint4(0, 0, 0, 0);
        uint4* a4 = (uint4*)A2;
        for (int idx = tid; idx < A2BYTES / 16; idx += 256) a4[idx] = z;
    }
    __syncthreads();

    // ---- layer-1: fwd rows t, trans rows 32+t, split-bf16 into A' ----
    #pragma unroll
    for (int jj = 0; jj < 4; jj++) {
        int t = 4 * jg + jj;
        int r = r0 + t;
        int pi = pis[t], pj = pjs[t];
        #pragma unroll
        for (int q = 0; q < 5; q++) {
            int h = h0 + q;
            if (h < HH) {
                size_t idx = (size_t)r * 160 + h;
                float cc = d_Cg2[0][idx] + d_Cg2[1][idx] + pb1[h];
                float vf = fmaxf(cc + d_A[pi * HH + h] + d_Bt[pj * HH + h], 0.f);
                float vt = fmaxf(cc + d_A[pj * HH + h] + d_Bt[pi * HH + h], 0.f);
                unsigned short hu, lu;
                split_bf16(vf, hu, lu);
                unsigned short* p = A2 + (size_t)t * 488 + 3 * h;
                p[0] = hu; p[1] = hu; p[2] = lu;
                split_bf16(vt, hu, lu);
                unsigned short* p2 = A2 + (size_t)(32 + t) * 488 + 3 * h;
                p2[0] = hu; p2[1] = hu; p2[2] = lu;
            }
        }
    }
    CP_WAIT0();
    __syncthreads();

    // ---- layer-2 mma: 15 chunks of 32 k' ----
    float c[10][4];
    #pragma unroll
    for (int t = 0; t < 10; t++)
        #pragma unroll
        for (int q = 0; q < 4; q++) c[t][q] = 0.f;

    for (int ch = 0; ch < 15; ch++) {
        int buf = ch & 1, nb = buf ^ 1;
        bool more = (ch + 1 < 15);
        if (more) {
            #pragma unroll
            for (int v = 0; v < 3; v++) {
                int unit = tid + 256 * v;
                if (unit < 640) {
                    int n = unit >> 2, q = unit & 3;
                    CP_ASYNC16(W2u[nb] + n * 80 + q * 16,
                               (const char*)d_W2i + (size_t)n * 960
                               + (ch + 1) * 64 + q * 16);
                }
            }
            CP_COMMIT();
        }
        const char* W = (const char*)W2b[buf];
        const char* A = (const char*)A2;
        #pragma unroll
        for (int s = 0; s < 2; s++) {
            int k0 = ch * 32 + s * 16;
            int ab = (16 * wm + g) * A2RS + (k0 + tg * 2) * 2;
            uint32_t a0 = *(const uint32_t*)(A + ab);
            uint32_t a1 = *(const uint32_t*)(A + ab + 8 * A2RS);
            uint32_t a2 = *(const uint32_t*)(A + ab + 16);
            uint32_t a3 = *(const uint32_t*)(A + ab + 8 * A2RS + 16);
            #pragma unroll
            for (int t = 0; t < 10; t++) {
                int wo = (wn * 80 + 8 * t + g) * 80 + s * 32 + tg * 4;
                uint32_t b0 = *(const uint32_t*)(W + wo);
                uint32_t b1 = *(const uint32_t*)(W + wo + 16);
                mma16816(c[t], a0, a1, a2, a3, b0, b1);
            }
        }
        if (more) { CP_WAIT0(); }
        __syncthreads();
    }

    // ---- layer-3: relu(c + pb2) * pw3, reduce ----
    float sg = 0.f, sg8 = 0.f;
    #pragma unroll
    for (int t = 0; t < 10; t++) {
        int n0 = wn * 80 + 8 * t + tg * 2;
        int n1 = n0 + 1;
        float b20 = (n0 < HH) ? pb2[n0] : 0.f;
        float b21 = (n1 < HH) ? pb2[n1] : 0.f;
        float w30 = (n0 < HH) ? pw3[n0] : 0.f;
        float w31 = (n1 < HH) ? pw3[n1] : 0.f;
        sg  += fmaxf(c[t][0] + b20, 0.f) * w30 + fmaxf(c[t][1] + b21, 0.f) * w31;
        sg8 += fmaxf(c[t][2] + b20, 0.f) * w30 + fmaxf(c[t][3] + b21, 0.f) * w31;
    }
    sg  += __shfl_xor_sync(0xffffffffu, sg, 1);
    sg  += __shfl_xor_sync(0xffffffffu, sg, 2);
    sg8 += __shfl_xor_sync(0xffffffffu, sg8, 1);
    sg8 += __shfl_xor_sync(0xffffffffu, sg8, 2);
    if (tg == 0) {
        rsum[16 * wm + g][wn] = sg;
        rsum[16 * wm + g + 8][wn] = sg8;
    }
    __syncthreads();

    if (tid < 64) {
        int row = tid;
        int t = row & 31;
        int fi, se;
        if (row < 32) { fi = pis[t]; se = pjs[t]; }
        else          { fi = pjs[t]; se = pis[t]; }
        float sc = rsum[row][0] + rsum[row][1] + pb3[0];
        float v = ((d_ms[fi] + d_ms[se]) + sc) * (1.f / 3.f);
        v = fminf(fmaxf(v, 0.f), 1.f);
        out[(size_t)fi * SS + (se % SS)] = v;
    }
}

// ---------------------------------------------------------------------------
extern "C" void kernel_launch(void* const* d_in, const int* in_sizes, int n_in,
                              void* d_out, int out_size)
{
    const float* X   = (const float*)d_in[0];
    const void*  sp  = d_in[1];
    const float* aw1 = (const float*)d_in[2];
    const float* ab1 = (const float*)d_in[3];
    const float* aw2 = (const float*)d_in[4];
    const float* ab2 = (const float*)d_in[5];
    const float* aw3 = (const float*)d_in[6];
    const float* ab3 = (const float*)d_in[7];
    const float* mw1 = (const float*)d_in[8];
    const float* mb1 = (const float*)d_in[9];
    const float* mw2 = (const float*)d_in[10];
    const float* mb2 = (const float*)d_in[11];
    const float* mw3 = (const float*)d_in[12];
    const float* mb3 = (const float*)d_in[13];
    const float* pw1 = (const float*)d_in[14];
    const float* pb1 = (const float*)d_in[15];
    const float* pw2 = (const float*)d_in[16];
    const float* pb2 = (const float*)d_in[17];
    const float* pw3 = (const float*)d_in[18];
    const float* pb3 = (const float*)d_in[19];
    float* out = (float*)d_out;

    cudaFuncSetAttribute(k_gemm, cudaFuncAttributeMaxDynamicSharedMemorySize,
                         SMEMG);
    cudaFuncSetAttribute(k_attn1g, cudaFuncAttributeMaxDynamicSharedMemorySize,
                         SMEMG);
    cudaFuncSetAttribute(k_pairE, cudaFuncAttributeMaxDynamicSharedMemorySize,
                         SMEMPE);

    const int wtot = 160 * (KPR + KA + K2);
    k_prep0<<<73, 256>>>(sp);
    k_wprep<<<(wtot + 255) / 256, 256>>>(pw1, aw1, pw2);
    k_attn1g<<<48, 256, SMEMG>>>(X);
    k_attn2g<<<48, 256>>>(X, ab1, aw2, ab2, aw3, ab3);
    k_terms<<<288, 256>>>(pw1, mw1);
    k_reduce<<<(NSPAN * HH + 255) / 256, 256>>>();
    k_ment<<<NSPAN, 160>>>(mb1, mw2, mb2, mw3, mb3);
    k_gemm<<<146, 256, SMEMG>>>();
    k_pairE<<<NPAIR / 32, 256, SMEMPE>>>(pb1, pb2, pw3, pb3, out);
}

// round 11
// speedup vs baseline: 6.0612x; 1.0449x over previous
#include <cuda_runtime.h>
#include <cuda_bf16.h>
#include <cstdint>

#define BB 2
#define TT 2048
#define EE 768
#define SS 96
#define HH 150
#define HS 168
#define WW 8
#define E3 2304
#define NSPAN (BB*SS)      // 192
#define NROW (NSPAN*WW)    // 1536
#define NPAIR 9312
#define NPAIRP 9344        // 73*128
#define KPR 6912           // 3*E3 interleaved split K (pair GEMM)
#define KA 2304            // 3*768 interleaved split K (attn GEMM)
#define K2 480             // 3*160 interleaved split K (layer-2)
#define NCHA2 36
#define ABUF 26624         // 128 rows * 208 B
#define WBUF 33280         // 160 rows * 208 B
#define SMEMG (2*ABUF + 2*WBUF)        // 119808
#define A2RS 976           // pairE A' row stride bytes (488 shorts)
#define A2BYTES (64*A2RS)              // 62464
#define W2CB 12800         // 160 rows * 80 B per chunk buffer
#define SMEMPE (A2BYTES + 2*W2CB)      // 88064

// -------- device scratch --------
__device__ int   d_starts[NSPAN];
__device__ __align__(16) float d_g[NSPAN * E3];
__device__ float d_part[3 * 16 * NSPAN * HH];
__device__ float d_ap[8 * NROW * 160];
__device__ float d_at[NROW];
__device__ float d_A[NSPAN * HH];
__device__ float d_Bt[NSPAN * HH];
__device__ float d_ms[NSPAN];
__device__ int   d_pi[NPAIRP], d_pj[NPAIRP];
__device__ __align__(16) __nv_bfloat16 d_Wi[160 * KPR];
__device__ __align__(16) __nv_bfloat16 d_AWi[160 * KA];
__device__ __align__(16) __nv_bfloat16 d_W2i[160 * K2];
__device__ float d_Cg2[2][(size_t)NPAIRP * 160];

// -------- generic-PTX helpers --------
__device__ __forceinline__ uint32_t smem_u32(const void* p) {
    uint32_t a;
    asm("{ .reg .u64 t; cvta.to.shared.u64 t, %1; cvt.u32.u64 %0, t; }"
        : "=r"(a) : "l"(p));
    return a;
}
#define CP_ASYNC16(dst, src) \
    asm volatile("cp.async.cg.shared.global [%0], [%1], 16;" \
                 :: "r"(dst), "l"(src) : "memory")
#define CP_COMMIT() asm volatile("cp.async.commit_group;" ::: "memory")
#define CP_WAIT0()  asm volatile("cp.async.wait_group 0;" ::: "memory")

__device__ __forceinline__ void mma16816(float c[4], uint32_t a0, uint32_t a1,
                                         uint32_t a2, uint32_t a3,
                                         uint32_t b0, uint32_t b1) {
    asm volatile(
        "mma.sync.aligned.m16n8k16.row.col.f32.bf16.bf16.f32 "
        "{%0,%1,%2,%3}, {%4,%5,%6,%7}, {%8,%9}, {%0,%1,%2,%3};"
        : "+f"(c[0]), "+f"(c[1]), "+f"(c[2]), "+f"(c[3])
        : "r"(a0), "r"(a1), "r"(a2), "r"(a3), "r"(b0), "r"(b1));
}

__device__ __forceinline__ void split_bf16(float p, unsigned short& hu,
                                           unsigned short& lu) {
    asm("cvt.rn.bf16.f32 %0, %1;" : "=h"(hu) : "f"(p));
    float hf = __uint_as_float(((uint32_t)hu) << 16);
    float l = p - hf;
    asm("cvt.rn.bf16.f32 %0, %1;" : "=h"(lu) : "f"(l));
}

// ---------------------------------------------------------------------------
// k_prep0: pair list (blocks 0..71) + span_starts conversion (block 72)
// ---------------------------------------------------------------------------
__global__ void k_prep0(const void* sp) {
    if (blockIdx.x == 72) {
        __shared__ int is64;
        if (threadIdx.x == 0) {
            const int* w32 = (const int*)sp;
            int z = 1;
            for (int i = 1; i < 64; i += 2) if (w32[i] != 0) { z = 0; break; }
            is64 = z;
        }
        __syncthreads();
        int i = threadIdx.x;
        if (i < NSPAN) {
            if (is64) d_starts[i] = (int)((const long long*)sp)[i];
            else      d_starts[i] = ((const int*)sp)[i];
        }
        return;
    }
    int idx = blockIdx.x * 256 + threadIdx.x;
    int b = idx / (SS * SS), r = idx % (SS * SS);
    int i = r / SS, j = r % SS;
    if (j >= i) {
        int row = b * 4656 + i * SS - i * (i - 1) / 2 + (j - i);
        d_pi[row] = b * SS + i;
        d_pj[row] = b * SS + j;
    }
    if (idx < NPAIRP - NPAIR) {
        d_pi[NPAIR + idx] = NSPAN - 1;
        d_pj[NPAIR + idx] = NSPAN - 1;
    }
}

// ---------------------------------------------------------------------------
// k_wprep: one thread per (n, k) — compute split once, write 3 shorts
// pattern for W side: [hi, lo, hi]
// ---------------------------------------------------------------------------
__global__ void k_wprep(const float* __restrict__ pw1,
                        const float* __restrict__ aw1,
                        const float* __restrict__ pw2) {
    int idx = blockIdx.x * blockDim.x + threadIdx.x;
    const int S0 = 160 * E3;          // Wc: k in 0..2303
    const int S1 = 160 * 768;         // aw1: k in 0..767
    const int S2 = 160 * 160;         // pw2: k in 0..159 (real <150)
    if (idx >= S0 + S1 + S2) return;
    float w = 0.f;
    unsigned short* dst;
    if (idx < S0) {
        int n = idx / E3, k = idx % E3;
        if (n < HH) w = pw1[(size_t)2 * E3 * HH + (size_t)k * HH + n];
        dst = (unsigned short*)d_Wi + (size_t)n * KPR + 3 * k;
    } else if (idx < S0 + S1) {
        int i2 = idx - S0;
        int n = i2 / 768, k = i2 % 768;
        if (n < HH) w = aw1[(size_t)k * HH + n];
        dst = (unsigned short*)d_AWi + (size_t)n * KA + 3 * k;
    } else {
        int i3 = idx - S0 - S1;
        int n = i3 / 160, k = i3 % 160;
        if (n < HH && k < HH) w = pw2[(size_t)k * HH + n];
        dst = (unsigned short*)d_W2i + (size_t)n * K2 + 3 * k;
    }
    unsigned short hu, lu;
    split_bf16(w, hu, lu);
    dst[0] = hu; dst[1] = lu; dst[2] = hu;
}

// ---------------------------------------------------------------------------
// shared staging helpers for the mma GEMM template
// ---------------------------------------------------------------------------
__device__ __forceinline__ void cpw_generic(uint32_t wdst, const char* srcbase,
                                            size_t rstride, int choff, int tid) {
    #pragma unroll
    for (int v = 0; v < 2; v++) {
        int unit = tid + 256 * v;
        if (unit < 320) {
            int n = unit >> 1, kh = unit & 1;
            const char* src = srcbase + (size_t)n * rstride + choff + kh * 96;
            uint32_t dst = wdst + n * 208 + kh * 96;
            #pragma unroll
            for (int q = 0; q < 6; q++)
                CP_ASYNC16(dst + q * 16, src + q * 16);
        }
    }
}

__device__ __forceinline__ void pack_store(char* dst, int aoff,
                                           const float* pv) {
    unsigned short us[48];
    #pragma unroll
    for (int k = 0; k < 16; k++) {
        unsigned short hu, lu;
        split_bf16(pv[k], hu, lu);
        us[3*k+0] = hu; us[3*k+1] = hu; us[3*k+2] = lu;
    }
    uint32_t u[24];
    #pragma unroll
    for (int j = 0; j < 24; j++)
        u[j] = (uint32_t)us[2*j] | ((uint32_t)us[2*j+1] << 16);
    uint4* d = (uint4*)(dst + aoff);
    d[0] = make_uint4(u[0],  u[1],  u[2],  u[3]);
    d[1] = make_uint4(u[4],  u[5],  u[6],  u[7]);
    d[2] = make_uint4(u[8],  u[9],  u[10], u[11]);
    d[3] = make_uint4(u[12], u[13], u[14], u[15]);
    d[4] = make_uint4(u[16], u[17], u[18], u[19]);
    d[5] = make_uint4(u[20], u[21], u[22], u[23]);
}

// ---------------------------------------------------------------------------
// k_attn1g: attn layer-1 via mma.sync. 12 M-tiles x 8 K-splits = 96 blocks.
// ---------------------------------------------------------------------------
__global__ void __launch_bounds__(256) k_attn1g(const float* __restrict__ X)
{
    extern __shared__ __align__(16) char smg[];
    char* Ab[2] = { smg, smg + ABUF };
    char* Wb[2] = { smg + 2 * ABUF, smg + 2 * ABUF + WBUF };
    uint32_t Wbu[2] = { smem_u32(Wb[0]), smem_u32(Wb[1]) };

    int tid = threadIdx.x, wid = tid >> 5, lane = tid & 31;
    int g = lane >> 2, tg = lane & 3;
    int wm = wid & 3, wn = wid >> 2;
    int mt = blockIdx.x >> 3, ksp = blockIdx.x & 7;
    int m0 = mt * 128;
    int wkoff = ksp * 576;               // 288 k' * 2B

    int arow = tid >> 1, akh = tid & 1;
    int grow = m0 + arow;
    int si = grow >> 3, w = grow & 7;
    int b = si / SS;
    const float* Xp = X + ((size_t)(b * TT + d_starts[si] + w)) * EE
                        + ksp * 96 + akh * 16;
    int aoff = arow * 208 + akh * 96;

    float c[2][10][4];
    #pragma unroll
    for (int m2 = 0; m2 < 2; m2++)
        #pragma unroll
        for (int t = 0; t < 10; t++)
            #pragma unroll
            for (int q = 0; q < 4; q++) c[m2][t][q] = 0.f;

    float xr[16];
    cpw_generic(Wbu[0], (const char*)d_AWi, KA * 2, wkoff, tid);
    CP_COMMIT();
    {
        const float4* x4 = (const float4*)Xp;
        #pragma unroll
        for (int u = 0; u < 4; u++) {
            float4 a = x4[u];
            xr[4*u] = a.x; xr[4*u+1] = a.y; xr[4*u+2] = a.z; xr[4*u+3] = a.w;
        }
    }
    pack_store(Ab[0], aoff, xr);
    CP_WAIT0();
    __syncthreads();

    for (int ch = 0; ch < 3; ch++) {
        int buf = ch & 1, nb = buf ^ 1;
        bool more = (ch + 1 < 3);
        if (more) {
            cpw_generic(Wbu[nb], (const char*)d_AWi, KA * 2,
                        wkoff + (ch + 1) * 192, tid);
            CP_COMMIT();
            const float4* x4 = (const float4*)(Xp + (ch + 1) * 32);
            #pragma unroll
            for (int u = 0; u < 4; u++) {
                float4 a = x4[u];
                xr[4*u] = a.x; xr[4*u+1] = a.y; xr[4*u+2] = a.z; xr[4*u+3] = a.w;
            }
        }
        const char* A = Ab[buf];
        const char* W = Wb[buf];
        #pragma unroll
        for (int s = 0; s < 6; s++) {
            uint32_t a[2][4];
            #pragma unroll
            for (int m2 = 0; m2 < 2; m2++) {
                int r0 = (wm * 32 + m2 * 16 + g) * 208 + s * 32 + tg * 4;
                a[m2][0] = *(const uint32_t*)(A + r0);
                a[m2][1] = *(const uint32_t*)(A + r0 + 8 * 208);
                a[m2][2] = *(const uint32_t*)(A + r0 + 16);
                a[m2][3] = *(const uint32_t*)(A + r0 + 8 * 208 + 16);
            }
            #pragma unroll
            for (int t = 0; t < 10; t++) {
                int wo = (wn * 80 + 8 * t + g) * 208 + s * 32 + tg * 4;
                uint32_t b0 = *(const uint32_t*)(W + wo);
                uint32_t b1 = *(const uint32_t*)(W + wo + 16);
                mma16816(c[0][t], a[0][0], a[0][1], a[0][2], a[0][3], b0, b1);
                mma16816(c[1][t], a[1][0], a[1][1], a[1][2], a[1][3], b0, b1);
            }
        }
        if (more) pack_store(Ab[nb], aoff, xr);
        CP_WAIT0();
        __syncthreads();
    }

    float* Cd = d_ap + (size_t)ksp * NROW * 160;
    #pragma unroll
    for (int m2 = 0; m2 < 2; m2++) {
        int rowa = m0 + wm * 32 + m2 * 16 + g;
        #pragma unroll
        for (int t = 0; t < 10; t++) {
            int col = wn * 80 + 8 * t + tg * 2;
            *(float2*)&Cd[(size_t)rowa * 160 + col] = make_float2(c[m2][t][0], c[m2][t][1]);
            *(float2*)&Cd[(size_t)(rowa + 8) * 160 + col] = make_float2(c[m2][t][2], c[m2][t][3]);
        }
    }
}

// ---------------------------------------------------------------------------
// k_attn2: reduce 8 partials + attn layers 2,3 -> d_at.  48 blocks.
// ---------------------------------------------------------------------------
__global__ void __launch_bounds__(256) k_attn2(
    const float* __restrict__ ab1, const float* __restrict__ aw2,
    const float* __restrict__ ab2, const float* __restrict__ aw3,
    const float* __restrict__ ab3)
{
    int r0 = blockIdx.x * 32;
    int tid = threadIdx.x;
    int jg = tid >> 5, hg = tid & 31;
    int h0 = 5 * hg;
    int kk2 = tid >> 4, hb2 = tid & 15;

    __shared__ __align__(16) float s1[32 * HS];
    __shared__ __align__(16) float ews[16 * HS];
    __shared__ __align__(16) float eps[16 * 36];

    for (int idx = tid; idx < 32 * 160; idx += 256) {
        int t = idx / 160, h = idx - (idx / 160) * 160;
        float v = 0.f;
        if (h < HH) {
            float s = ab1[h];
            #pragma unroll
            for (int ks = 0; ks < 8; ks++)
                s += d_ap[((size_t)ks * NROW + r0 + t) * 160 + h];
            v = fmaxf(s, 0.f);
        }
        s1[t * HS + h] = v;
    }

    float acc2[4][5];
    #pragma unroll
    for (int jj = 0; jj < 4; jj++)
        #pragma unroll
        for (int q = 0; q < 5; q++) {
            int h = h0 + q;
            acc2[jj][q] = (h < HH) ? ab2[h] : 0.f;
        }
    for (int k0 = 0; k0 < 160; k0 += 16) {
        __syncthreads();
        #pragma unroll
        for (int q = 0; q < 10; q++) {
            int h = hb2 + 16 * q;
            if (h < 160) {
                float v = 0.f;
                if ((k0 + kk2) < HH && h < HH) v = aw2[(k0 + kk2) * HH + h];
                ews[kk2 * HS + h] = v;
            }
        }
        #pragma unroll
        for (int r = 0; r < 2; r++) {
            int idx = tid + 256 * r;
            int t = idx >> 4, kk = idx & 15;
            eps[kk * 36 + t] = s1[t * HS + k0 + kk];
        }
        __syncthreads();
        #pragma unroll
        for (int kk = 0; kk < 16; kk++) {
            float4 p = *(const float4*)&eps[kk * 36 + 4 * jg];
            const float* wr = &ews[kk * HS + h0];
            float w0 = wr[0], w1 = wr[1], w2 = wr[2], w3 = wr[3], w4 = wr[4];
            acc2[0][0] += p.x * w0; acc2[0][1] += p.x * w1; acc2[0][2] += p.x * w2;
            acc2[0][3] += p.x * w3; acc2[0][4] += p.x * w4;
            acc2[1][0] += p.y * w0; acc2[1][1] += p.y * w1; acc2[1][2] += p.y * w2;
            acc2[1][3] += p.y * w3; acc2[1][4] += p.y * w4;
            acc2[2][0] += p.z * w0; acc2[2][1] += p.z * w1; acc2[2][2] += p.z * w2;
            acc2[2][3] += p.z * w3; acc2[2][4] += p.z * w4;
            acc2[3][0] += p.w * w0; acc2[3][1] += p.w * w1; acc2[3][2] += p.w * w2;
            acc2[3][3] += p.w * w3; acc2[3][4] += p.w * w4;
        }
    }
    float part[4];
    #pragma unroll
    for (int jj = 0; jj < 4; jj++) {
        float s = 0.f;
        #pragma unroll
        for (int q = 0; q < 5; q++) {
            int h = h0 + q;
            if (h < HH) s += fmaxf(acc2[jj][q], 0.f) * aw3[h];
        }
        part[jj] = s;
    }
    #pragma unroll
    for (int jj = 0; jj < 4; jj++)
        #pragma unroll
        for (int off = 16; off > 0; off >>= 1)
            part[jj] += __shfl_xor_sync(0xffffffffu, part[jj], off);
    if (hg == 0) {
        #pragma unroll
        for (int jj = 0; jj < 4; jj++)
            d_at[r0 + 4 * jg + jj] = part[jj] + ab3[0];
    }
}

// ---------------------------------------------------------------------------
// k_gather: build g_i. grid = NSPAN*3, one 256-wide e-slice per block.
// ---------------------------------------------------------------------------
__global__ void __launch_bounds__(256) k_gather(const float* __restrict__ X)
{
    int si = blockIdx.x / 3;
    int e = (blockIdx.x % 3) * 256 + threadIdx.x;
    int b = si / SS;
    __shared__ float atv[8];
    if (threadIdx.x < 8) atv[threadIdx.x] = d_at[si * 8 + threadIdx.x];
    __syncthreads();

    const float* Xb = X + ((size_t)(b * TT + d_starts[si])) * EE + e;
    float s = 0.f, x0 = 0.f, x7 = 0.f;
    #pragma unroll
    for (int w = 0; w < WW; w++) {
        float xv = Xb[w * EE];
        if (w == 0) x0 = xv;
        if (w == 7) x7 = xv;
        s += xv * atv[w];
    }
    float* gp = d_g + (size_t)si * E3;
    gp[e]          = x0;
    gp[EE + e]     = x7;
    gp[2 * EE + e] = s;
}

// ---------------------------------------------------------------------------
__global__ void __launch_bounds__(256) k_terms(
    const float* __restrict__ pw1, const float* __restrict__ mw1)
{
    int x = blockIdx.x;
    int sc  = x % 6;
    int mat = (x / 6) % 3;
    int ks  = x / 18;
    const float* Wm = (mat == 0) ? pw1 : (mat == 1 ? pw1 + (size_t)E3 * HH : mw1);
    int s0 = sc * 32;
    int kbase = ks * 144;
    int tid = threadIdx.x;
    int jg = tid >> 5;
    int hg = tid & 31;
    int h0 = 5 * hg;
    int kk2 = tid >> 4;
    int hb2 = tid & 15;

    __shared__ __align__(16) float wst[16 * HS];
    __shared__ __align__(16) float pst[16 * 36];

    float acc[4][5];
    #pragma unroll
    for (int jj = 0; jj < 4; jj++)
        #pragma unroll
        for (int q = 0; q < 5; q++) acc[jj][q] = 0.f;

    for (int kc = 0; kc < 144; kc += 16) {
        int k0 = kbase + kc;
        __syncthreads();
        #pragma unroll
        for (int q = 0; q < 10; q++) {
            int h = hb2 + 16 * q;
            if (h < 160)
                wst[kk2 * HS + h] = (h < HH) ? Wm[(size_t)(k0 + kk2) * HH + h] : 0.f;
        }
        #pragma unroll
        for (int r = 0; r < 2; r++) {
            int idx = tid + 256 * r;
            int t = idx >> 4, kk = idx & 15;
            pst[kk * 36 + t] = d_g[(size_t)(s0 + t) * E3 + k0 + kk];
        }
        __syncthreads();
        #pragma unroll
        for (int kk = 0; kk < 16; kk++) {
            float4 p = *(const float4*)&pst[kk * 36 + 4 * jg];
            const float* wr = &wst[kk * HS + h0];
            float w0 = wr[0], w1 = wr[1], w2 = wr[2], w3 = wr[3], w4 = wr[4];
            acc[0][0] += p.x * w0; acc[0][1] += p.x * w1; acc[0][2] += p.x * w2;
            acc[0][3] += p.x * w3; acc[0][4] += p.x * w4;
            acc[1][0] += p.y * w0; acc[1][1] += p.y * w1; acc[1][2] += p.y * w2;
            acc[1][3] += p.y * w3; acc[1][4] += p.y * w4;
            acc[2][0] += p.z * w0; acc[2][1] += p.z * w1; acc[2][2] += p.z * w2;
            acc[2][3] += p.z * w3; acc[2][4] += p.z * w4;
            acc[3][0] += p.w * w0; acc[3][1] += p.w * w1; acc[3][2] += p.w * w2;
            acc[3][3] += p.w * w3; acc[3][4] += p.w * w4;
        }
    }
    #pragma unroll
    for (int jj = 0; jj < 4; jj++) {
        int t = 4 * jg + jj;
        float* op = d_part + (((size_t)mat * 16 + ks) * NSPAN + s0 + t) * HH;
        #pragma unroll
        for (int q = 0; q < 5; q++) {
            int h = h0 + q;
            if (h < HH) op[h] = acc[jj][q];
        }
    }
}

// ---------------------------------------------------------------------------
// k_redment: per-span partial reduction (A, Bt, m1) + mention MLP.  192 blocks.
// ---------------------------------------------------------------------------
__global__ void __launch_bounds__(160) k_redment(
    const float* __restrict__ mb1, const float* __restrict__ mw2,
    const float* __restrict__ mb2, const float* __restrict__ mw3,
    const float* __restrict__ mb3)
{
    int s = blockIdx.x;
    int tid = threadIdx.x;
    __shared__ float s1[HH];
    __shared__ float warpsum[8];

    if (tid < HH) {
        float a = 0.f, b = 0.f, m = 0.f;
        #pragma unroll
        for (int ks = 0; ks < 16; ks++) {
            a += d_part[(((size_t)0 * 16 + ks) * NSPAN + s) * HH + tid];
            b += d_part[(((size_t)1 * 16 + ks) * NSPAN + s) * HH + tid];
            m += d_part[(((size_t)2 * 16 + ks) * NSPAN + s) * HH + tid];
        }
        d_A[s * HH + tid]  = a;
        d_Bt[s * HH + tid] = b;
        s1[tid] = fmaxf(m + mb1[tid], 0.f);
    }
    __syncthreads();
    float p = 0.f;
    if (tid < HH) {
        float v = mb2[tid];
        for (int k = 0; k < HH; k++) v += s1[k] * mw2[k * HH + tid];
        p = fmaxf(v, 0.f) * mw3[tid];
    }
    #pragma unroll
    for (int o = 16; o > 0; o >>= 1) p += __shfl_down_sync(0xffffffffu, p, o);
    if ((tid & 31) == 0) warpsum[tid >> 5] = p;
    __syncthreads();
    if (tid == 0) {
        float t = mb3[0];
        for (int w = 0; w < 5; w++) t += warpsum[w];
        d_ms[s] = t;
    }
}

// ---------------------------------------------------------------------------
// k_gemm: pair C-term via mma.sync (validated).
// ---------------------------------------------------------------------------
__device__ __forceinline__ void lda_pair(const float* gi, const float* gj,
                                         int ch, float* pv) {
    const float4* a4 = (const float4*)(gi + ch * 32);
    const float4* b4 = (const float4*)(gj + ch * 32);
    #pragma unroll
    for (int u = 0; u < 4; u++) {
        float4 a = a4[u], b = b4[u];
        pv[4*u+0] = a.x * b.x; pv[4*u+1] = a.y * b.y;
        pv[4*u+2] = a.z * b.z; pv[4*u+3] = a.w * b.w;
    }
}

__global__ void __launch_bounds__(256) k_gemm()
{
    extern __shared__ __align__(16) char smg[];
    char* Ab[2] = { smg, smg + ABUF };
    char* Wb[2] = { smg + 2 * ABUF, smg + 2 * ABUF + WBUF };
    uint32_t Wbu[2] = { smem_u32(Wb[0]), smem_u32(Wb[1]) };

    int tid = threadIdx.x, wid = tid >> 5, lane = tid & 31;
    int g = lane >> 2, tg = lane & 3;
    int wm = wid & 3, wn = wid >> 2;
    int mt = blockIdx.x >> 1, ksp = blockIdx.x & 1;
    int m0 = mt * 128;
    int wkoff = ksp * 3456 * 2;

    int arow = tid >> 1, akh = tid & 1;
    const float* gi = d_g + (size_t)d_pi[m0 + arow] * E3 + ksp * 1152 + akh * 16;
    const float* gj = d_g + (size_t)d_pj[m0 + arow] * E3 + ksp * 1152 + akh * 16;
    int aoff = arow * 208 + akh * 96;

    float c[2][10][4];
    #pragma unroll
    for (int m2 = 0; m2 < 2; m2++)
        #pragma unroll
        for (int t = 0; t < 10; t++)
            #pragma unroll
            for (int q = 0; q < 4; q++) c[m2][t][q] = 0.f;

    float pv[16];
    cpw_generic(Wbu[0], (const char*)d_Wi, KPR * 2, wkoff, tid);
    CP_COMMIT();
    lda_pair(gi, gj, 0, pv);
    pack_store(Ab[0], aoff, pv);
    CP_WAIT0();
    __syncthreads();

    for (int ch = 0; ch < NCHA2; ch++) {
        int buf = ch & 1, nb = buf ^ 1;
        bool more = (ch + 1 < NCHA2);
        if (more) {
            cpw_generic(Wbu[nb], (const char*)d_Wi, KPR * 2,
                        wkoff + (ch + 1) * 192, tid);
            CP_COMMIT();
            lda_pair(gi, gj, ch + 1, pv);
        }
        const char* A = Ab[buf];
        const char* W = Wb[buf];
        #pragma unroll
        for (int s = 0; s < 6; s++) {
            uint32_t a[2][4];
            #pragma unroll
            for (int m2 = 0; m2 < 2; m2++) {
                int r0 = (wm * 32 + m2 * 16 + g) * 208 + s * 32 + tg * 4;
                a[m2][0] = *(const uint32_t*)(A + r0);
                a[m2][1] = *(const uint32_t*)(A + r0 + 8 * 208);
                a[m2][2] = *(const uint32_t*)(A + r0 + 16);
                a[m2][3] = *(const uint32_t*)(A + r0 + 8 * 208 + 16);
            }
            #pragma unroll
            for (int t = 0; t < 10; t++) {
                int wo = (wn * 80 + 8 * t + g) * 208 + s * 32 + tg * 4;
                uint32_t b0 = *(const uint32_t*)(W + wo);
                uint32_t b1 = *(const uint32_t*)(W + wo + 16);
                mma16816(c[0][t], a[0][0], a[0][1], a[0][2], a[0][3], b0, b1);
                mma16816(c[1][t], a[1][0], a[1][1], a[1][2], a[1][3], b0, b1);
            }
        }
        if (more) pack_store(Ab[nb], aoff, pv);
        CP_WAIT0();
        __syncthreads();
    }

    float* Cd = d_Cg2[ksp];
    #pragma unroll
    for (int m2 = 0; m2 < 2; m2++) {
        int rowa = m0 + wm * 32 + m2 * 16 + g;
        #pragma unroll
        for (int t = 0; t < 10; t++) {
            int col = wn * 80 + 8 * t + tg * 2;
            *(float2*)&Cd[(size_t)rowa * 160 + col] = make_float2(c[m2][t][0], c[m2][t][1]);
            *(float2*)&Cd[(size_t)(rowa + 8) * 160 + col] = make_float2(c[m2][t][2], c[m2][t][3]);
        }
    }
}

// ---------------------------------------------------------------------------
// k_pairE: layer-1 epilogue -> split-bf16 A' (64x488), tensor layer-2,
// fused relu*pw3 layer-3 from C fragments. 291 blocks. (validated)
// ---------------------------------------------------------------------------
__global__ void __launch_bounds__(256) k_pairE(
    const float* __restrict__ pb1, const float* __restrict__ pb2,
    const float* __restrict__ pw3, const float* __restrict__ pb3,
    float* __restrict__ out)
{
    extern __shared__ __align__(16) char smE[];
    unsigned short* A2 = (unsigned short*)smE;            // 64 x 488 shorts
    char* W2b[2] = { smE + A2BYTES, smE + A2BYTES + W2CB };
    uint32_t W2u[2] = { smem_u32(W2b[0]), smem_u32(W2b[1]) };
    __shared__ int pis[32], pjs[32];
    __shared__ float rsum[64][2];

    int r0 = blockIdx.x * 32;
    int tid = threadIdx.x;
    int jg = tid >> 5;
    int hg = tid & 31;
    int h0 = 5 * hg;
    int lane = tid & 31, wid = tid >> 5;
    int g = lane >> 2, tg = lane & 3;
    int wm = wid & 3, wn = wid >> 2;

    if (tid < 32) { pis[tid] = d_pi[r0 + tid]; pjs[tid] = d_pj[r0 + tid]; }

    #pragma unroll
    for (int v = 0; v < 3; v++) {
        int unit = tid + 256 * v;
        if (unit < 640) {
            int n = unit >> 2, q = unit & 3;
            CP_ASYNC16(W2u[0] + n * 80 + q * 16,
                       (const char*)d_W2i + (size_t)n * 960 + q * 16);
        }
    }
    CP_COMMIT();

    {
        uint4 z = make_uint4(0, 0, 0, 0);
        uint4* a4 = (uint4*)A2;
        for (int idx = tid; idx < A2BYTES / 16; idx += 256) a4[idx] = z;
    }
    __syncthreads();

    #pragma unroll
    for (int jj = 0; jj < 4; jj++) {
        int t = 4 * jg + jj;
        int r = r0 + t;
        int pi = pis[t], pj = pjs[t];
        #pragma unroll
        for (int q = 0; q < 5; q++) {
            int h = h0 + q;
            if (h < HH) {
                size_t idx = (size_t)r * 160 + h;
                float cc = d_Cg2[0][idx] + d_Cg2[1][idx] + pb1[h];
                float vf = fmaxf(cc + d_A[pi * HH + h] + d_Bt[pj * HH + h], 0.f);
                float vt = fmaxf(cc + d_A[pj * HH + h] + d_Bt[pi * HH + h], 0.f);
                unsigned short hu, lu;
                split_bf16(vf, hu, lu);
                unsigned short* p = A2 + (size_t)t * 488 + 3 * h;
                p[0] = hu; p[1] = hu; p[2] = lu;
                split_bf16(vt, hu, lu);
                unsigned short* p2 = A2 + (size_t)(32 + t) * 488 + 3 * h;
                p2[0] = hu; p2[1] = hu; p2[2] = lu;
            }
        }
    }
    CP_WAIT0();
    __syncthreads();

    float c[10][4];
    #pragma unroll
    for (int t = 0; t < 10; t++)
        #pragma unroll
        for (int q = 0; q < 4; q++) c[t][q] = 0.f;

    for (int ch = 0; ch < 15; ch++) {
        int buf = ch & 1, nb = buf ^ 1;
        bool more = (ch + 1 < 15);
        if (more) {
            #pragma unroll
            for (int v = 0; v < 3; v++) {
                int unit = tid + 256 * v;
                if (unit < 640) {
                    int n = unit >> 2, q = unit & 3;
                    CP_ASYNC16(W2u[nb] + n * 80 + q * 16,
                               (const char*)d_W2i + (size_t)n * 960
                               + (ch + 1) * 64 + q * 16);
                }
            }
            CP_COMMIT();
        }
        const char* W = (const char*)W2b[buf];
        const char* A = (const char*)A2;
        #pragma unroll
        for (int s = 0; s < 2; s++) {
            int k0 = ch * 32 + s * 16;
            int ab = (16 * wm + g) * A2RS + (k0 + tg * 2) * 2;
            uint32_t a0 = *(const uint32_t*)(A + ab);
            uint32_t a1 = *(const uint32_t*)(A + ab + 8 * A2RS);
            uint32_t a2 = *(const uint32_t*)(A + ab + 16);
            uint32_t a3 = *(const uint32_t*)(A + ab + 8 * A2RS + 16);
            #pragma unroll
            for (int t = 0; t < 10; t++) {
                int wo = (wn * 80 + 8 * t + g) * 80 + s * 32 + tg * 4;
                uint32_t b0 = *(const uint32_t*)(W + wo);
                uint32_t b1 = *(const uint32_t*)(W + wo + 16);
                mma16816(c[t], a0, a1, a2, a3, b0, b1);
            }
        }
        if (more) { CP_WAIT0(); }
        __syncthreads();
    }

    float sg = 0.f, sg8 = 0.f;
    #pragma unroll
    for (int t = 0; t < 10; t++) {
        int n0 = wn * 80 + 8 * t + tg * 2;
        int n1 = n0 + 1;
        float b20 = (n0 < HH) ? pb2[n0] : 0.f;
        float b21 = (n1 < HH) ? pb2[n1] : 0.f;
        float w30 = (n0 < HH) ? pw3[n0] : 0.f;
        float w31 = (n1 < HH) ? pw3[n1] : 0.f;
        sg  += fmaxf(c[t][0] + b20, 0.f) * w30 + fmaxf(c[t][1] + b21, 0.f) * w31;
        sg8 += fmaxf(c[t][2] + b20, 0.f) * w30 + fmaxf(c[t][3] + b21, 0.f) * w31;
    }
    sg  += __shfl_xor_sync(0xffffffffu, sg, 1);
    sg  += __shfl_xor_sync(0xffffffffu, sg, 2);
    sg8 += __shfl_xor_sync(0xffffffffu, sg8, 1);
    sg8 += __shfl_xor_sync(0xffffffffu, sg8, 2);
    if (tg == 0) {
        rsum[16 * wm + g][wn] = sg;
        rsum[16 * wm + g + 8][wn] = sg8;
    }
    __syncthreads();

    if (tid < 64) {
        int row = tid;
        int t = row & 31;
        int fi, se;
        if (row < 32) { fi = pis[t]; se = pjs[t]; }
        else          { fi = pjs[t]; se = pis[t]; }
        float sc = rsum[row][0] + rsum[row][1] + pb3[0];
        float v = ((d_ms[fi] + d_ms[se]) + sc) * (1.f / 3.f);
        v = fminf(fmaxf(v, 0.f), 1.f);
        out[(size_t)fi * SS + (se % SS)] = v;
    }
}

// ---------------------------------------------------------------------------
extern "C" void kernel_launch(void* const* d_in, const int* in_sizes, int n_in,
                              void* d_out, int out_size)
{
    const float* X   = (const float*)d_in[0];
    const void*  sp  = d_in[1];
    const float* aw1 = (const float*)d_in[2];
    const float* ab1 = (const float*)d_in[3];
    const float* aw2 = (const float*)d_in[4];
    const float* ab2 = (const float*)d_in[5];
    const float* aw3 = (const float*)d_in[6];
    const float* ab3 = (const float*)d_in[7];
    const float* mw1 = (const float*)d_in[8];
    const float* mb1 = (const float*)d_in[9];
    const float* mw2 = (const float*)d_in[10];
    const float* mb2 = (const float*)d_in[11];
    const float* mw3 = (const float*)d_in[12];
    const float* mb3 = (const float*)d_in[13];
    const float* pw1 = (const float*)d_in[14];
    const float* pb1 = (const float*)d_in[15];
    const float* pw2 = (const float*)d_in[16];
    const float* pb2 = (const float*)d_in[17];
    const float* pw3 = (const float*)d_in[18];
    const float* pb3 = (const float*)d_in[19];
    float* out = (float*)d_out;

    cudaFuncSetAttribute(k_gemm, cudaFuncAttributeMaxDynamicSharedMemorySize,
                         SMEMG);
    cudaFuncSetAttribute(k_attn1g, cudaFuncAttributeMaxDynamicSharedMemorySize,
                         SMEMG);
    cudaFuncSetAttribute(k_pairE, cudaFuncAttributeMaxDynamicSharedMemorySize,
                         SMEMPE);

    const int wtot = 160 * (E3 + 768 + 160);
    k_prep0<<<73, 256>>>(sp);
    k_wprep<<<(wtot + 255) / 256, 256>>>(pw1, aw1, pw2);
    k_attn1g<<<96, 256, SMEMG>>>(X);
    k_attn2<<<48, 256>>>(ab1, aw2, ab2, aw3, ab3);
    k_gather<<<NSPAN * 3, 256>>>(X);
    k_terms<<<288, 256>>>(pw1, mw1);
    k_redment<<<NSPAN, 160>>>(mb1, mw2, mb2, mw3, mb3);
    k_gemm<<<146, 256, SMEMG>>>();
    k_pairE<<<NPAIR / 32, 256, SMEMPE>>>(pb1, pb2, pw3, pb3, out);
}